// round 1
// baseline (speedup 1.0000x reference)
#include <cuda_runtime.h>
#include <cuda_bf16.h>
#include <math.h>

// Problem constants
#define EMBED 512
#define HEADS 8
#define DEPTH 64
#define BATCH 2
#define SEQ   4096
#define MROWS (BATCH * SEQ)          // 8192

// ---------------------------------------------------------------------------
// Device scratch (allocations are forbidden; use __device__ globals)
// ---------------------------------------------------------------------------
__device__ float g_Qh[BATCH * HEADS * SEQ * DEPTH];   // [B,H,S,D]
__device__ float g_Kh[BATCH * HEADS * SEQ * DEPTH];
__device__ float g_Vh[BATCH * HEADS * SEQ * DEPTH];
__device__ float g_ctx[BATCH * SEQ * EMBED];          // [B,S,E]

// ---------------------------------------------------------------------------
// GEMM: C[M,512] = A[M,512] @ W[512,512] + bias, M = 8192
// BM=BN=128, BK=16, 256 threads, 8x8 register tile per thread.
// head_major: write C into [B,H,S,D] layout instead of [M,512].
// ---------------------------------------------------------------------------
__global__ __launch_bounds__(256) void gemm512_kernel(
    const float* __restrict__ A, const float* __restrict__ W,
    const float* __restrict__ bias, float* __restrict__ C, int head_major)
{
    __shared__ float As[16][132];   // A transposed: As[k][m], padded
    __shared__ float Ws[16][128];   // W tile: Ws[k][n]

    const int tid = threadIdx.x;
    const int tx  = tid & 15;       // 0..15 (n direction)
    const int ty  = tid >> 4;       // 0..15 (m direction)
    const int m0  = blockIdx.y * 128;
    const int n0  = blockIdx.x * 128;

    float acc[8][8];
#pragma unroll
    for (int i = 0; i < 8; ++i)
#pragma unroll
        for (int j = 0; j < 8; ++j) acc[i][j] = 0.0f;

    for (int k0 = 0; k0 < 512; k0 += 16) {
        // Load A tile: 128 rows x 16 k = 512 float4
#pragma unroll
        for (int l = 0; l < 2; ++l) {
            int idx = tid + l * 256;            // 0..511
            int row = idx >> 2;                 // 0..127
            int k4  = (idx & 3) * 4;            // 0,4,8,12
            float4 av = *(const float4*)(A + (size_t)(m0 + row) * 512 + k0 + k4);
            As[k4 + 0][row] = av.x;
            As[k4 + 1][row] = av.y;
            As[k4 + 2][row] = av.z;
            As[k4 + 3][row] = av.w;
        }
        // Load W tile: 16 k x 128 n = 512 float4
#pragma unroll
        for (int l = 0; l < 2; ++l) {
            int idx = tid + l * 256;
            int kk  = idx >> 5;                 // 0..15
            int n4  = (idx & 31) * 4;           // 0..124
            *(float4*)&Ws[kk][n4] =
                *(const float4*)(W + (size_t)(k0 + kk) * 512 + n0 + n4);
        }
        __syncthreads();

#pragma unroll
        for (int kk = 0; kk < 16; ++kk) {
            float a[8], b[8];
            *(float4*)&a[0] = *(float4*)&As[kk][ty * 8];
            *(float4*)&a[4] = *(float4*)&As[kk][ty * 8 + 4];
            *(float4*)&b[0] = *(float4*)&Ws[kk][tx * 8];
            *(float4*)&b[4] = *(float4*)&Ws[kk][tx * 8 + 4];
#pragma unroll
            for (int i = 0; i < 8; ++i)
#pragma unroll
                for (int j = 0; j < 8; ++j)
                    acc[i][j] = fmaf(a[i], b[j], acc[i][j]);
        }
        __syncthreads();
    }

    // Epilogue
    if (!head_major) {
#pragma unroll
        for (int i = 0; i < 8; ++i) {
            int m = m0 + ty * 8 + i;
            float* crow = C + (size_t)m * 512 + n0 + tx * 8;
            float4 o0, o1;
            const float* bp = bias + n0 + tx * 8;
            o0.x = acc[i][0] + bp[0]; o0.y = acc[i][1] + bp[1];
            o0.z = acc[i][2] + bp[2]; o0.w = acc[i][3] + bp[3];
            o1.x = acc[i][4] + bp[4]; o1.y = acc[i][5] + bp[5];
            o1.z = acc[i][6] + bp[6]; o1.w = acc[i][7] + bp[7];
            *(float4*)&crow[0] = o0;
            *(float4*)&crow[4] = o1;
        }
    } else {
#pragma unroll
        for (int i = 0; i < 8; ++i) {
            int m = m0 + ty * 8 + i;
            int b = m >> 12;            // /4096
            int s = m & 4095;
            int nbase = n0 + tx * 8;
            int h = nbase >> 6;         // 8 consecutive cols never cross a head
            int d = nbase & 63;
            float* dst = C + ((size_t)(b * HEADS + h) * SEQ + s) * DEPTH + d;
#pragma unroll
            for (int j = 0; j < 8; ++j)
                dst[j] = acc[i][j] + bias[nbase + j];
        }
    }
}

// ---------------------------------------------------------------------------
// Flash attention: per (b,h) and 64-row Q tile.
// S tile 64x64 via 4x4 register tiling (16x16 thread layout), online softmax,
// P staged through smem (aliasing the K tile), PV accumulation 4x4.
// ---------------------------------------------------------------------------
#define STR 68   // smem row stride (floats), padded

__device__ __forceinline__ float rmax16(float v) {
#pragma unroll
    for (int s = 8; s > 0; s >>= 1)
        v = fmaxf(v, __shfl_xor_sync(0xffffffffu, v, s));
    return v;
}
__device__ __forceinline__ float rsum16(float v) {
#pragma unroll
    for (int s = 8; s > 0; s >>= 1)
        v += __shfl_xor_sync(0xffffffffu, v, s);
    return v;
}

__global__ __launch_bounds__(256) void attn_kernel(
    const float* __restrict__ Qh, const float* __restrict__ Kh,
    const float* __restrict__ Vh, const float* __restrict__ mask,
    float* __restrict__ ctx)
{
    extern __shared__ float sm[];
    float* Qt = sm;                 // [64][STR]  Q transposed: Qt[d][i]
    float* KP = Qt + 64 * STR;      // [64][STR]  Kt[d][j]  -> later P[i][j]
    float* Vs = KP + 64 * STR;      // [64][STR]  V[j][d]

    const int tid = threadIdx.x;
    const int tx  = tid & 15;       // key/col group
    const int ty  = tid >> 4;       // query/row group
    const int bh  = blockIdx.y;     // b*8 + h
    const int b   = bh >> 3;
    const int h   = bh & 7;
    const int qi0 = blockIdx.x * 64;

    const float* Qb = Qh + (size_t)bh * SEQ * DEPTH;
    const float* Kb = Kh + (size_t)bh * SEQ * DEPTH;
    const float* Vb = Vh + (size_t)bh * SEQ * DEPTH;
    const float* mb = mask + (size_t)b * SEQ;

    // Load Q tile transposed: Qt[d][i] = Q[qi0+i][d]
#pragma unroll
    for (int l = 0; l < 4; ++l) {
        int idx = tid + l * 256;    // 0..1023 float4 ids
        int r   = idx >> 4;         // row 0..63
        int d4  = (idx & 15) * 4;   // 0..60
        float4 qv = *(const float4*)(Qb + (size_t)(qi0 + r) * DEPTH + d4);
        Qt[(d4 + 0) * STR + r] = qv.x;
        Qt[(d4 + 1) * STR + r] = qv.y;
        Qt[(d4 + 2) * STR + r] = qv.z;
        Qt[(d4 + 3) * STR + r] = qv.w;
    }

    float m_i[4], l_i[4], O[4][4];
#pragma unroll
    for (int i = 0; i < 4; ++i) {
        m_i[i] = -1e30f;
        l_i[i] = 0.0f;
#pragma unroll
        for (int j = 0; j < 4; ++j) O[i][j] = 0.0f;
    }
    const float scale = 0.125f;     // 1/sqrt(64)

    for (int j0 = 0; j0 < SEQ; j0 += 64) {
        __syncthreads();            // previous PV reads of KP/Vs done (and Qt load on iter 0)

        // Load K tile transposed (KP[d][j]) and V tile (Vs[j][d])
#pragma unroll
        for (int l = 0; l < 4; ++l) {
            int idx = tid + l * 256;
            int r   = idx >> 4;
            int d4  = (idx & 15) * 4;
            float4 kv = *(const float4*)(Kb + (size_t)(j0 + r) * DEPTH + d4);
            KP[(d4 + 0) * STR + r] = kv.x;
            KP[(d4 + 1) * STR + r] = kv.y;
            KP[(d4 + 2) * STR + r] = kv.z;
            KP[(d4 + 3) * STR + r] = kv.w;
            float4 vv = *(const float4*)(Vb + (size_t)(j0 + r) * DEPTH + d4);
            *(float4*)&Vs[r * STR + d4] = vv;
        }
        __syncthreads();

        // S = Q K^T  (4x4 per thread)
        float s[4][4];
#pragma unroll
        for (int i = 0; i < 4; ++i)
#pragma unroll
            for (int j = 0; j < 4; ++j) s[i][j] = 0.0f;

#pragma unroll 8
        for (int d = 0; d < 64; ++d) {
            float4 a = *(float4*)&Qt[d * STR + ty * 4];
            float4 kv = *(float4*)&KP[d * STR + tx * 4];
            float av[4] = {a.x, a.y, a.z, a.w};
            float bv[4] = {kv.x, kv.y, kv.z, kv.w};
#pragma unroll
            for (int i = 0; i < 4; ++i)
#pragma unroll
                for (int j = 0; j < 4; ++j)
                    s[i][j] = fmaf(av[i], bv[j], s[i][j]);
        }

        // scale + additive mask (mask[b, j] * -1e9)
        float mk[4];
#pragma unroll
        for (int j = 0; j < 4; ++j)
            mk[j] = mb[j0 + tx * 4 + j] * -1e9f;
#pragma unroll
        for (int i = 0; i < 4; ++i)
#pragma unroll
            for (int j = 0; j < 4; ++j)
                s[i][j] = s[i][j] * scale + mk[j];

        // online softmax per row
#pragma unroll
        for (int i = 0; i < 4; ++i) {
            float mt = fmaxf(fmaxf(s[i][0], s[i][1]), fmaxf(s[i][2], s[i][3]));
            mt = rmax16(mt);
            float mnew = fmaxf(m_i[i], mt);
            float corr = __expf(m_i[i] - mnew);
            m_i[i] = mnew;
            float rs = 0.0f;
#pragma unroll
            for (int j = 0; j < 4; ++j) {
                float p = __expf(s[i][j] - mnew);
                s[i][j] = p;
                rs += p;
            }
            rs = rsum16(rs);
            l_i[i] = l_i[i] * corr + rs;
#pragma unroll
            for (int j = 0; j < 4; ++j) O[i][j] *= corr;
        }

        __syncthreads();            // all K-tile reads done before P overwrites KP

        // write P[i][j] into KP
#pragma unroll
        for (int i = 0; i < 4; ++i)
#pragma unroll
            for (int j = 0; j < 4; ++j)
                KP[(ty * 4 + i) * STR + tx * 4 + j] = s[i][j];
        __syncthreads();

        // O += P @ V   (rows = ty*4.., dcols = tx*4..)
#pragma unroll 8
        for (int j = 0; j < 64; ++j) {
            float4 vv = *(float4*)&Vs[j * STR + tx * 4];
            float p0 = KP[(ty * 4 + 0) * STR + j];
            float p1 = KP[(ty * 4 + 1) * STR + j];
            float p2 = KP[(ty * 4 + 2) * STR + j];
            float p3 = KP[(ty * 4 + 3) * STR + j];
            O[0][0] = fmaf(p0, vv.x, O[0][0]); O[0][1] = fmaf(p0, vv.y, O[0][1]);
            O[0][2] = fmaf(p0, vv.z, O[0][2]); O[0][3] = fmaf(p0, vv.w, O[0][3]);
            O[1][0] = fmaf(p1, vv.x, O[1][0]); O[1][1] = fmaf(p1, vv.y, O[1][1]);
            O[1][2] = fmaf(p1, vv.z, O[1][2]); O[1][3] = fmaf(p1, vv.w, O[1][3]);
            O[2][0] = fmaf(p2, vv.x, O[2][0]); O[2][1] = fmaf(p2, vv.y, O[2][1]);
            O[2][2] = fmaf(p2, vv.z, O[2][2]); O[2][3] = fmaf(p2, vv.w, O[2][3]);
            O[3][0] = fmaf(p3, vv.x, O[3][0]); O[3][1] = fmaf(p3, vv.y, O[3][1]);
            O[3][2] = fmaf(p3, vv.z, O[3][2]); O[3][3] = fmaf(p3, vv.w, O[3][3]);
        }
    }

    // epilogue: normalize and write context [B,S,E]
#pragma unroll
    for (int i = 0; i < 4; ++i) {
        float inv = 1.0f / l_i[i];
        int row = qi0 + ty * 4 + i;
        float4 o;
        o.x = O[i][0] * inv; o.y = O[i][1] * inv;
        o.z = O[i][2] * inv; o.w = O[i][3] * inv;
        *(float4*)(ctx + ((size_t)(b * SEQ + row)) * EMBED + h * DEPTH + tx * 4) = o;
    }
}

// ---------------------------------------------------------------------------
// Launcher
// ---------------------------------------------------------------------------
extern "C" void kernel_launch(void* const* d_in, const int* in_sizes, int n_in,
                              void* d_out, int out_size)
{
    const float* q    = (const float*)d_in[0];
    const float* k    = (const float*)d_in[1];
    const float* v    = (const float*)d_in[2];
    const float* mask = (const float*)d_in[3];
    const float* Wq   = (const float*)d_in[4];
    const float* bq   = (const float*)d_in[5];
    const float* Wk   = (const float*)d_in[6];
    const float* bk   = (const float*)d_in[7];
    const float* Wv   = (const float*)d_in[8];
    const float* bv   = (const float*)d_in[9];
    const float* Wo   = (const float*)d_in[10];
    const float* bo   = (const float*)d_in[11];
    float* out = (float*)d_out;

    float *Qh, *Kh, *Vh, *ctx;
    cudaGetSymbolAddress((void**)&Qh,  g_Qh);
    cudaGetSymbolAddress((void**)&Kh,  g_Kh);
    cudaGetSymbolAddress((void**)&Vh,  g_Vh);
    cudaGetSymbolAddress((void**)&ctx, g_ctx);

    dim3 ggrid(512 / 128, MROWS / 128);   // (4, 64)
    gemm512_kernel<<<ggrid, 256>>>(q, Wq, bq, Qh, 1);
    gemm512_kernel<<<ggrid, 256>>>(k, Wk, bk, Kh, 1);
    gemm512_kernel<<<ggrid, 256>>>(v, Wv, bv, Vh, 1);

    const int ATTN_SMEM = 3 * 64 * STR * (int)sizeof(float);   // 52224 B
    cudaFuncSetAttribute(attn_kernel,
                         cudaFuncAttributeMaxDynamicSharedMemorySize, ATTN_SMEM);
    attn_kernel<<<dim3(SEQ / 64, BATCH * HEADS), 256, ATTN_SMEM>>>(
        Qh, Kh, Vh, mask, ctx);

    gemm512_kernel<<<ggrid, 256>>>(ctx, Wo, bo, out, 0);
}

// round 2
// speedup vs baseline: 1.0423x; 1.0423x over previous
#include <cuda_runtime.h>
#include <cuda_bf16.h>
#include <math.h>

// Problem constants
#define EMBED 512
#define HEADS 8
#define DEPTH 64
#define BATCH 2
#define SEQ   4096
#define MROWS (BATCH * SEQ)          // 8192

// ---------------------------------------------------------------------------
// Device scratch (allocations are forbidden; use __device__ globals)
// ---------------------------------------------------------------------------
__device__ float g_Qh[BATCH * HEADS * DEPTH * SEQ];   // [B,H,D,S]  (d-major!)
__device__ float g_Kh[BATCH * HEADS * DEPTH * SEQ];   // [B,H,D,S]
__device__ float g_Vh[BATCH * HEADS * SEQ * DEPTH];   // [B,H,S,D]
__device__ float g_ctx[BATCH * SEQ * EMBED];          // [B,S,E]

// ---------------------------------------------------------------------------
// GEMM: 8192x512 @ 512x512 + bias.
// MODE 0: C[m][n] row-major           (ctx @ Wo -> out)
// MODE 1: C -> [B,H,S,D]              (v @ Wv -> Vh)
// MODE 2: C^T -> [B,H,D,S] (d-major)  (q @ Wq -> Qh, k @ Wk -> Kh)
// BM=BN=128, BK=16, 256 threads, 8x8 register tile.
// ---------------------------------------------------------------------------
template <int MODE>
__global__ __launch_bounds__(256) void gemm512_kernel(
    const float* __restrict__ A, const float* __restrict__ W,
    const float* __restrict__ bias, float* __restrict__ C)
{
    __shared__ float As[16][132];   // A transposed: As[k][m]
    __shared__ float Ws[16][128];   // W tile: Ws[k][n]

    const int tid = threadIdx.x;
    const int tx  = tid & 15;
    const int ty  = tid >> 4;
    const int m0  = blockIdx.y * 128;
    const int n0  = blockIdx.x * 128;

    float acc[8][8];
#pragma unroll
    for (int i = 0; i < 8; ++i)
#pragma unroll
        for (int j = 0; j < 8; ++j) acc[i][j] = 0.0f;

    for (int k0 = 0; k0 < 512; k0 += 16) {
#pragma unroll
        for (int l = 0; l < 2; ++l) {
            int idx = tid + l * 256;            // 0..511
            int row = idx >> 2;                 // 0..127
            int k4  = (idx & 3) * 4;            // 0,4,8,12
            float4 av = *(const float4*)(A + (size_t)(m0 + row) * 512 + k0 + k4);
            As[k4 + 0][row] = av.x;
            As[k4 + 1][row] = av.y;
            As[k4 + 2][row] = av.z;
            As[k4 + 3][row] = av.w;
        }
#pragma unroll
        for (int l = 0; l < 2; ++l) {
            int idx = tid + l * 256;
            int kk  = idx >> 5;
            int n4  = (idx & 31) * 4;
            *(float4*)&Ws[kk][n4] =
                *(const float4*)(W + (size_t)(k0 + kk) * 512 + n0 + n4);
        }
        __syncthreads();

#pragma unroll
        for (int kk = 0; kk < 16; ++kk) {
            float a[8], b[8];
            if (MODE == 2) {
                // transposed output: rows = n, cols = m
                *(float4*)&a[0] = *(float4*)&Ws[kk][ty * 8];
                *(float4*)&a[4] = *(float4*)&Ws[kk][ty * 8 + 4];
                *(float4*)&b[0] = *(float4*)&As[kk][tx * 8];
                *(float4*)&b[4] = *(float4*)&As[kk][tx * 8 + 4];
            } else {
                *(float4*)&a[0] = *(float4*)&As[kk][ty * 8];
                *(float4*)&a[4] = *(float4*)&As[kk][ty * 8 + 4];
                *(float4*)&b[0] = *(float4*)&Ws[kk][tx * 8];
                *(float4*)&b[4] = *(float4*)&Ws[kk][tx * 8 + 4];
            }
#pragma unroll
            for (int i = 0; i < 8; ++i)
#pragma unroll
                for (int j = 0; j < 8; ++j)
                    acc[i][j] = fmaf(a[i], b[j], acc[i][j]);
        }
        __syncthreads();
    }

    if (MODE == 0) {
#pragma unroll
        for (int i = 0; i < 8; ++i) {
            int m = m0 + ty * 8 + i;
            float* crow = C + (size_t)m * 512 + n0 + tx * 8;
            const float* bp = bias + n0 + tx * 8;
            float4 o0, o1;
            o0.x = acc[i][0] + bp[0]; o0.y = acc[i][1] + bp[1];
            o0.z = acc[i][2] + bp[2]; o0.w = acc[i][3] + bp[3];
            o1.x = acc[i][4] + bp[4]; o1.y = acc[i][5] + bp[5];
            o1.z = acc[i][6] + bp[6]; o1.w = acc[i][7] + bp[7];
            *(float4*)&crow[0] = o0;
            *(float4*)&crow[4] = o1;
        }
    } else if (MODE == 1) {
#pragma unroll
        for (int i = 0; i < 8; ++i) {
            int m = m0 + ty * 8 + i;
            int b = m >> 12;
            int s = m & 4095;
            int nbase = n0 + tx * 8;
            int h = nbase >> 6;
            int d = nbase & 63;
            float* dst = C + ((size_t)(b * HEADS + h) * SEQ + s) * DEPTH + d;
            float4 o0, o1;
            const float* bp = bias + nbase;
            o0.x = acc[i][0] + bp[0]; o0.y = acc[i][1] + bp[1];
            o0.z = acc[i][2] + bp[2]; o0.w = acc[i][3] + bp[3];
            o1.x = acc[i][4] + bp[4]; o1.y = acc[i][5] + bp[5];
            o1.z = acc[i][6] + bp[6]; o1.w = acc[i][7] + bp[7];
            *(float4*)&dst[0] = o0;
            *(float4*)&dst[4] = o1;
        }
    } else {
        // MODE 2: acc[i][j] = C^T[n0+ty*8+i][m0+tx*8+j] -> [B,H,D,S]
        int b  = m0 >> 12;
        int s0 = (m0 & 4095) + tx * 8;
#pragma unroll
        for (int i = 0; i < 8; ++i) {
            int n = n0 + ty * 8 + i;
            int h = n >> 6;
            int d = n & 63;
            float bi = bias[n];
            float* dst = C + ((size_t)(b * HEADS + h) * DEPTH + d) * SEQ + s0;
            float4 o0, o1;
            o0.x = acc[i][0] + bi; o0.y = acc[i][1] + bi;
            o0.z = acc[i][2] + bi; o0.w = acc[i][3] + bi;
            o1.x = acc[i][4] + bi; o1.y = acc[i][5] + bi;
            o1.z = acc[i][6] + bi; o1.w = acc[i][7] + bi;
            *(float4*)&dst[0] = o0;
            *(float4*)&dst[4] = o1;
        }
    }
}

// ---------------------------------------------------------------------------
// Flash attention: 128 Q rows x 128 K cols per block, 256 threads.
// QK^T: 8x8 per thread. PV: 8 rows x 4 dcols per thread.
// Q/K are d-major [B,H,D,S] -> conflict-free smem fills, no transpose needed.
// ---------------------------------------------------------------------------
#define STRQ 132
#define STRK 132
#define STRV 68

__device__ __forceinline__ float rmax16(float v) {
#pragma unroll
    for (int s = 8; s > 0; s >>= 1)
        v = fmaxf(v, __shfl_xor_sync(0xffffffffu, v, s));
    return v;
}
__device__ __forceinline__ float rsum16(float v) {
#pragma unroll
    for (int s = 8; s > 0; s >>= 1)
        v += __shfl_xor_sync(0xffffffffu, v, s);
    return v;
}

__global__ __launch_bounds__(256, 1) void attn_kernel(
    const float* __restrict__ Qg, const float* __restrict__ Kg,
    const float* __restrict__ Vg, const float* __restrict__ mask,
    float* __restrict__ ctx)
{
    extern __shared__ float sm[];
    float* Qt = sm;                   // [64][STRQ]   Qt[d][i]
    float* KP = Qt + 64 * STRQ;       // [128][STRK]  Kt[d][j], then P[i][j]
    float* Vs = KP + 128 * STRK;      // [128][STRV]  V[j][d]

    const int tid = threadIdx.x;
    const int tx  = tid & 15;
    const int ty  = tid >> 4;
    const int bh  = blockIdx.y;
    const int b   = bh >> 3;
    const int h   = bh & 7;
    const int qi0 = blockIdx.x * 128;

    const float* Qb = Qg + (size_t)bh * DEPTH * SEQ;
    const float* Kb = Kg + (size_t)bh * DEPTH * SEQ;
    const float* Vb = Vg + (size_t)bh * SEQ * DEPTH;
    const float* mb = mask + (size_t)b * SEQ;

    // Load Q tile (d-major): Qt[d][i] = Q[d][qi0+i]
#pragma unroll
    for (int l = 0; l < 8; ++l) {
        int idx = tid + l * 256;       // 2048 float4s
        int d   = idx >> 5;            // 0..63
        int i4  = (idx & 31) * 4;      // 0..124
        *(float4*)&Qt[d * STRQ + i4] =
            *(const float4*)(Qb + (size_t)d * SEQ + qi0 + i4);
    }

    float m_i[8], l_i[8], O[8][4];
#pragma unroll
    for (int i = 0; i < 8; ++i) {
        m_i[i] = -1e30f;
        l_i[i] = 0.0f;
#pragma unroll
        for (int j = 0; j < 4; ++j) O[i][j] = 0.0f;
    }
    const float scale = 0.125f;       // 1/sqrt(64)

    for (int j0 = 0; j0 < SEQ; j0 += 128) {
        __syncthreads();              // prior PV reads of KP/Vs complete

        // K tile (d-major): Kt[d][j]
#pragma unroll
        for (int l = 0; l < 8; ++l) {
            int idx = tid + l * 256;
            int d   = idx >> 5;
            int j4  = (idx & 31) * 4;
            *(float4*)&KP[d * STRK + j4] =
                *(const float4*)(Kb + (size_t)d * SEQ + j0 + j4);
        }
        // V tile: Vs[j][d]
#pragma unroll
        for (int l = 0; l < 8; ++l) {
            int idx = tid + l * 256;
            int j   = idx >> 4;
            int d4  = (idx & 15) * 4;
            *(float4*)&Vs[j * STRV + d4] =
                *(const float4*)(Vb + (size_t)(j0 + j) * DEPTH + d4);
        }
        __syncthreads();

        // S = Q K^T (8x8 per thread)
        float s[8][8];
#pragma unroll
        for (int i = 0; i < 8; ++i)
#pragma unroll
            for (int j = 0; j < 8; ++j) s[i][j] = 0.0f;

#pragma unroll 4
        for (int d = 0; d < 64; ++d) {
            float a[8], bv[8];
            *(float4*)&a[0]  = *(float4*)&Qt[d * STRQ + ty * 8];
            *(float4*)&a[4]  = *(float4*)&Qt[d * STRQ + ty * 8 + 4];
            *(float4*)&bv[0] = *(float4*)&KP[d * STRK + tx * 8];
            *(float4*)&bv[4] = *(float4*)&KP[d * STRK + tx * 8 + 4];
#pragma unroll
            for (int i = 0; i < 8; ++i)
#pragma unroll
                for (int j = 0; j < 8; ++j)
                    s[i][j] = fmaf(a[i], bv[j], s[i][j]);
        }

        // scale + additive mask
        float mk[8];
        {
            float4 mk0 = *(const float4*)(mb + j0 + tx * 8);
            float4 mk1 = *(const float4*)(mb + j0 + tx * 8 + 4);
            mk[0] = mk0.x * -1e9f; mk[1] = mk0.y * -1e9f;
            mk[2] = mk0.z * -1e9f; mk[3] = mk0.w * -1e9f;
            mk[4] = mk1.x * -1e9f; mk[5] = mk1.y * -1e9f;
            mk[6] = mk1.z * -1e9f; mk[7] = mk1.w * -1e9f;
        }
#pragma unroll
        for (int i = 0; i < 8; ++i)
#pragma unroll
            for (int j = 0; j < 8; ++j)
                s[i][j] = fmaf(s[i][j], scale, mk[j]);

        // online softmax (rows: 16 tx-threads per row group)
#pragma unroll
        for (int i = 0; i < 8; ++i) {
            float mt = s[i][0];
#pragma unroll
            for (int j = 1; j < 8; ++j) mt = fmaxf(mt, s[i][j]);
            mt = rmax16(mt);
            float mnew = fmaxf(m_i[i], mt);
            float corr = __expf(m_i[i] - mnew);
            m_i[i] = mnew;
            float rs = 0.0f;
#pragma unroll
            for (int j = 0; j < 8; ++j) {
                float p = __expf(s[i][j] - mnew);
                s[i][j] = p;
                rs += p;
            }
            rs = rsum16(rs);
            l_i[i] = fmaf(l_i[i], corr, rs);
#pragma unroll
            for (int j = 0; j < 4; ++j) O[i][j] *= corr;
        }

        __syncthreads();              // QK^T reads of Kt done; safe to overwrite with P

        // store P row-major: P[i][j]
#pragma unroll
        for (int i = 0; i < 8; ++i) {
            float4 p0, p1;
            p0.x = s[i][0]; p0.y = s[i][1]; p0.z = s[i][2]; p0.w = s[i][3];
            p1.x = s[i][4]; p1.y = s[i][5]; p1.z = s[i][6]; p1.w = s[i][7];
            *(float4*)&KP[(ty * 8 + i) * STRK + tx * 8]     = p0;
            *(float4*)&KP[(ty * 8 + i) * STRK + tx * 8 + 4] = p1;
        }
        __syncthreads();

        // O += P @ V : 8 rows x 4 dcols per thread, j unrolled by 4
#pragma unroll 2
        for (int jj = 0; jj < 128; jj += 4) {
            float p[8][4];
#pragma unroll
            for (int i = 0; i < 8; ++i)
                *(float4*)&p[i][0] = *(float4*)&KP[(ty * 8 + i) * STRK + jj];
#pragma unroll
            for (int dj = 0; dj < 4; ++dj) {
                float4 v4 = *(float4*)&Vs[(jj + dj) * STRV + tx * 4];
#pragma unroll
                for (int i = 0; i < 8; ++i) {
                    O[i][0] = fmaf(p[i][dj], v4.x, O[i][0]);
                    O[i][1] = fmaf(p[i][dj], v4.y, O[i][1]);
                    O[i][2] = fmaf(p[i][dj], v4.z, O[i][2]);
                    O[i][3] = fmaf(p[i][dj], v4.w, O[i][3]);
                }
            }
        }
    }

    // epilogue: normalize, write ctx[B,S,E]
#pragma unroll
    for (int i = 0; i < 8; ++i) {
        float inv = 1.0f / l_i[i];
        int row = qi0 + ty * 8 + i;
        float4 o;
        o.x = O[i][0] * inv; o.y = O[i][1] * inv;
        o.z = O[i][2] * inv; o.w = O[i][3] * inv;
        *(float4*)(ctx + ((size_t)(b * SEQ + row)) * EMBED + h * DEPTH + tx * 4) = o;
    }
}

// ---------------------------------------------------------------------------
// Launcher
// ---------------------------------------------------------------------------
extern "C" void kernel_launch(void* const* d_in, const int* in_sizes, int n_in,
                              void* d_out, int out_size)
{
    const float* q    = (const float*)d_in[0];
    const float* k    = (const float*)d_in[1];
    const float* v    = (const float*)d_in[2];
    const float* mask = (const float*)d_in[3];
    const float* Wq   = (const float*)d_in[4];
    const float* bq   = (const float*)d_in[5];
    const float* Wk   = (const float*)d_in[6];
    const float* bk   = (const float*)d_in[7];
    const float* Wv   = (const float*)d_in[8];
    const float* bv   = (const float*)d_in[9];
    const float* Wo   = (const float*)d_in[10];
    const float* bo   = (const float*)d_in[11];
    float* out = (float*)d_out;

    float *Qh, *Kh, *Vh, *ctx;
    cudaGetSymbolAddress((void**)&Qh,  g_Qh);
    cudaGetSymbolAddress((void**)&Kh,  g_Kh);
    cudaGetSymbolAddress((void**)&Vh,  g_Vh);
    cudaGetSymbolAddress((void**)&ctx, g_ctx);

    dim3 ggrid(512 / 128, MROWS / 128);   // (4, 64)
    gemm512_kernel<2><<<ggrid, 256>>>(q, Wq, bq, Qh);
    gemm512_kernel<2><<<ggrid, 256>>>(k, Wk, bk, Kh);
    gemm512_kernel<1><<<ggrid, 256>>>(v, Wv, bv, Vh);

    const int ATTN_SMEM = (64 * STRQ + 128 * STRK + 128 * STRV) * (int)sizeof(float);
    cudaFuncSetAttribute(attn_kernel,
                         cudaFuncAttributeMaxDynamicSharedMemorySize, ATTN_SMEM);
    attn_kernel<<<dim3(SEQ / 128, BATCH * HEADS), 256, ATTN_SMEM>>>(
        Qh, Kh, Vh, mask, ctx);

    gemm512_kernel<0><<<ggrid, 256>>>(ctx, Wo, bo, out);
}

// round 3
// speedup vs baseline: 1.1422x; 1.0958x over previous
#include <cuda_runtime.h>
#include <cuda_bf16.h>
#include <math.h>

// Problem constants
#define EMBED 512
#define HEADS 8
#define DEPTH 64
#define BATCH 2
#define SEQ   4096
#define MROWS (BATCH * SEQ)          // 8192

typedef unsigned long long u64;

// ---------------------------------------------------------------------------
// f32x2 packed-FMA helpers (Blackwell native, PTX-only)
// ---------------------------------------------------------------------------
__device__ __forceinline__ u64 pack2(float lo, float hi) {
    u64 r; asm("mov.b64 %0, {%1, %2};" : "=l"(r) : "f"(lo), "f"(hi)); return r;
}
__device__ __forceinline__ u64 splat2(float v) {
    u64 r; asm("mov.b64 %0, {%1, %1};" : "=l"(r) : "f"(v)); return r;
}
__device__ __forceinline__ float2 unpack2(u64 v) {
    float2 r; asm("mov.b64 {%0, %1}, %2;" : "=f"(r.x), "=f"(r.y) : "l"(v)); return r;
}
__device__ __forceinline__ void fma2(u64& d, u64 a, u64 b) {
    asm("fma.rn.f32x2 %0, %1, %2, %0;" : "+l"(d) : "l"(a), "l"(b));
}
__device__ __forceinline__ void mul2(u64& d, u64 a) {
    asm("mul.rn.f32x2 %0, %0, %1;" : "+l"(d) : "l"(a));
}

union F4U { float4 f; struct { u64 lo, hi; } u; };

// ---------------------------------------------------------------------------
// Device scratch
// ---------------------------------------------------------------------------
__device__ float g_Qh[BATCH * HEADS * DEPTH * SEQ];   // [B,H,D,S]  (d-major)
__device__ float g_Kh[BATCH * HEADS * DEPTH * SEQ];   // [B,H,D,S]
__device__ float g_Vh[BATCH * HEADS * SEQ * DEPTH];   // [B,H,S,D]
__device__ float g_ctx[BATCH * SEQ * EMBED];          // [B,S,E]

// ---------------------------------------------------------------------------
// GEMM: 8192x512 @ 512x512 + bias, f32x2 inner loop.
// MODE 0: C[m][n] row-major; MODE 1: C -> [B,H,S,D]; MODE 2: C^T -> [B,H,D,S]
// ---------------------------------------------------------------------------
template <int MODE>
__global__ __launch_bounds__(256, 2) void gemm512_kernel(
    const float* __restrict__ A, const float* __restrict__ W,
    const float* __restrict__ bias, float* __restrict__ C)
{
    __shared__ float As[16][132];
    __shared__ float Ws[16][128];

    const int tid = threadIdx.x;
    const int tx  = tid & 15;
    const int ty  = tid >> 4;
    const int m0  = blockIdx.y * 128;
    const int n0  = blockIdx.x * 128;

    u64 acc[8][4];
#pragma unroll
    for (int i = 0; i < 8; ++i)
#pragma unroll
        for (int j = 0; j < 4; ++j) acc[i][j] = 0ull;

    for (int k0 = 0; k0 < 512; k0 += 16) {
#pragma unroll
        for (int l = 0; l < 2; ++l) {
            int idx = tid + l * 256;
            int row = idx >> 2;
            int k4  = (idx & 3) * 4;
            float4 av = *(const float4*)(A + (size_t)(m0 + row) * 512 + k0 + k4);
            As[k4 + 0][row] = av.x;
            As[k4 + 1][row] = av.y;
            As[k4 + 2][row] = av.z;
            As[k4 + 3][row] = av.w;
        }
#pragma unroll
        for (int l = 0; l < 2; ++l) {
            int idx = tid + l * 256;
            int kk  = idx >> 5;
            int n4  = (idx & 31) * 4;
            *(float4*)&Ws[kk][n4] =
                *(const float4*)(W + (size_t)(k0 + kk) * 512 + n0 + n4);
        }
        __syncthreads();

#pragma unroll
        for (int kk = 0; kk < 16; ++kk) {
            float a[8];
            F4U b0, b1;
            if (MODE == 2) {
                *(float4*)&a[0] = *(float4*)&Ws[kk][ty * 8];
                *(float4*)&a[4] = *(float4*)&Ws[kk][ty * 8 + 4];
                b0.f = *(float4*)&As[kk][tx * 8];
                b1.f = *(float4*)&As[kk][tx * 8 + 4];
            } else {
                *(float4*)&a[0] = *(float4*)&As[kk][ty * 8];
                *(float4*)&a[4] = *(float4*)&As[kk][ty * 8 + 4];
                b0.f = *(float4*)&Ws[kk][tx * 8];
                b1.f = *(float4*)&Ws[kk][tx * 8 + 4];
            }
#pragma unroll
            for (int i = 0; i < 8; ++i) {
                u64 as = splat2(a[i]);
                fma2(acc[i][0], as, b0.u.lo);
                fma2(acc[i][1], as, b0.u.hi);
                fma2(acc[i][2], as, b1.u.lo);
                fma2(acc[i][3], as, b1.u.hi);
            }
        }
        __syncthreads();
    }

    // unpack accumulators
    float accf[8][8];
#pragma unroll
    for (int i = 0; i < 8; ++i)
#pragma unroll
        for (int jp = 0; jp < 4; ++jp) {
            float2 u = unpack2(acc[i][jp]);
            accf[i][jp * 2]     = u.x;
            accf[i][jp * 2 + 1] = u.y;
        }

    if (MODE == 0) {
#pragma unroll
        for (int i = 0; i < 8; ++i) {
            int m = m0 + ty * 8 + i;
            float* crow = C + (size_t)m * 512 + n0 + tx * 8;
            const float* bp = bias + n0 + tx * 8;
            float4 o0, o1;
            o0.x = accf[i][0] + bp[0]; o0.y = accf[i][1] + bp[1];
            o0.z = accf[i][2] + bp[2]; o0.w = accf[i][3] + bp[3];
            o1.x = accf[i][4] + bp[4]; o1.y = accf[i][5] + bp[5];
            o1.z = accf[i][6] + bp[6]; o1.w = accf[i][7] + bp[7];
            *(float4*)&crow[0] = o0;
            *(float4*)&crow[4] = o1;
        }
    } else if (MODE == 1) {
#pragma unroll
        for (int i = 0; i < 8; ++i) {
            int m = m0 + ty * 8 + i;
            int b = m >> 12;
            int s = m & 4095;
            int nbase = n0 + tx * 8;
            int h = nbase >> 6;
            int d = nbase & 63;
            float* dst = C + ((size_t)(b * HEADS + h) * SEQ + s) * DEPTH + d;
            const float* bp = bias + nbase;
            float4 o0, o1;
            o0.x = accf[i][0] + bp[0]; o0.y = accf[i][1] + bp[1];
            o0.z = accf[i][2] + bp[2]; o0.w = accf[i][3] + bp[3];
            o1.x = accf[i][4] + bp[4]; o1.y = accf[i][5] + bp[5];
            o1.z = accf[i][6] + bp[6]; o1.w = accf[i][7] + bp[7];
            *(float4*)&dst[0] = o0;
            *(float4*)&dst[4] = o1;
        }
    } else {
        int b  = m0 >> 12;
        int s0 = (m0 & 4095) + tx * 8;
#pragma unroll
        for (int i = 0; i < 8; ++i) {
            int n = n0 + ty * 8 + i;
            int h = n >> 6;
            int d = n & 63;
            float bi = bias[n];
            float* dst = C + ((size_t)(b * HEADS + h) * DEPTH + d) * SEQ + s0;
            float4 o0, o1;
            o0.x = accf[i][0] + bi; o0.y = accf[i][1] + bi;
            o0.z = accf[i][2] + bi; o0.w = accf[i][3] + bi;
            o1.x = accf[i][4] + bi; o1.y = accf[i][5] + bi;
            o1.z = accf[i][6] + bi; o1.w = accf[i][7] + bi;
            *(float4*)&dst[0] = o0;
            *(float4*)&dst[4] = o1;
        }
    }
}

// ---------------------------------------------------------------------------
// Flash attention: 128x128 tile, 256 threads, f32x2 math everywhere.
// ---------------------------------------------------------------------------
#define STRQ 132
#define STRK 132
#define STRV 68

__device__ __forceinline__ float rmax16(float v) {
#pragma unroll
    for (int s = 8; s > 0; s >>= 1)
        v = fmaxf(v, __shfl_xor_sync(0xffffffffu, v, s));
    return v;
}
__device__ __forceinline__ float rsum16(float v) {
#pragma unroll
    for (int s = 8; s > 0; s >>= 1)
        v += __shfl_xor_sync(0xffffffffu, v, s);
    return v;
}

__global__ __launch_bounds__(256, 1) void attn_kernel(
    const float* __restrict__ Qg, const float* __restrict__ Kg,
    const float* __restrict__ Vg, const float* __restrict__ mask,
    float* __restrict__ ctx)
{
    extern __shared__ float sm[];
    float* Qt = sm;                   // [64][STRQ]   Qt[d][i]
    float* KP = Qt + 64 * STRQ;       // [128][STRK]  Kt[d][j] -> P[i][j]
    float* Vs = KP + 128 * STRK;      // [128][STRV]  V[j][d]

    const int tid = threadIdx.x;
    const int tx  = tid & 15;
    const int ty  = tid >> 4;
    const int bh  = blockIdx.y;
    const int b   = bh >> 3;
    const int h   = bh & 7;
    const int qi0 = blockIdx.x * 128;

    const float* Qb = Qg + (size_t)bh * DEPTH * SEQ;
    const float* Kb = Kg + (size_t)bh * DEPTH * SEQ;
    const float* Vb = Vg + (size_t)bh * SEQ * DEPTH;
    const float* mb = mask + (size_t)b * SEQ;

#pragma unroll
    for (int l = 0; l < 8; ++l) {
        int idx = tid + l * 256;
        int d   = idx >> 5;
        int i4  = (idx & 31) * 4;
        *(float4*)&Qt[d * STRQ + i4] =
            *(const float4*)(Qb + (size_t)d * SEQ + qi0 + i4);
    }

    float m_i[8], l_i[8];
    u64 O[8][2];                       // 8 rows x 4 d-cols as 2 pairs
#pragma unroll
    for (int i = 0; i < 8; ++i) {
        m_i[i] = -1e30f;
        l_i[i] = 0.0f;
        O[i][0] = 0ull; O[i][1] = 0ull;
    }
    const float scale = 0.125f;       // 1/sqrt(64)

    for (int j0 = 0; j0 < SEQ; j0 += 128) {
        __syncthreads();

#pragma unroll
        for (int l = 0; l < 8; ++l) {
            int idx = tid + l * 256;
            int d   = idx >> 5;
            int j4  = (idx & 31) * 4;
            *(float4*)&KP[d * STRK + j4] =
                *(const float4*)(Kb + (size_t)d * SEQ + j0 + j4);
        }
#pragma unroll
        for (int l = 0; l < 8; ++l) {
            int idx = tid + l * 256;
            int j   = idx >> 4;
            int d4  = (idx & 15) * 4;
            *(float4*)&Vs[j * STRV + d4] =
                *(const float4*)(Vb + (size_t)(j0 + j) * DEPTH + d4);
        }
        __syncthreads();

        // S = Q K^T : 8x8 per thread via f32x2 (acc as 8x4 pairs)
        u64 sa[8][4];
#pragma unroll
        for (int i = 0; i < 8; ++i)
#pragma unroll
            for (int j = 0; j < 4; ++j) sa[i][j] = 0ull;

#pragma unroll 4
        for (int d = 0; d < 64; ++d) {
            float a[8];
            F4U b0, b1;
            *(float4*)&a[0] = *(float4*)&Qt[d * STRQ + ty * 8];
            *(float4*)&a[4] = *(float4*)&Qt[d * STRQ + ty * 8 + 4];
            b0.f = *(float4*)&KP[d * STRK + tx * 8];
            b1.f = *(float4*)&KP[d * STRK + tx * 8 + 4];
#pragma unroll
            for (int i = 0; i < 8; ++i) {
                u64 as = splat2(a[i]);
                fma2(sa[i][0], as, b0.u.lo);
                fma2(sa[i][1], as, b0.u.hi);
                fma2(sa[i][2], as, b1.u.lo);
                fma2(sa[i][3], as, b1.u.hi);
            }
        }

        // unpack, scale + mask
        float s[8][8];
        float mk[8];
        {
            float4 mk0 = *(const float4*)(mb + j0 + tx * 8);
            float4 mk1 = *(const float4*)(mb + j0 + tx * 8 + 4);
            mk[0] = mk0.x * -1e9f; mk[1] = mk0.y * -1e9f;
            mk[2] = mk0.z * -1e9f; mk[3] = mk0.w * -1e9f;
            mk[4] = mk1.x * -1e9f; mk[5] = mk1.y * -1e9f;
            mk[6] = mk1.z * -1e9f; mk[7] = mk1.w * -1e9f;
        }
#pragma unroll
        for (int i = 0; i < 8; ++i)
#pragma unroll
            for (int jp = 0; jp < 4; ++jp) {
                float2 u = unpack2(sa[i][jp]);
                s[i][jp * 2]     = fmaf(u.x, scale, mk[jp * 2]);
                s[i][jp * 2 + 1] = fmaf(u.y, scale, mk[jp * 2 + 1]);
            }

        // online softmax
#pragma unroll
        for (int i = 0; i < 8; ++i) {
            float mt = s[i][0];
#pragma unroll
            for (int j = 1; j < 8; ++j) mt = fmaxf(mt, s[i][j]);
            mt = rmax16(mt);
            float mnew = fmaxf(m_i[i], mt);
            float corr = __expf(m_i[i] - mnew);
            m_i[i] = mnew;
            float rs = 0.0f;
#pragma unroll
            for (int j = 0; j < 8; ++j) {
                float p = __expf(s[i][j] - mnew);
                s[i][j] = p;
                rs += p;
            }
            rs = rsum16(rs);
            l_i[i] = fmaf(l_i[i], corr, rs);
            u64 c2 = splat2(corr);
            mul2(O[i][0], c2);
            mul2(O[i][1], c2);
        }

        __syncthreads();

#pragma unroll
        for (int i = 0; i < 8; ++i) {
            float4 p0, p1;
            p0.x = s[i][0]; p0.y = s[i][1]; p0.z = s[i][2]; p0.w = s[i][3];
            p1.x = s[i][4]; p1.y = s[i][5]; p1.z = s[i][6]; p1.w = s[i][7];
            *(float4*)&KP[(ty * 8 + i) * STRK + tx * 8]     = p0;
            *(float4*)&KP[(ty * 8 + i) * STRK + tx * 8 + 4] = p1;
        }
        __syncthreads();

        // O += P @ V : f32x2 over d pairs
#pragma unroll 2
        for (int jj = 0; jj < 128; jj += 4) {
            float p[8][4];
#pragma unroll
            for (int i = 0; i < 8; ++i)
                *(float4*)&p[i][0] = *(float4*)&KP[(ty * 8 + i) * STRK + jj];
#pragma unroll
            for (int dj = 0; dj < 4; ++dj) {
                F4U v4; v4.f = *(float4*)&Vs[(jj + dj) * STRV + tx * 4];
#pragma unroll
                for (int i = 0; i < 8; ++i) {
                    u64 pp = splat2(p[i][dj]);
                    fma2(O[i][0], pp, v4.u.lo);
                    fma2(O[i][1], pp, v4.u.hi);
                }
            }
        }
    }

    // epilogue
#pragma unroll
    for (int i = 0; i < 8; ++i) {
        float inv = 1.0f / l_i[i];
        int row = qi0 + ty * 8 + i;
        float2 o0 = unpack2(O[i][0]);
        float2 o1 = unpack2(O[i][1]);
        float4 o;
        o.x = o0.x * inv; o.y = o0.y * inv;
        o.z = o1.x * inv; o.w = o1.y * inv;
        *(float4*)(ctx + ((size_t)(b * SEQ + row)) * EMBED + h * DEPTH + tx * 4) = o;
    }
}

// ---------------------------------------------------------------------------
// Launcher
// ---------------------------------------------------------------------------
extern "C" void kernel_launch(void* const* d_in, const int* in_sizes, int n_in,
                              void* d_out, int out_size)
{
    const float* q    = (const float*)d_in[0];
    const float* k    = (const float*)d_in[1];
    const float* v    = (const float*)d_in[2];
    const float* mask = (const float*)d_in[3];
    const float* Wq   = (const float*)d_in[4];
    const float* bq   = (const float*)d_in[5];
    const float* Wk   = (const float*)d_in[6];
    const float* bk   = (const float*)d_in[7];
    const float* Wv   = (const float*)d_in[8];
    const float* bv   = (const float*)d_in[9];
    const float* Wo   = (const float*)d_in[10];
    const float* bo   = (const float*)d_in[11];
    float* out = (float*)d_out;

    float *Qh, *Kh, *Vh, *ctx;
    cudaGetSymbolAddress((void**)&Qh,  g_Qh);
    cudaGetSymbolAddress((void**)&Kh,  g_Kh);
    cudaGetSymbolAddress((void**)&Vh,  g_Vh);
    cudaGetSymbolAddress((void**)&ctx, g_ctx);

    dim3 ggrid(512 / 128, MROWS / 128);   // (4, 64)
    gemm512_kernel<2><<<ggrid, 256>>>(q, Wq, bq, Qh);
    gemm512_kernel<2><<<ggrid, 256>>>(k, Wk, bk, Kh);
    gemm512_kernel<1><<<ggrid, 256>>>(v, Wv, bv, Vh);

    const int ATTN_SMEM = (64 * STRQ + 128 * STRK + 128 * STRV) * (int)sizeof(float);
    cudaFuncSetAttribute(attn_kernel,
                         cudaFuncAttributeMaxDynamicSharedMemorySize, ATTN_SMEM);
    attn_kernel<<<dim3(SEQ / 128, BATCH * HEADS), 256, ATTN_SMEM>>>(
        Qh, Kh, Vh, mask, ctx);

    gemm512_kernel<0><<<ggrid, 256>>>(ctx, Wo, bo, out);
}

// round 5
// speedup vs baseline: 1.3738x; 1.2028x over previous
#include <cuda_runtime.h>
#include <cuda.h>
#include <math.h>

#define EMBED 512
#define HEADS 8
#define DEPTH 64
#define BATCH 2
#define SEQ   4096
#define MROWS (BATCH * SEQ)          // 8192

typedef unsigned long long u64;
typedef unsigned int u32;

// ---------------------------------------------------------------------------
// f32x2 packed-FMA helpers (projection GEMMs)
// ---------------------------------------------------------------------------
__device__ __forceinline__ u64 splat2(float v) {
    u64 r; asm("mov.b64 %0, {%1, %1};" : "=l"(r) : "f"(v)); return r;
}
__device__ __forceinline__ float2 unpack2(u64 v) {
    float2 r; asm("mov.b64 {%0, %1}, %2;" : "=f"(r.x), "=f"(r.y) : "l"(v)); return r;
}
__device__ __forceinline__ void fma2(u64& d, u64 a, u64 b) {
    asm("fma.rn.f32x2 %0, %1, %2, %0;" : "+l"(d) : "l"(a), "l"(b));
}
union F4U { float4 f; struct { u64 lo, hi; } u; };

// ---------------------------------------------------------------------------
// Device scratch
// ---------------------------------------------------------------------------
__device__ float g_Qh[BATCH * HEADS * SEQ * DEPTH];   // [B,H,S,D]
__device__ float g_Kh[BATCH * HEADS * SEQ * DEPTH];   // [B,H,S,D]
__device__ float g_Vh[BATCH * HEADS * DEPTH * SEQ];   // [B,H,D,S] (d-major)
__device__ float g_ctx[BATCH * SEQ * EMBED];          // [B,S,E]

// ---------------------------------------------------------------------------
// GEMM: 8192x512 @ 512x512 + bias (FFMA2)  -- unchanged from R3
// MODE 0: C row-major; MODE 1: C -> [B,H,S,D]; MODE 2: C^T -> [B,H,D,S]
// ---------------------------------------------------------------------------
template <int MODE>
__global__ __launch_bounds__(256, 2) void gemm512_kernel(
    const float* __restrict__ A, const float* __restrict__ W,
    const float* __restrict__ bias, float* __restrict__ C)
{
    __shared__ float As[16][132];
    __shared__ float Ws[16][128];

    const int tid = threadIdx.x;
    const int tx  = tid & 15;
    const int ty  = tid >> 4;
    const int m0  = blockIdx.y * 128;
    const int n0  = blockIdx.x * 128;

    u64 acc[8][4];
#pragma unroll
    for (int i = 0; i < 8; ++i)
#pragma unroll
        for (int j = 0; j < 4; ++j) acc[i][j] = 0ull;

    for (int k0 = 0; k0 < 512; k0 += 16) {
#pragma unroll
        for (int l = 0; l < 2; ++l) {
            int idx = tid + l * 256;
            int row = idx >> 2;
            int k4  = (idx & 3) * 4;
            float4 av = *(const float4*)(A + (size_t)(m0 + row) * 512 + k0 + k4);
            As[k4 + 0][row] = av.x;
            As[k4 + 1][row] = av.y;
            As[k4 + 2][row] = av.z;
            As[k4 + 3][row] = av.w;
        }
#pragma unroll
        for (int l = 0; l < 2; ++l) {
            int idx = tid + l * 256;
            int kk  = idx >> 5;
            int n4  = (idx & 31) * 4;
            *(float4*)&Ws[kk][n4] =
                *(const float4*)(W + (size_t)(k0 + kk) * 512 + n0 + n4);
        }
        __syncthreads();

#pragma unroll
        for (int kk = 0; kk < 16; ++kk) {
            float a[8];
            F4U b0, b1;
            if (MODE == 2) {
                *(float4*)&a[0] = *(float4*)&Ws[kk][ty * 8];
                *(float4*)&a[4] = *(float4*)&Ws[kk][ty * 8 + 4];
                b0.f = *(float4*)&As[kk][tx * 8];
                b1.f = *(float4*)&As[kk][tx * 8 + 4];
            } else {
                *(float4*)&a[0] = *(float4*)&As[kk][ty * 8];
                *(float4*)&a[4] = *(float4*)&As[kk][ty * 8 + 4];
                b0.f = *(float4*)&Ws[kk][tx * 8];
                b1.f = *(float4*)&Ws[kk][tx * 8 + 4];
            }
#pragma unroll
            for (int i = 0; i < 8; ++i) {
                u64 as = splat2(a[i]);
                fma2(acc[i][0], as, b0.u.lo);
                fma2(acc[i][1], as, b0.u.hi);
                fma2(acc[i][2], as, b1.u.lo);
                fma2(acc[i][3], as, b1.u.hi);
            }
        }
        __syncthreads();
    }

    float accf[8][8];
#pragma unroll
    for (int i = 0; i < 8; ++i)
#pragma unroll
        for (int jp = 0; jp < 4; ++jp) {
            float2 u = unpack2(acc[i][jp]);
            accf[i][jp * 2]     = u.x;
            accf[i][jp * 2 + 1] = u.y;
        }

    if (MODE == 0) {
#pragma unroll
        for (int i = 0; i < 8; ++i) {
            int m = m0 + ty * 8 + i;
            float* crow = C + (size_t)m * 512 + n0 + tx * 8;
            const float* bp = bias + n0 + tx * 8;
            float4 o0, o1;
            o0.x = accf[i][0] + bp[0]; o0.y = accf[i][1] + bp[1];
            o0.z = accf[i][2] + bp[2]; o0.w = accf[i][3] + bp[3];
            o1.x = accf[i][4] + bp[4]; o1.y = accf[i][5] + bp[5];
            o1.z = accf[i][6] + bp[6]; o1.w = accf[i][7] + bp[7];
            *(float4*)&crow[0] = o0;
            *(float4*)&crow[4] = o1;
        }
    } else if (MODE == 1) {
#pragma unroll
        for (int i = 0; i < 8; ++i) {
            int m = m0 + ty * 8 + i;
            int b = m >> 12;
            int s = m & 4095;
            int nbase = n0 + tx * 8;
            int h = nbase >> 6;
            int d = nbase & 63;
            float* dst = C + ((size_t)(b * HEADS + h) * SEQ + s) * DEPTH + d;
            const float* bp = bias + nbase;
            float4 o0, o1;
            o0.x = accf[i][0] + bp[0]; o0.y = accf[i][1] + bp[1];
            o0.z = accf[i][2] + bp[2]; o0.w = accf[i][3] + bp[3];
            o1.x = accf[i][4] + bp[4]; o1.y = accf[i][5] + bp[5];
            o1.z = accf[i][6] + bp[6]; o1.w = accf[i][7] + bp[7];
            *(float4*)&dst[0] = o0;
            *(float4*)&dst[4] = o1;
        }
    } else {
        int b  = m0 >> 12;
        int s0 = (m0 & 4095) + tx * 8;
#pragma unroll
        for (int i = 0; i < 8; ++i) {
            int n = n0 + ty * 8 + i;
            int h = n >> 6;
            int d = n & 63;
            float bi = bias[n];
            float* dst = C + ((size_t)(b * HEADS + h) * DEPTH + d) * SEQ + s0;
            float4 o0, o1;
            o0.x = accf[i][0] + bi; o0.y = accf[i][1] + bi;
            o0.z = accf[i][2] + bi; o0.w = accf[i][3] + bi;
            o1.x = accf[i][4] + bi; o1.y = accf[i][5] + bi;
            o1.z = accf[i][6] + bi; o1.w = accf[i][7] + bi;
            *(float4*)&dst[0] = o0;
            *(float4*)&dst[4] = o1;
        }
    }
}

// ---------------------------------------------------------------------------
// mma.sync tf32 helpers (baseline PTX, works on compute_103)
// ---------------------------------------------------------------------------
__device__ __forceinline__ u32 tf32r(float x) {
    u32 r; asm("cvt.rna.tf32.f32 %0, %1;" : "=r"(r) : "f"(x)); return r;
}
__device__ __forceinline__ void mma_tf32(float c[4], const u32 a[4], u32 b0, u32 b1) {
    asm("mma.sync.aligned.m16n8k8.row.col.f32.tf32.tf32.f32 "
        "{%0,%1,%2,%3}, {%4,%5,%6,%7}, {%8,%9}, {%0,%1,%2,%3};"
        : "+f"(c[0]), "+f"(c[1]), "+f"(c[2]), "+f"(c[3])
        : "r"(a[0]), "r"(a[1]), "r"(a[2]), "r"(a[3]), "r"(b0), "r"(b1));
}

// smem layout (bytes)
#define SM_MASK 0                       // 128 floats
#define SM_KP   1024                    // 16nt*8ks*32t*16B = 65536
#define SM_VP   (SM_KP + 65536)         // 8nt*16ks*32t*16B = 65536
#define SM_PP   (SM_VP + 65536)         // 8 warps * 8192B   = 65536
#define SM_TOT  (SM_PP + 65536)         // 197632

// ---------------------------------------------------------------------------
// Flash attention on mma.sync tf32.
// 128 Q rows/CTA, 128-key tiles, 8 warps (warp w owns Q rows 16w..16w+15).
// QK^T: Qhi*Khi + Qlo*Khi + Qhi*Klo. PV: P*(Vhi) + P*(Vlo). No online max.
// ---------------------------------------------------------------------------
__global__ __launch_bounds__(256, 1) void attn_mma(
    const float* __restrict__ Qg, const float* __restrict__ Kg,
    const float* __restrict__ Vg, const float* __restrict__ mask,
    float* __restrict__ ctx)
{
    extern __shared__ char smem[];
    float*  smask = (float*)(smem + SM_MASK);
    float4* KP    = (float4*)(smem + SM_KP);
    float4* VP    = (float4*)(smem + SM_VP);

    const int tid  = threadIdx.x;
    const int w    = tid >> 5;
    const int lane = tid & 31;
    const int g    = lane >> 2;       // group id (row within frag)
    const int t4   = lane & 3;        // thread in group
    const int bh   = blockIdx.y, b = bh >> 3, h = bh & 7;
    const int qi0  = blockIdx.x * 128;

    const float* Qb = Qg + (size_t)bh * SEQ * DEPTH;
    const float* Kb = Kg + (size_t)bh * SEQ * DEPTH;
    const float* Vb = Vg + (size_t)bh * DEPTH * SEQ;
    const float* mb = mask + (size_t)b * SEQ;

    // ---- Q fragments in registers (hi/lo split), rows 16w+g / 16w+g+8 ----
    u32 qhi[8][4], qlo[8][4];
    {
        const float* q0 = Qb + (size_t)(qi0 + 16 * w + g) * DEPTH;
        const float* q1 = q0 + 8 * DEPTH;
#pragma unroll
        for (int ks = 0; ks < 8; ++ks) {
            float x0 = q0[ks * 8 + t4];
            float x1 = q1[ks * 8 + t4];
            float x2 = q0[ks * 8 + t4 + 4];
            float x3 = q1[ks * 8 + t4 + 4];
            qhi[ks][0] = tf32r(x0); qlo[ks][0] = tf32r(x0 - __uint_as_float(qhi[ks][0]));
            qhi[ks][1] = tf32r(x1); qlo[ks][1] = tf32r(x1 - __uint_as_float(qhi[ks][1]));
            qhi[ks][2] = tf32r(x2); qlo[ks][2] = tf32r(x2 - __uint_as_float(qhi[ks][2]));
            qhi[ks][3] = tf32r(x3); qlo[ks][3] = tf32r(x3 - __uint_as_float(qhi[ks][3]));
        }
    }

    float oacc[8][4];
#pragma unroll
    for (int nt = 0; nt < 8; ++nt)
#pragma unroll
        for (int e = 0; e < 4; ++e) oacc[nt][e] = 0.0f;
    float lsum0 = 0.0f, lsum1 = 0.0f;

    float* PPw = (float*)(smem + SM_PP + w * 8192);

    for (int jt = 0; jt < SEQ / 128; ++jt) {
        const int j0 = jt * 128;
        __syncthreads();   // prior PV reads of VP/KP done

        // ---- fill K tile: cells (nt16, ks8, t32) -> [b0hi,b1hi,b0lo,b1lo] ----
#pragma unroll
        for (int it = 0; it < 16; ++it) {
            int cell = tid + it * 256;
            int t  = cell & 31, ks = (cell >> 5) & 7, nt = cell >> 8;
            int gg = t >> 2,  tt = t & 3;
            const float* src = Kb + (size_t)(j0 + nt * 8 + gg) * DEPTH + ks * 8 + tt;
            float x0 = src[0], x1 = src[4];
            u32 h0 = tf32r(x0), h1 = tf32r(x1);
            u32 l0 = tf32r(x0 - __uint_as_float(h0));
            u32 l1 = tf32r(x1 - __uint_as_float(h1));
            float4 v;
            v.x = __uint_as_float(h0); v.y = __uint_as_float(h1);
            v.z = __uint_as_float(l0); v.w = __uint_as_float(l1);
            KP[(nt * 8 + ks) * 32 + t] = v;
        }
        // ---- fill V^T tile: cells (nt8, ks16, t32) ----
#pragma unroll
        for (int it = 0; it < 16; ++it) {
            int cell = tid + it * 256;
            int t  = cell & 31, ks = (cell >> 5) & 15, nt = cell >> 9;
            int gg = t >> 2,  tt = t & 3;
            const float* src = Vb + (size_t)(nt * 8 + gg) * SEQ + j0 + ks * 8 + tt;
            float x0 = src[0], x1 = src[4];
            u32 h0 = tf32r(x0), h1 = tf32r(x1);
            u32 l0 = tf32r(x0 - __uint_as_float(h0));
            u32 l1 = tf32r(x1 - __uint_as_float(h1));
            float4 v;
            v.x = __uint_as_float(h0); v.y = __uint_as_float(h1);
            v.z = __uint_as_float(l0); v.w = __uint_as_float(l1);
            VP[(nt * 16 + ks) * 32 + t] = v;
        }
        if (tid < 128) smask[tid] = mb[j0 + tid] * (-1e9f);
        __syncthreads();

        // ---- S = Q K^T ----
        float sacc[16][4];
#pragma unroll
        for (int nt = 0; nt < 16; ++nt)
#pragma unroll
            for (int e = 0; e < 4; ++e) sacc[nt][e] = 0.0f;

#pragma unroll
        for (int nt = 0; nt < 16; ++nt) {
#pragma unroll
            for (int ks = 0; ks < 8; ++ks) {
                float4 bb = KP[(nt * 8 + ks) * 32 + lane];
                u32 bh0 = __float_as_uint(bb.x), bh1 = __float_as_uint(bb.y);
                u32 bl0 = __float_as_uint(bb.z), bl1 = __float_as_uint(bb.w);
                mma_tf32(sacc[nt], qhi[ks], bh0, bh1);
                mma_tf32(sacc[nt], qlo[ks], bh0, bh1);
                mma_tf32(sacc[nt], qhi[ks], bl0, bl1);
            }
        }

        // ---- softmax (no max-sub) + scatter P into A-fragment layout ----
#pragma unroll
        for (int nt = 0; nt < 16; ++nt) {
#pragma unroll
            for (int e = 0; e < 2; ++e) {
                int c   = nt * 8 + 2 * t4 + e;
                int kin = 2 * t4 + e;
                float mk = smask[c];
                float p0 = __expf(fmaf(sacc[nt][e],     0.125f, mk));   // row g
                float p1 = __expf(fmaf(sacc[nt][2 + e], 0.125f, mk));   // row g+8
                u32 r0 = tf32r(p0), r1 = tf32r(p1);
                lsum0 += __uint_as_float(r0);
                lsum1 += __uint_as_float(r1);
                int tr   = g * 4 + (kin & 3);
                int slot = (kin >= 4) ? 2 : 0;
                PPw[(nt * 32 + tr) * 4 + slot]     = __uint_as_float(r0);
                PPw[(nt * 32 + tr) * 4 + slot + 1] = __uint_as_float(r1);
            }
        }
        __syncwarp();

        // ---- O += P V ----
#pragma unroll
        for (int ks = 0; ks < 16; ++ks) {
            float4 a4 = ((float4*)PPw)[ks * 32 + lane];
            u32 ap[4] = { __float_as_uint(a4.x), __float_as_uint(a4.y),
                          __float_as_uint(a4.z), __float_as_uint(a4.w) };
#pragma unroll
            for (int nt = 0; nt < 8; ++nt) {
                float4 bv = VP[(nt * 16 + ks) * 32 + lane];
                mma_tf32(oacc[nt], ap, __float_as_uint(bv.x), __float_as_uint(bv.y));
                mma_tf32(oacc[nt], ap, __float_as_uint(bv.z), __float_as_uint(bv.w));
            }
        }
        __syncwarp();
    }

    // ---- epilogue: reduce lsum over the 4-thread group, normalize, store ----
    lsum0 += __shfl_xor_sync(0xffffffffu, lsum0, 1);
    lsum0 += __shfl_xor_sync(0xffffffffu, lsum0, 2);
    lsum1 += __shfl_xor_sync(0xffffffffu, lsum1, 1);
    lsum1 += __shfl_xor_sync(0xffffffffu, lsum1, 2);
    float inv0 = 1.0f / lsum0, inv1 = 1.0f / lsum1;

    int row0 = qi0 + 16 * w + g;
    float* dst0 = ctx + ((size_t)(b * SEQ + row0)) * EMBED + h * DEPTH;
    float* dst1 = dst0 + (size_t)8 * EMBED;
#pragma unroll
    for (int nt = 0; nt < 8; ++nt) {
        int c = nt * 8 + 2 * t4;
        float2 o0 = make_float2(oacc[nt][0] * inv0, oacc[nt][1] * inv0);
        float2 o1 = make_float2(oacc[nt][2] * inv1, oacc[nt][3] * inv1);
        *(float2*)(dst0 + c) = o0;
        *(float2*)(dst1 + c) = o1;
    }
}

// ---------------------------------------------------------------------------
// Launcher
// ---------------------------------------------------------------------------
extern "C" void kernel_launch(void* const* d_in, const int* in_sizes, int n_in,
                              void* d_out, int out_size)
{
    const float* q    = (const float*)d_in[0];
    const float* k    = (const float*)d_in[1];
    const float* v    = (const float*)d_in[2];
    const float* mask = (const float*)d_in[3];
    const float* Wq   = (const float*)d_in[4];
    const float* bq   = (const float*)d_in[5];
    const float* Wk   = (const float*)d_in[6];
    const float* bk   = (const float*)d_in[7];
    const float* Wv   = (const float*)d_in[8];
    const float* bv   = (const float*)d_in[9];
    const float* Wo   = (const float*)d_in[10];
    const float* bo   = (const float*)d_in[11];
    float* out = (float*)d_out;

    float *Qh, *Kh, *Vh, *ctx;
    cudaGetSymbolAddress((void**)&Qh,  g_Qh);
    cudaGetSymbolAddress((void**)&Kh,  g_Kh);
    cudaGetSymbolAddress((void**)&Vh,  g_Vh);
    cudaGetSymbolAddress((void**)&ctx, g_ctx);

    dim3 ggrid(512 / 128, MROWS / 128);   // (4, 64)
    gemm512_kernel<1><<<ggrid, 256>>>(q, Wq, bq, Qh);   // [B,H,S,D]
    gemm512_kernel<1><<<ggrid, 256>>>(k, Wk, bk, Kh);   // [B,H,S,D]
    gemm512_kernel<2><<<ggrid, 256>>>(v, Wv, bv, Vh);   // [B,H,D,S]

    cudaFuncSetAttribute(attn_mma, cudaFuncAttributeMaxDynamicSharedMemorySize, SM_TOT);
    attn_mma<<<dim3(SEQ / 128, BATCH * HEADS), 256, SM_TOT>>>(Qh, Kh, Vh, mask, ctx);

    gemm512_kernel<0><<<ggrid, 256>>>(ctx, Wo, bo, out);
}

// round 6
// speedup vs baseline: 2.3245x; 1.6920x over previous
#include <cuda_runtime.h>
#include <cuda.h>
#include <cuda_fp16.h>
#include <math.h>

#define EMBED 512
#define HEADS 8
#define DEPTH 64
#define BATCH 2
#define SEQ   4096
#define MROWS (BATCH * SEQ)          // 8192

typedef unsigned long long u64;
typedef unsigned int u32;

// ---------------------------------------------------------------------------
// f32x2 packed-FMA helpers (projection GEMMs)
// ---------------------------------------------------------------------------
__device__ __forceinline__ u64 splat2(float v) {
    u64 r; asm("mov.b64 %0, {%1, %1};" : "=l"(r) : "f"(v)); return r;
}
__device__ __forceinline__ float2 unpack2(u64 v) {
    float2 r; asm("mov.b64 {%0, %1}, %2;" : "=f"(r.x), "=f"(r.y) : "l"(v)); return r;
}
__device__ __forceinline__ void fma2(u64& d, u64 a, u64 b) {
    asm("fma.rn.f32x2 %0, %1, %2, %0;" : "+l"(d) : "l"(a), "l"(b));
}
union F4U { float4 f; struct { u64 lo, hi; } u; };

// ---------------------------------------------------------------------------
// Device scratch
// ---------------------------------------------------------------------------
__device__ float g_Qh[BATCH * HEADS * SEQ * DEPTH];   // [B,H,S,D]
__device__ float g_Kh[BATCH * HEADS * SEQ * DEPTH];   // [B,H,S,D]
__device__ float g_Vh[BATCH * HEADS * DEPTH * SEQ];   // [B,H,D,S] (d-major)
__device__ float g_ctx[BATCH * SEQ * EMBED];          // [B,S,E]

// ---------------------------------------------------------------------------
// GEMM: 8192x512 @ 512x512 + bias (FFMA2)
// MODE 0: C row-major; MODE 1: C -> [B,H,S,D]; MODE 2: C^T -> [B,H,D,S]
// ---------------------------------------------------------------------------
template <int MODE>
__global__ __launch_bounds__(256, 2) void gemm512_kernel(
    const float* __restrict__ A, const float* __restrict__ W,
    const float* __restrict__ bias, float* __restrict__ C)
{
    __shared__ float As[16][132];
    __shared__ float Ws[16][128];

    const int tid = threadIdx.x;
    const int tx  = tid & 15;
    const int ty  = tid >> 4;
    const int m0  = blockIdx.y * 128;
    const int n0  = blockIdx.x * 128;

    u64 acc[8][4];
#pragma unroll
    for (int i = 0; i < 8; ++i)
#pragma unroll
        for (int j = 0; j < 4; ++j) acc[i][j] = 0ull;

    for (int k0 = 0; k0 < 512; k0 += 16) {
#pragma unroll
        for (int l = 0; l < 2; ++l) {
            int idx = tid + l * 256;
            int row = idx >> 2;
            int k4  = (idx & 3) * 4;
            float4 av = *(const float4*)(A + (size_t)(m0 + row) * 512 + k0 + k4);
            As[k4 + 0][row] = av.x;
            As[k4 + 1][row] = av.y;
            As[k4 + 2][row] = av.z;
            As[k4 + 3][row] = av.w;
        }
#pragma unroll
        for (int l = 0; l < 2; ++l) {
            int idx = tid + l * 256;
            int kk  = idx >> 5;
            int n4  = (idx & 31) * 4;
            *(float4*)&Ws[kk][n4] =
                *(const float4*)(W + (size_t)(k0 + kk) * 512 + n0 + n4);
        }
        __syncthreads();

#pragma unroll
        for (int kk = 0; kk < 16; ++kk) {
            float a[8];
            F4U b0, b1;
            if (MODE == 2) {
                *(float4*)&a[0] = *(float4*)&Ws[kk][ty * 8];
                *(float4*)&a[4] = *(float4*)&Ws[kk][ty * 8 + 4];
                b0.f = *(float4*)&As[kk][tx * 8];
                b1.f = *(float4*)&As[kk][tx * 8 + 4];
            } else {
                *(float4*)&a[0] = *(float4*)&As[kk][ty * 8];
                *(float4*)&a[4] = *(float4*)&As[kk][ty * 8 + 4];
                b0.f = *(float4*)&Ws[kk][tx * 8];
                b1.f = *(float4*)&Ws[kk][tx * 8 + 4];
            }
#pragma unroll
            for (int i = 0; i < 8; ++i) {
                u64 as = splat2(a[i]);
                fma2(acc[i][0], as, b0.u.lo);
                fma2(acc[i][1], as, b0.u.hi);
                fma2(acc[i][2], as, b1.u.lo);
                fma2(acc[i][3], as, b1.u.hi);
            }
        }
        __syncthreads();
    }

    float accf[8][8];
#pragma unroll
    for (int i = 0; i < 8; ++i)
#pragma unroll
        for (int jp = 0; jp < 4; ++jp) {
            float2 u = unpack2(acc[i][jp]);
            accf[i][jp * 2]     = u.x;
            accf[i][jp * 2 + 1] = u.y;
        }

    if (MODE == 0) {
#pragma unroll
        for (int i = 0; i < 8; ++i) {
            int m = m0 + ty * 8 + i;
            float* crow = C + (size_t)m * 512 + n0 + tx * 8;
            const float* bp = bias + n0 + tx * 8;
            float4 o0, o1;
            o0.x = accf[i][0] + bp[0]; o0.y = accf[i][1] + bp[1];
            o0.z = accf[i][2] + bp[2]; o0.w = accf[i][3] + bp[3];
            o1.x = accf[i][4] + bp[4]; o1.y = accf[i][5] + bp[5];
            o1.z = accf[i][6] + bp[6]; o1.w = accf[i][7] + bp[7];
            *(float4*)&crow[0] = o0;
            *(float4*)&crow[4] = o1;
        }
    } else if (MODE == 1) {
#pragma unroll
        for (int i = 0; i < 8; ++i) {
            int m = m0 + ty * 8 + i;
            int b = m >> 12;
            int s = m & 4095;
            int nbase = n0 + tx * 8;
            int h = nbase >> 6;
            int d = nbase & 63;
            float* dst = C + ((size_t)(b * HEADS + h) * SEQ + s) * DEPTH + d;
            const float* bp = bias + nbase;
            float4 o0, o1;
            o0.x = accf[i][0] + bp[0]; o0.y = accf[i][1] + bp[1];
            o0.z = accf[i][2] + bp[2]; o0.w = accf[i][3] + bp[3];
            o1.x = accf[i][4] + bp[4]; o1.y = accf[i][5] + bp[5];
            o1.z = accf[i][6] + bp[6]; o1.w = accf[i][7] + bp[7];
            *(float4*)&dst[0] = o0;
            *(float4*)&dst[4] = o1;
        }
    } else {
        int b  = m0 >> 12;
        int s0 = (m0 & 4095) + tx * 8;
#pragma unroll
        for (int i = 0; i < 8; ++i) {
            int n = n0 + ty * 8 + i;
            int h = n >> 6;
            int d = n & 63;
            float bi = bias[n];
            float* dst = C + ((size_t)(b * HEADS + h) * DEPTH + d) * SEQ + s0;
            float4 o0, o1;
            o0.x = accf[i][0] + bi; o0.y = accf[i][1] + bi;
            o0.z = accf[i][2] + bi; o0.w = accf[i][3] + bi;
            o1.x = accf[i][4] + bi; o1.y = accf[i][5] + bi;
            o1.z = accf[i][6] + bi; o1.w = accf[i][7] + bi;
            *(float4*)&dst[0] = o0;
            *(float4*)&dst[4] = o1;
        }
    }
}

// ---------------------------------------------------------------------------
// fp16 mma.sync helpers (baseline PTX, compute_103-safe)
// ---------------------------------------------------------------------------
__device__ __forceinline__ void mma16(float c[4], const u32 a[4], u32 b0, u32 b1) {
    asm("mma.sync.aligned.m16n8k16.row.col.f32.f16.f16.f32 "
        "{%0,%1,%2,%3}, {%4,%5,%6,%7}, {%8,%9}, {%0,%1,%2,%3};"
        : "+f"(c[0]), "+f"(c[1]), "+f"(c[2]), "+f"(c[3])
        : "r"(a[0]), "r"(a[1]), "r"(a[2]), "r"(a[3]), "r"(b0), "r"(b1));
}
__device__ __forceinline__ u32 f2h2(float lo, float hi) {
    __half2 h = __float22half2_rn(make_float2(lo, hi));   // .x -> low 16 bits
    return *(u32*)&h;
}
__device__ __forceinline__ float2 h22f(u32 v) {
    __half2 h = *(__half2*)&v;
    return __half22float2(h);
}
// hi/lo split of a float2 into two half2 words
__device__ __forceinline__ void split2(float2 x, u32& hi, u32& lo) {
    hi = f2h2(x.x, x.y);
    float2 back = h22f(hi);
    lo = f2h2(x.x - back.x, x.y - back.y);
}

// smem layout (bytes)
#define SM_MASK 0                       // 128 floats
#define SM_KC   1024                    // 16nt*4ks*32ln*16B = 32768
#define SM_VC   (SM_KC + 32768)         // 8nt*8ks*32ln*16B  = 32768
#define SM_TOT  (SM_VC + 32768)         // 66560

// ---------------------------------------------------------------------------
// Flash attention on mma.sync fp16 (hi/lo error-compensated).
// 128 Q rows/CTA, 128-key tiles, 8 warps; warp w owns Q rows 16w..16w+15.
// QK^T: Qhi*Khi + Qlo*Khi + Qhi*Klo.  PV: P*Vhi + P*Vlo.
// P stays in registers: C-frag of QK^T == A-frag of PV (fp16 m16n8k16).
// ---------------------------------------------------------------------------
__global__ __launch_bounds__(256, 2) void attn_mma(
    const float* __restrict__ Qg, const float* __restrict__ Kg,
    const float* __restrict__ Vg, const float* __restrict__ mask,
    float* __restrict__ ctx)
{
    extern __shared__ char smem[];
    float* smask = (float*)(smem + SM_MASK);
    uint4* KC    = (uint4*)(smem + SM_KC);
    uint4* VC    = (uint4*)(smem + SM_VC);

    const int tid  = threadIdx.x;
    const int w    = tid >> 5;
    const int lane = tid & 31;
    const int g    = lane >> 2;
    const int t4   = lane & 3;
    const int bh   = blockIdx.y, b = bh >> 3, h = bh & 7;
    const int qi0  = blockIdx.x * 128;

    const float* Qb = Qg + (size_t)bh * SEQ * DEPTH;
    const float* Kb = Kg + (size_t)bh * SEQ * DEPTH;
    const float* Vb = Vg + (size_t)bh * DEPTH * SEQ;
    const float* mb = mask + (size_t)b * SEQ;

    // ---- Q fragments in registers (hi/lo), rows 16w+g / 16w+g+8 ----
    u32 qhi[4][4], qlo[4][4];
    {
        const float* q0 = Qb + (size_t)(qi0 + 16 * w + g) * DEPTH;
#pragma unroll
        for (int ks = 0; ks < 4; ++ks) {
            int d0 = ks * 16 + 2 * t4;
            float2 x0 = *(const float2*)(q0 + d0);                 // a0: row g,  k,k+1
            float2 x1 = *(const float2*)(q0 + 8 * DEPTH + d0);     // a1: row g+8
            float2 x2 = *(const float2*)(q0 + d0 + 8);             // a2: row g,  k+8,k+9
            float2 x3 = *(const float2*)(q0 + 8 * DEPTH + d0 + 8); // a3: row g+8
            split2(x0, qhi[ks][0], qlo[ks][0]);
            split2(x1, qhi[ks][1], qlo[ks][1]);
            split2(x2, qhi[ks][2], qlo[ks][2]);
            split2(x3, qhi[ks][3], qlo[ks][3]);
        }
    }

    float oacc[8][4];
#pragma unroll
    for (int nt = 0; nt < 8; ++nt)
#pragma unroll
        for (int e = 0; e < 4; ++e) oacc[nt][e] = 0.0f;
    float lsum0 = 0.0f, lsum1 = 0.0f;

    for (int jt = 0; jt < SEQ / 128; ++jt) {
        const int j0 = jt * 128;
        __syncthreads();   // prior tile fully consumed

        // ---- K cells: (nt16, ks4, ln32) -> {b0hi,b1hi,b0lo,b1lo} ----
#pragma unroll
        for (int it = 0; it < 8; ++it) {
            int cell = tid + it * 256;
            int ln = cell & 31, ks = (cell >> 5) & 3, nt = cell >> 7;
            int gg = ln >> 2, tt = ln & 3;
            const float* src = Kb + (size_t)(j0 + nt * 8 + gg) * DEPTH + ks * 16 + 2 * tt;
            float2 x0 = *(const float2*)src;
            float2 x1 = *(const float2*)(src + 8);
            uint4 cv;
            split2(x0, cv.x, cv.z);
            split2(x1, cv.y, cv.w);
            KC[(nt * 4 + ks) * 32 + ln] = cv;
        }
        // ---- V cells: (nt8, ks8, ln32); V^T B-frag from d-major V ----
#pragma unroll
        for (int it = 0; it < 8; ++it) {
            int cell = tid + it * 256;
            int ln = cell & 31, ks = (cell >> 5) & 7, nt = cell >> 8;
            int gg = ln >> 2, tt = ln & 3;
            const float* src = Vb + (size_t)(nt * 8 + gg) * SEQ + j0 + ks * 16 + 2 * tt;
            float2 x0 = *(const float2*)src;
            float2 x1 = *(const float2*)(src + 8);
            uint4 cv;
            split2(x0, cv.x, cv.z);
            split2(x1, cv.y, cv.w);
            VC[(nt * 8 + ks) * 32 + ln] = cv;
        }
        if (tid < 128) smask[tid] = mb[j0 + tid] * (-1e9f);
        __syncthreads();

        // ---- per nt-pair: QK^T MMAs -> exp -> pack P A-frags in registers ----
        u32 pa[8][4];
#pragma unroll
        for (int kp = 0; kp < 8; ++kp) {
            float sacc[2][4] = {{0.f,0.f,0.f,0.f},{0.f,0.f,0.f,0.f}};
#pragma unroll
            for (int i = 0; i < 2; ++i) {
                int nt = kp * 2 + i;
#pragma unroll
                for (int ks = 0; ks < 4; ++ks) {
                    uint4 cv = KC[(nt * 4 + ks) * 32 + lane];
                    mma16(sacc[i], qhi[ks], cv.x, cv.y);
                    mma16(sacc[i], qlo[ks], cv.x, cv.y);
                    mma16(sacc[i], qhi[ks], cv.z, cv.w);
                }
            }
            // exp + pack: cols c = nt*8 + 2*t4 + e
            float p[2][4];
#pragma unroll
            for (int i = 0; i < 2; ++i) {
                int c0 = (kp * 2 + i) * 8 + 2 * t4;
                float mk0 = smask[c0], mk1 = smask[c0 + 1];
                p[i][0] = __expf(fmaf(sacc[i][0], 0.125f, mk0));   // row g
                p[i][1] = __expf(fmaf(sacc[i][1], 0.125f, mk1));
                p[i][2] = __expf(fmaf(sacc[i][2], 0.125f, mk0));   // row g+8
                p[i][3] = __expf(fmaf(sacc[i][3], 0.125f, mk1));
                lsum0 += p[i][0] + p[i][1];
                lsum1 += p[i][2] + p[i][3];
            }
            pa[kp][0] = f2h2(p[0][0], p[0][1]);   // a0: row g,  k0,k0+1
            pa[kp][1] = f2h2(p[0][2], p[0][3]);   // a1: row g+8
            pa[kp][2] = f2h2(p[1][0], p[1][1]);   // a2: row g,  k0+8,k0+9
            pa[kp][3] = f2h2(p[1][2], p[1][3]);   // a3: row g+8
        }

        // ---- O += P V  (P in registers) ----
#pragma unroll
        for (int ks = 0; ks < 8; ++ks) {
#pragma unroll
            for (int nt = 0; nt < 8; ++nt) {
                uint4 cv = VC[(nt * 8 + ks) * 32 + lane];
                mma16(oacc[nt], pa[ks], cv.x, cv.y);
                mma16(oacc[nt], pa[ks], cv.z, cv.w);
            }
        }
    }

    // ---- epilogue ----
    lsum0 += __shfl_xor_sync(0xffffffffu, lsum0, 1);
    lsum0 += __shfl_xor_sync(0xffffffffu, lsum0, 2);
    lsum1 += __shfl_xor_sync(0xffffffffu, lsum1, 1);
    lsum1 += __shfl_xor_sync(0xffffffffu, lsum1, 2);
    float inv0 = 1.0f / lsum0, inv1 = 1.0f / lsum1;

    int row0 = qi0 + 16 * w + g;
    float* dst0 = ctx + ((size_t)(b * SEQ + row0)) * EMBED + h * DEPTH;
    float* dst1 = dst0 + (size_t)8 * EMBED;
#pragma unroll
    for (int nt = 0; nt < 8; ++nt) {
        int c = nt * 8 + 2 * t4;
        *(float2*)(dst0 + c) = make_float2(oacc[nt][0] * inv0, oacc[nt][1] * inv0);
        *(float2*)(dst1 + c) = make_float2(oacc[nt][2] * inv1, oacc[nt][3] * inv1);
    }
}

// ---------------------------------------------------------------------------
// Launcher
// ---------------------------------------------------------------------------
extern "C" void kernel_launch(void* const* d_in, const int* in_sizes, int n_in,
                              void* d_out, int out_size)
{
    const float* q    = (const float*)d_in[0];
    const float* k    = (const float*)d_in[1];
    const float* v    = (const float*)d_in[2];
    const float* mask = (const float*)d_in[3];
    const float* Wq   = (const float*)d_in[4];
    const float* bq   = (const float*)d_in[5];
    const float* Wk   = (const float*)d_in[6];
    const float* bk   = (const float*)d_in[7];
    const float* Wv   = (const float*)d_in[8];
    const float* bv   = (const float*)d_in[9];
    const float* Wo   = (const float*)d_in[10];
    const float* bo   = (const float*)d_in[11];
    float* out = (float*)d_out;

    float *Qh, *Kh, *Vh, *ctx;
    cudaGetSymbolAddress((void**)&Qh,  g_Qh);
    cudaGetSymbolAddress((void**)&Kh,  g_Kh);
    cudaGetSymbolAddress((void**)&Vh,  g_Vh);
    cudaGetSymbolAddress((void**)&ctx, g_ctx);

    dim3 ggrid(512 / 128, MROWS / 128);   // (4, 64)
    gemm512_kernel<1><<<ggrid, 256>>>(q, Wq, bq, Qh);   // [B,H,S,D]
    gemm512_kernel<1><<<ggrid, 256>>>(k, Wk, bk, Kh);   // [B,H,S,D]
    gemm512_kernel<2><<<ggrid, 256>>>(v, Wv, bv, Vh);   // [B,H,D,S]

    cudaFuncSetAttribute(attn_mma, cudaFuncAttributeMaxDynamicSharedMemorySize, SM_TOT);
    attn_mma<<<dim3(SEQ / 128, BATCH * HEADS), 256, SM_TOT>>>(Qh, Kh, Vh, mask, ctx);

    gemm512_kernel<0><<<ggrid, 256>>>(ctx, Wo, bo, out);
}

// round 7
// speedup vs baseline: 3.0015x; 1.2913x over previous
#include <cuda_runtime.h>
#include <cuda.h>
#include <cuda_fp16.h>
#include <math.h>

#define EMBED 512
#define HEADS 8
#define DEPTH 64
#define BATCH 2
#define SEQ   4096
#define MROWS (BATCH * SEQ)          // 8192

typedef unsigned long long u64;
typedef unsigned int u32;

// ---------------------------------------------------------------------------
// Device scratch
// ---------------------------------------------------------------------------
__device__ float g_Qh[BATCH * HEADS * SEQ * DEPTH];   // [B,H,S,D]
__device__ float g_Kh[BATCH * HEADS * SEQ * DEPTH];   // [B,H,S,D]
__device__ float g_Vh[BATCH * HEADS * DEPTH * SEQ];   // [B,H,D,S] (d-major)
__device__ float g_ctx[BATCH * SEQ * EMBED];          // [B,S,E]
__device__ uint4 g_Wc[4 * 64 * 32 * 32];              // packed B-cells, 4 weights

// ---------------------------------------------------------------------------
// fp16 mma.sync helpers (baseline PTX, compute_103-safe)
// ---------------------------------------------------------------------------
__device__ __forceinline__ void mma16(float c[4], const u32 a[4], u32 b0, u32 b1) {
    asm("mma.sync.aligned.m16n8k16.row.col.f32.f16.f16.f32 "
        "{%0,%1,%2,%3}, {%4,%5,%6,%7}, {%8,%9}, {%0,%1,%2,%3};"
        : "+f"(c[0]), "+f"(c[1]), "+f"(c[2]), "+f"(c[3])
        : "r"(a[0]), "r"(a[1]), "r"(a[2]), "r"(a[3]), "r"(b0), "r"(b1));
}
__device__ __forceinline__ u32 f2h2(float lo, float hi) {
    __half2 h = __float22half2_rn(make_float2(lo, hi));   // .x -> low 16 bits
    return *(u32*)&h;
}
__device__ __forceinline__ float2 h22f(u32 v) {
    __half2 h = *(__half2*)&v;
    return __half22float2(h);
}
__device__ __forceinline__ void split2(float2 x, u32& hi, u32& lo) {
    hi = f2h2(x.x, x.y);
    float2 back = h22f(hi);
    lo = f2h2(x.x - back.x, x.y - back.y);
}

// ---------------------------------------------------------------------------
// Weight prep: W[512][512] (k-major) -> B-fragment cells {b0hi,b1hi,b0lo,b1lo}
// cell array layout: [ntg 64][ksg 32][ln 32] uint4
// grid (4 nblk, 16 kblk), 256 threads
// ---------------------------------------------------------------------------
__global__ __launch_bounds__(256) void wprep_kernel(
    const float* __restrict__ W, uint4* __restrict__ out)
{
    __shared__ float sw[32][132];
    const int tid = threadIdx.x;
    const int n0 = blockIdx.x * 128;
    const int k0 = blockIdx.y * 32;

#pragma unroll
    for (int it = 0; it < 4; ++it) {
        int idx = tid + it * 256;          // 1024 float4
        int row = idx >> 5;                // k 0..31
        int n4  = (idx & 31) * 4;
        *(float4*)&sw[row][n4] = *(const float4*)(W + (size_t)(k0 + row) * 512 + n0 + n4);
    }
    __syncthreads();

#pragma unroll
    for (int it = 0; it < 4; ++it) {
        int idx = tid + it * 256;          // 1024 cells
        int ln = idx & 31, ks = (idx >> 5) & 1, nt = idx >> 6;
        int gg = ln >> 2, tt = ln & 3;
        int nl = nt * 8 + gg;
        int kl = ks * 16 + 2 * tt;
        float2 x0 = make_float2(sw[kl][nl],     sw[kl + 1][nl]);
        float2 x1 = make_float2(sw[kl + 8][nl], sw[kl + 9][nl]);
        uint4 cv;
        split2(x0, cv.x, cv.z);
        split2(x1, cv.y, cv.w);
        out[((size_t)(blockIdx.x * 16 + nt) * 32 + blockIdx.y * 2 + ks) * 32 + ln] = cv;
    }
}

// ---------------------------------------------------------------------------
// Tensor-core GEMM: C = A[8192,512] @ W[512,512] + bias (hi/lo fp16 MMA)
// MODE 0: C row-major; MODE 1: C -> [B,H,S,D]; MODE 2: C^T -> [B,H,D,S]
// grid (4 n, 64 m), 256 threads, warp w owns rows m0+16w..+15, all 128 n-cols.
// ---------------------------------------------------------------------------
#define ASTR 36

template <int MODE>
__global__ __launch_bounds__(256, 2) void gemm_mma(
    const float* __restrict__ A, const uint4* __restrict__ Wc,
    const float* __restrict__ bias, float* __restrict__ C)
{
    __shared__ float As[128 * ASTR];        // 18432 B
    __shared__ uint4 BC[16 * 2 * 32];       // 16384 B

    const int tid  = threadIdx.x;
    const int w    = tid >> 5;
    const int lane = tid & 31;
    const int g    = lane >> 2;
    const int t4   = lane & 3;
    const int n0   = blockIdx.x * 128;
    const int m0   = blockIdx.y * 128;

    float acc[16][4];
#pragma unroll
    for (int nt = 0; nt < 16; ++nt)
#pragma unroll
        for (int e = 0; e < 4; ++e) acc[nt][e] = 0.0f;

    const float* arow = As + (16 * w + g) * ASTR;

    for (int kc = 0; kc < 16; ++kc) {
        __syncthreads();
        // A tile: 128 rows x 32 k (raw fp32, coalesced)
#pragma unroll
        for (int it = 0; it < 4; ++it) {
            int idx = tid + it * 256;       // 1024 float4
            int row = idx >> 3;
            int k4  = (idx & 7) * 4;
            *(float4*)&As[row * ASTR + k4] =
                *(const float4*)(A + (size_t)(m0 + row) * 512 + kc * 32 + k4);
        }
        // B cells: straight uint4 copy from packed weights
#pragma unroll
        for (int it = 0; it < 4; ++it) {
            int idx = tid + it * 256;       // 1024 cells
            int ln = idx & 31, ks = (idx >> 5) & 1, nt = idx >> 6;
            BC[idx] = Wc[((size_t)(blockIdx.x * 16 + nt) * 32 + kc * 2 + ks) * 32 + ln];
        }
        __syncthreads();

#pragma unroll
        for (int ks = 0; ks < 2; ++ks) {
            u32 ahi[4], alo[4];
            const float* base = arow + ks * 16 + 2 * t4;
            split2(*(const float2*)(base),                  ahi[0], alo[0]);
            split2(*(const float2*)(base + 8 * ASTR),       ahi[1], alo[1]);
            split2(*(const float2*)(base + 8),              ahi[2], alo[2]);
            split2(*(const float2*)(base + 8 * ASTR + 8),   ahi[3], alo[3]);
#pragma unroll
            for (int nt = 0; nt < 16; ++nt) {
                uint4 cv = BC[(nt * 2 + ks) * 32 + lane];
                mma16(acc[nt], ahi, cv.x, cv.y);
                mma16(acc[nt], alo, cv.x, cv.y);
                mma16(acc[nt], ahi, cv.z, cv.w);
            }
        }
    }

    // ---- epilogue ----
    const int m  = m0 + 16 * w + g;        // row for c0/c1 (c2/c3 at m+8)
    if (MODE == 0) {
#pragma unroll
        for (int nt = 0; nt < 16; ++nt) {
            int n = n0 + nt * 8 + 2 * t4;
            float2 bi = *(const float2*)(bias + n);
            *(float2*)(C + (size_t)m * 512 + n) =
                make_float2(acc[nt][0] + bi.x, acc[nt][1] + bi.y);
            *(float2*)(C + (size_t)(m + 8) * 512 + n) =
                make_float2(acc[nt][2] + bi.x, acc[nt][3] + bi.y);
        }
    } else if (MODE == 1) {
        int b = m >> 12, s = m & 4095;
#pragma unroll
        for (int nt = 0; nt < 16; ++nt) {
            int n = n0 + nt * 8 + 2 * t4;
            int h = n >> 6, d = n & 63;
            float2 bi = *(const float2*)(bias + n);
            float* dst = C + ((size_t)(b * HEADS + h) * SEQ + s) * DEPTH + d;
            *(float2*)dst = make_float2(acc[nt][0] + bi.x, acc[nt][1] + bi.y);
            *(float2*)(dst + 8 * DEPTH) =
                make_float2(acc[nt][2] + bi.x, acc[nt][3] + bi.y);
        }
    } else {
        int b = m >> 12, s = m & 4095;
#pragma unroll
        for (int nt = 0; nt < 16; ++nt) {
            int n = n0 + nt * 8 + 2 * t4;
            int h = n >> 6, d = n & 63;
            float2 bi = *(const float2*)(bias + n);
            float* base = C + ((size_t)(b * HEADS + h) * DEPTH + d) * SEQ + s;
            base[0]           = acc[nt][0] + bi.x;
            base[SEQ]         = acc[nt][1] + bi.y;
            base[8]           = acc[nt][2] + bi.x;
            base[SEQ + 8]     = acc[nt][3] + bi.y;
        }
    }
}

// ---------------------------------------------------------------------------
// Flash attention on mma.sync fp16 (hi/lo error-compensated) -- as R5.
// ---------------------------------------------------------------------------
#define SM_MASK 0
#define SM_KC   1024
#define SM_VC   (SM_KC + 32768)
#define SM_TOT  (SM_VC + 32768)

__global__ __launch_bounds__(256, 2) void attn_mma(
    const float* __restrict__ Qg, const float* __restrict__ Kg,
    const float* __restrict__ Vg, const float* __restrict__ mask,
    float* __restrict__ ctx)
{
    extern __shared__ char smem[];
    float* smask = (float*)(smem + SM_MASK);
    uint4* KC    = (uint4*)(smem + SM_KC);
    uint4* VC    = (uint4*)(smem + SM_VC);

    const int tid  = threadIdx.x;
    const int w    = tid >> 5;
    const int lane = tid & 31;
    const int g    = lane >> 2;
    const int t4   = lane & 3;
    const int bh   = blockIdx.y, b = bh >> 3, h = bh & 7;
    const int qi0  = blockIdx.x * 128;

    const float* Qb = Qg + (size_t)bh * SEQ * DEPTH;
    const float* Kb = Kg + (size_t)bh * SEQ * DEPTH;
    const float* Vb = Vg + (size_t)bh * DEPTH * SEQ;
    const float* mb = mask + (size_t)b * SEQ;

    u32 qhi[4][4], qlo[4][4];
    {
        const float* q0 = Qb + (size_t)(qi0 + 16 * w + g) * DEPTH;
#pragma unroll
        for (int ks = 0; ks < 4; ++ks) {
            int d0 = ks * 16 + 2 * t4;
            float2 x0 = *(const float2*)(q0 + d0);
            float2 x1 = *(const float2*)(q0 + 8 * DEPTH + d0);
            float2 x2 = *(const float2*)(q0 + d0 + 8);
            float2 x3 = *(const float2*)(q0 + 8 * DEPTH + d0 + 8);
            split2(x0, qhi[ks][0], qlo[ks][0]);
            split2(x1, qhi[ks][1], qlo[ks][1]);
            split2(x2, qhi[ks][2], qlo[ks][2]);
            split2(x3, qhi[ks][3], qlo[ks][3]);
        }
    }

    float oacc[8][4];
#pragma unroll
    for (int nt = 0; nt < 8; ++nt)
#pragma unroll
        for (int e = 0; e < 4; ++e) oacc[nt][e] = 0.0f;
    float lsum0 = 0.0f, lsum1 = 0.0f;

    for (int jt = 0; jt < SEQ / 128; ++jt) {
        const int j0 = jt * 128;
        __syncthreads();

#pragma unroll
        for (int it = 0; it < 8; ++it) {
            int cell = tid + it * 256;
            int ln = cell & 31, ks = (cell >> 5) & 3, nt = cell >> 7;
            int gg = ln >> 2, tt = ln & 3;
            const float* src = Kb + (size_t)(j0 + nt * 8 + gg) * DEPTH + ks * 16 + 2 * tt;
            float2 x0 = *(const float2*)src;
            float2 x1 = *(const float2*)(src + 8);
            uint4 cv;
            split2(x0, cv.x, cv.z);
            split2(x1, cv.y, cv.w);
            KC[(nt * 4 + ks) * 32 + ln] = cv;
        }
#pragma unroll
        for (int it = 0; it < 8; ++it) {
            int cell = tid + it * 256;
            int ln = cell & 31, ks = (cell >> 5) & 7, nt = cell >> 8;
            int gg = ln >> 2, tt = ln & 3;
            const float* src = Vb + (size_t)(nt * 8 + gg) * SEQ + j0 + ks * 16 + 2 * tt;
            float2 x0 = *(const float2*)src;
            float2 x1 = *(const float2*)(src + 8);
            uint4 cv;
            split2(x0, cv.x, cv.z);
            split2(x1, cv.y, cv.w);
            VC[(nt * 8 + ks) * 32 + ln] = cv;
        }
        if (tid < 128) smask[tid] = mb[j0 + tid] * (-1e9f);
        __syncthreads();

        u32 pa[8][4];
#pragma unroll
        for (int kp = 0; kp < 8; ++kp) {
            float sacc[2][4] = {{0.f,0.f,0.f,0.f},{0.f,0.f,0.f,0.f}};
#pragma unroll
            for (int i = 0; i < 2; ++i) {
                int nt = kp * 2 + i;
#pragma unroll
                for (int ks = 0; ks < 4; ++ks) {
                    uint4 cv = KC[(nt * 4 + ks) * 32 + lane];
                    mma16(sacc[i], qhi[ks], cv.x, cv.y);
                    mma16(sacc[i], qlo[ks], cv.x, cv.y);
                    mma16(sacc[i], qhi[ks], cv.z, cv.w);
                }
            }
            float p[2][4];
#pragma unroll
            for (int i = 0; i < 2; ++i) {
                int c0 = (kp * 2 + i) * 8 + 2 * t4;
                float mk0 = smask[c0], mk1 = smask[c0 + 1];
                p[i][0] = __expf(fmaf(sacc[i][0], 0.125f, mk0));
                p[i][1] = __expf(fmaf(sacc[i][1], 0.125f, mk1));
                p[i][2] = __expf(fmaf(sacc[i][2], 0.125f, mk0));
                p[i][3] = __expf(fmaf(sacc[i][3], 0.125f, mk1));
                lsum0 += p[i][0] + p[i][1];
                lsum1 += p[i][2] + p[i][3];
            }
            pa[kp][0] = f2h2(p[0][0], p[0][1]);
            pa[kp][1] = f2h2(p[0][2], p[0][3]);
            pa[kp][2] = f2h2(p[1][0], p[1][1]);
            pa[kp][3] = f2h2(p[1][2], p[1][3]);
        }

#pragma unroll
        for (int ks = 0; ks < 8; ++ks) {
#pragma unroll
            for (int nt = 0; nt < 8; ++nt) {
                uint4 cv = VC[(nt * 8 + ks) * 32 + lane];
                mma16(oacc[nt], pa[ks], cv.x, cv.y);
                mma16(oacc[nt], pa[ks], cv.z, cv.w);
            }
        }
    }

    lsum0 += __shfl_xor_sync(0xffffffffu, lsum0, 1);
    lsum0 += __shfl_xor_sync(0xffffffffu, lsum0, 2);
    lsum1 += __shfl_xor_sync(0xffffffffu, lsum1, 1);
    lsum1 += __shfl_xor_sync(0xffffffffu, lsum1, 2);
    float inv0 = 1.0f / lsum0, inv1 = 1.0f / lsum1;

    int row0 = qi0 + 16 * w + g;
    float* dst0 = ctx + ((size_t)(b * SEQ + row0)) * EMBED + h * DEPTH;
    float* dst1 = dst0 + (size_t)8 * EMBED;
#pragma unroll
    for (int nt = 0; nt < 8; ++nt) {
        int c = nt * 8 + 2 * t4;
        *(float2*)(dst0 + c) = make_float2(oacc[nt][0] * inv0, oacc[nt][1] * inv0);
        *(float2*)(dst1 + c) = make_float2(oacc[nt][2] * inv1, oacc[nt][3] * inv1);
    }
}

// ---------------------------------------------------------------------------
// Launcher
// ---------------------------------------------------------------------------
extern "C" void kernel_launch(void* const* d_in, const int* in_sizes, int n_in,
                              void* d_out, int out_size)
{
    const float* q    = (const float*)d_in[0];
    const float* k    = (const float*)d_in[1];
    const float* v    = (const float*)d_in[2];
    const float* mask = (const float*)d_in[3];
    const float* Wq   = (const float*)d_in[4];
    const float* bq   = (const float*)d_in[5];
    const float* Wk   = (const float*)d_in[6];
    const float* bk   = (const float*)d_in[7];
    const float* Wv   = (const float*)d_in[8];
    const float* bv   = (const float*)d_in[9];
    const float* Wo   = (const float*)d_in[10];
    const float* bo   = (const float*)d_in[11];
    float* out = (float*)d_out;

    float *Qh, *Kh, *Vh, *ctx;
    uint4* Wc;
    cudaGetSymbolAddress((void**)&Qh,  g_Qh);
    cudaGetSymbolAddress((void**)&Kh,  g_Kh);
    cudaGetSymbolAddress((void**)&Vh,  g_Vh);
    cudaGetSymbolAddress((void**)&ctx, g_ctx);
    cudaGetSymbolAddress((void**)&Wc,  g_Wc);

    const int WCN = 64 * 32 * 32;
    dim3 pgrid(4, 16);
    wprep_kernel<<<pgrid, 256>>>(Wq, Wc + 0 * WCN);
    wprep_kernel<<<pgrid, 256>>>(Wk, Wc + 1 * WCN);
    wprep_kernel<<<pgrid, 256>>>(Wv, Wc + 2 * WCN);
    wprep_kernel<<<pgrid, 256>>>(Wo, Wc + 3 * WCN);

    dim3 ggrid(4, 64);
    gemm_mma<1><<<ggrid, 256>>>(q, Wc + 0 * WCN, bq, Qh);   // [B,H,S,D]
    gemm_mma<1><<<ggrid, 256>>>(k, Wc + 1 * WCN, bk, Kh);   // [B,H,S,D]
    gemm_mma<2><<<ggrid, 256>>>(v, Wc + 2 * WCN, bv, Vh);   // [B,H,D,S]

    cudaFuncSetAttribute(attn_mma, cudaFuncAttributeMaxDynamicSharedMemorySize, SM_TOT);
    attn_mma<<<dim3(SEQ / 128, BATCH * HEADS), 256, SM_TOT>>>(Qh, Kh, Vh, mask, ctx);

    gemm_mma<0><<<ggrid, 256>>>(ctx, Wc + 3 * WCN, bo, out);
}

// round 8
// speedup vs baseline: 3.4210x; 1.1398x over previous
#include <cuda_runtime.h>
#include <cuda.h>
#include <cuda_fp16.h>
#include <math.h>

#define EMBED 512
#define HEADS 8
#define DEPTH 64
#define BATCH 2
#define SEQ   4096
#define MROWS (BATCH * SEQ)          // 8192

typedef unsigned long long u64;
typedef unsigned int u32;

// ---------------------------------------------------------------------------
// Device scratch
// ---------------------------------------------------------------------------
__device__ float g_Qh[BATCH * HEADS * SEQ * DEPTH];   // [B,H,S,D]
__device__ float g_Kh[BATCH * HEADS * SEQ * DEPTH];   // [B,H,S,D]
__device__ float g_Vh[BATCH * HEADS * DEPTH * SEQ];   // [B,H,D,S] (d-major)
__device__ float g_ctx[BATCH * SEQ * EMBED];          // [B,S,E]
__device__ uint4 g_Wc[4 * 64 * 32 * 32];              // packed W B-cells
__device__ uint4 g_Kc[BATCH * HEADS * 32 * 2048];     // packed K cells per (bh, jtile)
__device__ uint4 g_Vc[BATCH * HEADS * 32 * 2048];     // packed V cells

// ---------------------------------------------------------------------------
// fp16 mma.sync + cp.async helpers (baseline PTX, compute_103-safe)
// ---------------------------------------------------------------------------
__device__ __forceinline__ void mma16(float c[4], const u32 a[4], u32 b0, u32 b1) {
    asm("mma.sync.aligned.m16n8k16.row.col.f32.f16.f16.f32 "
        "{%0,%1,%2,%3}, {%4,%5,%6,%7}, {%8,%9}, {%0,%1,%2,%3};"
        : "+f"(c[0]), "+f"(c[1]), "+f"(c[2]), "+f"(c[3])
        : "r"(a[0]), "r"(a[1]), "r"(a[2]), "r"(a[3]), "r"(b0), "r"(b1));
}
__device__ __forceinline__ u32 f2h2(float lo, float hi) {
    __half2 h = __float22half2_rn(make_float2(lo, hi));
    return *(u32*)&h;
}
__device__ __forceinline__ float2 h22f(u32 v) {
    __half2 h = *(__half2*)&v;
    return __half22float2(h);
}
__device__ __forceinline__ void split2(float2 x, u32& hi, u32& lo) {
    hi = f2h2(x.x, x.y);
    float2 back = h22f(hi);
    lo = f2h2(x.x - back.x, x.y - back.y);
}
__device__ __forceinline__ u32 smem_u32(const void* p) {
    u32 a;
    asm("{ .reg .u64 t; cvta.to.shared.u64 t, %1; cvt.u32.u64 %0, t; }"
        : "=r"(a) : "l"(p));
    return a;
}
__device__ __forceinline__ void cpa16(u32 saddr, const void* gptr) {
    asm volatile("cp.async.cg.shared.global [%0], [%1], 16;"
                 :: "r"(saddr), "l"(gptr));
}
#define CP_COMMIT() asm volatile("cp.async.commit_group;" ::: "memory")
#define CP_WAIT(n)  asm volatile("cp.async.wait_group %0;" :: "n"(n) : "memory")

// ---------------------------------------------------------------------------
// Weight prep: W[512][512] -> B-fragment cells [ntg 64][ksg 32][ln 32]
// ---------------------------------------------------------------------------
__global__ __launch_bounds__(256) void wprep_kernel(
    const float* __restrict__ W, uint4* __restrict__ out)
{
    __shared__ float sw[32][132];
    const int tid = threadIdx.x;
    const int n0 = blockIdx.x * 128;
    const int k0 = blockIdx.y * 32;

#pragma unroll
    for (int it = 0; it < 4; ++it) {
        int idx = tid + it * 256;
        int row = idx >> 5;
        int n4  = (idx & 31) * 4;
        *(float4*)&sw[row][n4] = *(const float4*)(W + (size_t)(k0 + row) * 512 + n0 + n4);
    }
    __syncthreads();

#pragma unroll
    for (int it = 0; it < 4; ++it) {
        int idx = tid + it * 256;
        int ln = idx & 31, ks = (idx >> 5) & 1, nt = idx >> 6;
        int gg = ln >> 2, tt = ln & 3;
        int nl = nt * 8 + gg;
        int kl = ks * 16 + 2 * tt;
        float2 x0 = make_float2(sw[kl][nl],     sw[kl + 1][nl]);
        float2 x1 = make_float2(sw[kl + 8][nl], sw[kl + 9][nl]);
        uint4 cv;
        split2(x0, cv.x, cv.z);
        split2(x1, cv.y, cv.w);
        out[((size_t)(blockIdx.x * 16 + nt) * 32 + blockIdx.y * 2 + ks) * 32 + ln] = cv;
    }
}

// ---------------------------------------------------------------------------
// K pack: [B,H,S,D] fp32 -> cells. grid(32 jt, 16 bh), 256 thr.
// cell: ln=c&31, ks=(c>>5)&3, nt=c>>7; src row j0+nt*8+gg, d = ks*16+2tt (+8)
// ---------------------------------------------------------------------------
__global__ __launch_bounds__(256) void kpack_kernel(
    const float* __restrict__ Kh, uint4* __restrict__ out)
{
    const int tid = threadIdx.x;
    const int jt = blockIdx.x, bh = blockIdx.y, j0 = jt * 128;
    const float* Kb = Kh + (size_t)bh * SEQ * DEPTH;
    uint4* o = out + ((size_t)bh * 32 + jt) * 2048;
#pragma unroll
    for (int it = 0; it < 8; ++it) {
        int c = tid + it * 256;
        int ln = c & 31, ks = (c >> 5) & 3, nt = c >> 7;
        int gg = ln >> 2, tt = ln & 3;
        const float* src = Kb + (size_t)(j0 + nt * 8 + gg) * DEPTH + ks * 16 + 2 * tt;
        float2 x0 = *(const float2*)src;
        float2 x1 = *(const float2*)(src + 8);
        uint4 cv;
        split2(x0, cv.x, cv.z);
        split2(x1, cv.y, cv.w);
        o[c] = cv;
    }
}

// ---------------------------------------------------------------------------
// V pack: [B,H,D,S] fp32 -> cells. cell: ln=c&31, ks=(c>>5)&7, nt=c>>8
// ---------------------------------------------------------------------------
__global__ __launch_bounds__(256) void vpack_kernel(
    const float* __restrict__ Vh, uint4* __restrict__ out)
{
    const int tid = threadIdx.x;
    const int jt = blockIdx.x, bh = blockIdx.y, j0 = jt * 128;
    const float* Vb = Vh + (size_t)bh * DEPTH * SEQ;
    uint4* o = out + ((size_t)bh * 32 + jt) * 2048;
#pragma unroll
    for (int it = 0; it < 8; ++it) {
        int c = tid + it * 256;
        int ln = c & 31, ks = (c >> 5) & 7, nt = c >> 8;
        int gg = ln >> 2, tt = ln & 3;
        const float* src = Vb + (size_t)(nt * 8 + gg) * SEQ + j0 + ks * 16 + 2 * tt;
        float2 x0 = *(const float2*)src;
        float2 x1 = *(const float2*)(src + 8);
        uint4 cv;
        split2(x0, cv.x, cv.z);
        split2(x1, cv.y, cv.w);
        o[c] = cv;
    }
}

// ---------------------------------------------------------------------------
// Tensor-core GEMM (hi/lo fp16 MMA), unchanged from R6.
// MODE 0: C row-major; MODE 1: C -> [B,H,S,D]; MODE 2: C^T -> [B,H,D,S]
// ---------------------------------------------------------------------------
#define ASTR 36

template <int MODE>
__global__ __launch_bounds__(256, 2) void gemm_mma(
    const float* __restrict__ A, const uint4* __restrict__ Wc,
    const float* __restrict__ bias, float* __restrict__ C)
{
    __shared__ float As[128 * ASTR];
    __shared__ uint4 BC[16 * 2 * 32];

    const int tid  = threadIdx.x;
    const int w    = tid >> 5;
    const int lane = tid & 31;
    const int g    = lane >> 2;
    const int t4   = lane & 3;
    const int n0   = blockIdx.x * 128;
    const int m0   = blockIdx.y * 128;

    float acc[16][4];
#pragma unroll
    for (int nt = 0; nt < 16; ++nt)
#pragma unroll
        for (int e = 0; e < 4; ++e) acc[nt][e] = 0.0f;

    const float* arow = As + (16 * w + g) * ASTR;

    for (int kc = 0; kc < 16; ++kc) {
        __syncthreads();
#pragma unroll
        for (int it = 0; it < 4; ++it) {
            int idx = tid + it * 256;
            int row = idx >> 3;
            int k4  = (idx & 7) * 4;
            *(float4*)&As[row * ASTR + k4] =
                *(const float4*)(A + (size_t)(m0 + row) * 512 + kc * 32 + k4);
        }
#pragma unroll
        for (int it = 0; it < 4; ++it) {
            int idx = tid + it * 256;
            int ln = idx & 31, ks = (idx >> 5) & 1, nt = idx >> 6;
            BC[idx] = Wc[((size_t)(blockIdx.x * 16 + nt) * 32 + kc * 2 + ks) * 32 + ln];
        }
        __syncthreads();

#pragma unroll
        for (int ks = 0; ks < 2; ++ks) {
            u32 ahi[4], alo[4];
            const float* base = arow + ks * 16 + 2 * t4;
            split2(*(const float2*)(base),                ahi[0], alo[0]);
            split2(*(const float2*)(base + 8 * ASTR),     ahi[1], alo[1]);
            split2(*(const float2*)(base + 8),            ahi[2], alo[2]);
            split2(*(const float2*)(base + 8 * ASTR + 8), ahi[3], alo[3]);
#pragma unroll
            for (int nt = 0; nt < 16; ++nt) {
                uint4 cv = BC[(nt * 2 + ks) * 32 + lane];
                mma16(acc[nt], ahi, cv.x, cv.y);
                mma16(acc[nt], alo, cv.x, cv.y);
                mma16(acc[nt], ahi, cv.z, cv.w);
            }
        }
    }

    const int m = m0 + 16 * w + g;
    if (MODE == 0) {
#pragma unroll
        for (int nt = 0; nt < 16; ++nt) {
            int n = n0 + nt * 8 + 2 * t4;
            float2 bi = *(const float2*)(bias + n);
            *(float2*)(C + (size_t)m * 512 + n) =
                make_float2(acc[nt][0] + bi.x, acc[nt][1] + bi.y);
            *(float2*)(C + (size_t)(m + 8) * 512 + n) =
                make_float2(acc[nt][2] + bi.x, acc[nt][3] + bi.y);
        }
    } else if (MODE == 1) {
        int b = m >> 12, s = m & 4095;
#pragma unroll
        for (int nt = 0; nt < 16; ++nt) {
            int n = n0 + nt * 8 + 2 * t4;
            int h = n >> 6, d = n & 63;
            float2 bi = *(const float2*)(bias + n);
            float* dst = C + ((size_t)(b * HEADS + h) * SEQ + s) * DEPTH + d;
            *(float2*)dst = make_float2(acc[nt][0] + bi.x, acc[nt][1] + bi.y);
            *(float2*)(dst + 8 * DEPTH) =
                make_float2(acc[nt][2] + bi.x, acc[nt][3] + bi.y);
        }
    } else {
        int b = m >> 12, s = m & 4095;
#pragma unroll
        for (int nt = 0; nt < 16; ++nt) {
            int n = n0 + nt * 8 + 2 * t4;
            int h = n >> 6, d = n & 63;
            float2 bi = *(const float2*)(bias + n);
            float* base = C + ((size_t)(b * HEADS + h) * DEPTH + d) * SEQ + s;
            base[0]       = acc[nt][0] + bi.x;
            base[SEQ]     = acc[nt][1] + bi.y;
            base[8]       = acc[nt][2] + bi.x;
            base[SEQ + 8] = acc[nt][3] + bi.y;
        }
    }
}

// ---------------------------------------------------------------------------
// Flash attention: prepacked K/V cells, cp.async fills,
// K double-buffered (prefetch jt+1 during jt), V fill overlapped with QK.
// ---------------------------------------------------------------------------
#define SM_MASK 0
#define SM_KC0  1024
#define SM_KC1  (SM_KC0 + 32768)
#define SM_VC   (SM_KC1 + 32768)
#define SM_TOT  (SM_VC + 32768)     // 99328 B

__global__ __launch_bounds__(256, 2) void attn_mma(
    const float* __restrict__ Qg, const uint4* __restrict__ Kc,
    const uint4* __restrict__ Vc, const float* __restrict__ mask,
    float* __restrict__ ctx)
{
    extern __shared__ char smem[];
    const u32 sb = smem_u32(smem);
    float* smask = (float*)(smem + SM_MASK);

    const int tid  = threadIdx.x;
    const int w    = tid >> 5;
    const int lane = tid & 31;
    const int g    = lane >> 2;
    const int t4   = lane & 3;
    const int bh   = blockIdx.y, b = bh >> 3, h = bh & 7;
    const int qi0  = blockIdx.x * 128;

    const float* Qb  = Qg + (size_t)bh * SEQ * DEPTH;
    const uint4* Kcb = Kc + (size_t)bh * 32 * 2048;
    const uint4* Vcb = Vc + (size_t)bh * 32 * 2048;
    const float* mb  = mask + (size_t)b * SEQ;

    // Q fragments in registers (hi/lo)
    u32 qhi[4][4], qlo[4][4];
    {
        const float* q0 = Qb + (size_t)(qi0 + 16 * w + g) * DEPTH;
#pragma unroll
        for (int ks = 0; ks < 4; ++ks) {
            int d0 = ks * 16 + 2 * t4;
            split2(*(const float2*)(q0 + d0),                 qhi[ks][0], qlo[ks][0]);
            split2(*(const float2*)(q0 + 8 * DEPTH + d0),     qhi[ks][1], qlo[ks][1]);
            split2(*(const float2*)(q0 + d0 + 8),             qhi[ks][2], qlo[ks][2]);
            split2(*(const float2*)(q0 + 8 * DEPTH + d0 + 8), qhi[ks][3], qlo[ks][3]);
        }
    }

    float oacc[8][4];
#pragma unroll
    for (int nt = 0; nt < 8; ++nt)
#pragma unroll
        for (int e = 0; e < 4; ++e) oacc[nt][e] = 0.0f;
    float lsum0 = 0.0f, lsum1 = 0.0f;

    // prologue: prefetch K tile 0 into KC0
#pragma unroll
    for (int it = 0; it < 8; ++it) {
        int c = tid + it * 256;
        cpa16(sb + SM_KC0 + c * 16, Kcb + c);
    }
    CP_COMMIT();

    for (int jt = 0; jt < 32; ++jt) {
        const int cur = jt & 1;
        const u32 kbuf  = sb + (cur ? SM_KC1 : SM_KC0);
        const u32 kbufn = sb + (cur ? SM_KC0 : SM_KC1);
        const uint4* KCb = (const uint4*)(smem + (cur ? SM_KC1 : SM_KC0));
        const uint4* VCb = (const uint4*)(smem + SM_VC);
        (void)kbuf;

        __syncthreads();   // prior tile fully consumed

        // V fill (overlaps with QK phase below)
        const uint4* vsrc = Vcb + (size_t)jt * 2048;
#pragma unroll
        for (int it = 0; it < 8; ++it) {
            int c = tid + it * 256;
            cpa16(sb + SM_VC + c * 16, vsrc + c);
        }
        CP_COMMIT();

        // K prefetch for jt+1 into the other buffer
        int jn = (jt + 1 < 32) ? jt + 1 : 31;
        const uint4* ksrc = Kcb + (size_t)jn * 2048;
#pragma unroll
        for (int it = 0; it < 8; ++it) {
            int c = tid + it * 256;
            cpa16(kbufn + c * 16, ksrc + c);
        }
        CP_COMMIT();

        if (tid < 128) smask[tid] = mb[jt * 128 + tid] * (-1e9f);

        CP_WAIT(2);        // K(jt) complete (V(jt), K(jt+1) may be pending)
        __syncthreads();

        // ---- QK^T + exp + pack ----
        u32 pa[8][4];
#pragma unroll
        for (int kp = 0; kp < 8; ++kp) {
            float sacc[2][4] = {{0.f,0.f,0.f,0.f},{0.f,0.f,0.f,0.f}};
#pragma unroll
            for (int i = 0; i < 2; ++i) {
                int nt = kp * 2 + i;
#pragma unroll
                for (int ks = 0; ks < 4; ++ks) {
                    uint4 cv = KCb[(nt * 4 + ks) * 32 + lane];
                    mma16(sacc[i], qhi[ks], cv.x, cv.y);
                    mma16(sacc[i], qlo[ks], cv.x, cv.y);
                    mma16(sacc[i], qhi[ks], cv.z, cv.w);
                }
            }
            float p[2][4];
#pragma unroll
            for (int i = 0; i < 2; ++i) {
                int c0 = (kp * 2 + i) * 8 + 2 * t4;
                float mk0 = smask[c0], mk1 = smask[c0 + 1];
                p[i][0] = __expf(fmaf(sacc[i][0], 0.125f, mk0));
                p[i][1] = __expf(fmaf(sacc[i][1], 0.125f, mk1));
                p[i][2] = __expf(fmaf(sacc[i][2], 0.125f, mk0));
                p[i][3] = __expf(fmaf(sacc[i][3], 0.125f, mk1));
                lsum0 += p[i][0] + p[i][1];
                lsum1 += p[i][2] + p[i][3];
            }
            pa[kp][0] = f2h2(p[0][0], p[0][1]);
            pa[kp][1] = f2h2(p[0][2], p[0][3]);
            pa[kp][2] = f2h2(p[1][0], p[1][1]);
            pa[kp][3] = f2h2(p[1][2], p[1][3]);
        }

        CP_WAIT(1);        // V(jt) complete (K(jt+1) may be pending)
        __syncthreads();

        // ---- O += P V ----
#pragma unroll
        for (int ks = 0; ks < 8; ++ks) {
#pragma unroll
            for (int nt = 0; nt < 8; ++nt) {
                uint4 cv = VCb[(nt * 8 + ks) * 32 + lane];
                mma16(oacc[nt], pa[ks], cv.x, cv.y);
                mma16(oacc[nt], pa[ks], cv.z, cv.w);
            }
        }
    }

    lsum0 += __shfl_xor_sync(0xffffffffu, lsum0, 1);
    lsum0 += __shfl_xor_sync(0xffffffffu, lsum0, 2);
    lsum1 += __shfl_xor_sync(0xffffffffu, lsum1, 1);
    lsum1 += __shfl_xor_sync(0xffffffffu, lsum1, 2);
    float inv0 = 1.0f / lsum0, inv1 = 1.0f / lsum1;

    int row0 = qi0 + 16 * w + g;
    float* dst0 = ctx + ((size_t)(b * SEQ + row0)) * EMBED + h * DEPTH;
    float* dst1 = dst0 + (size_t)8 * EMBED;
#pragma unroll
    for (int nt = 0; nt < 8; ++nt) {
        int c = nt * 8 + 2 * t4;
        *(float2*)(dst0 + c) = make_float2(oacc[nt][0] * inv0, oacc[nt][1] * inv0);
        *(float2*)(dst1 + c) = make_float2(oacc[nt][2] * inv1, oacc[nt][3] * inv1);
    }
}

// ---------------------------------------------------------------------------
// Launcher
// ---------------------------------------------------------------------------
extern "C" void kernel_launch(void* const* d_in, const int* in_sizes, int n_in,
                              void* d_out, int out_size)
{
    const float* q    = (const float*)d_in[0];
    const float* k    = (const float*)d_in[1];
    const float* v    = (const float*)d_in[2];
    const float* mask = (const float*)d_in[3];
    const float* Wq   = (const float*)d_in[4];
    const float* bq   = (const float*)d_in[5];
    const float* Wk   = (const float*)d_in[6];
    const float* bk   = (const float*)d_in[7];
    const float* Wv   = (const float*)d_in[8];
    const float* bv   = (const float*)d_in[9];
    const float* Wo   = (const float*)d_in[10];
    const float* bo   = (const float*)d_in[11];
    float* out = (float*)d_out;

    float *Qh, *Kh, *Vh, *ctx;
    uint4 *Wc, *Kc, *Vc;
    cudaGetSymbolAddress((void**)&Qh,  g_Qh);
    cudaGetSymbolAddress((void**)&Kh,  g_Kh);
    cudaGetSymbolAddress((void**)&Vh,  g_Vh);
    cudaGetSymbolAddress((void**)&ctx, g_ctx);
    cudaGetSymbolAddress((void**)&Wc,  g_Wc);
    cudaGetSymbolAddress((void**)&Kc,  g_Kc);
    cudaGetSymbolAddress((void**)&Vc,  g_Vc);

    const int WCN = 64 * 32 * 32;
    dim3 pgrid(4, 16);
    wprep_kernel<<<pgrid, 256>>>(Wq, Wc + 0 * WCN);
    wprep_kernel<<<pgrid, 256>>>(Wk, Wc + 1 * WCN);
    wprep_kernel<<<pgrid, 256>>>(Wv, Wc + 2 * WCN);
    wprep_kernel<<<pgrid, 256>>>(Wo, Wc + 3 * WCN);

    dim3 ggrid(4, 64);
    gemm_mma<1><<<ggrid, 256>>>(q, Wc + 0 * WCN, bq, Qh);   // [B,H,S,D]
    gemm_mma<1><<<ggrid, 256>>>(k, Wc + 1 * WCN, bk, Kh);   // [B,H,S,D]
    gemm_mma<2><<<ggrid, 256>>>(v, Wc + 2 * WCN, bv, Vh);   // [B,H,D,S]

    dim3 kgrid(32, BATCH * HEADS);
    kpack_kernel<<<kgrid, 256>>>(Kh, Kc);
    vpack_kernel<<<kgrid, 256>>>(Vh, Vc);

    cudaFuncSetAttribute(attn_mma, cudaFuncAttributeMaxDynamicSharedMemorySize, SM_TOT);
    attn_mma<<<dim3(SEQ / 128, BATCH * HEADS), 256, SM_TOT>>>(Qh, Kc, Vc, mask, ctx);

    gemm_mma<0><<<ggrid, 256>>>(ctx, Wc + 3 * WCN, bo, out);
}

// round 9
// speedup vs baseline: 4.5633x; 1.3339x over previous
#include <cuda_runtime.h>
#include <cuda.h>
#include <cuda_fp16.h>
#include <math.h>

#define EMBED 512
#define HEADS 8
#define DEPTH 64
#define BATCH 2
#define SEQ   4096
#define MROWS (BATCH * SEQ)          // 8192

typedef unsigned long long u64;
typedef unsigned int u32;

// ---------------------------------------------------------------------------
// Device scratch
// ---------------------------------------------------------------------------
__device__ float g_Qh[BATCH * HEADS * SEQ * DEPTH];   // [B,H,S,D]
__device__ float g_Kh[BATCH * HEADS * SEQ * DEPTH];   // [B,H,S,D]
__device__ float g_Vh[BATCH * HEADS * DEPTH * SEQ];   // [B,H,D,S] (d-major)
__device__ float g_ctx[BATCH * SEQ * EMBED];          // [B,S,E]
__device__ uint4 g_Wc[4 * 64 * 32 * 32];              // packed W B-cells (hi+lo)
__device__ uint2 g_Kc[BATCH * HEADS * 32 * 2048];     // packed K cells (hi only)
__device__ uint2 g_Vc[BATCH * HEADS * 32 * 2048];     // packed V cells (hi only)

// ---------------------------------------------------------------------------
// fp16 mma.sync + cp.async helpers (baseline PTX, compute_103-safe)
// ---------------------------------------------------------------------------
__device__ __forceinline__ void mma16(float c[4], const u32 a[4], u32 b0, u32 b1) {
    asm("mma.sync.aligned.m16n8k16.row.col.f32.f16.f16.f32 "
        "{%0,%1,%2,%3}, {%4,%5,%6,%7}, {%8,%9}, {%0,%1,%2,%3};"
        : "+f"(c[0]), "+f"(c[1]), "+f"(c[2]), "+f"(c[3])
        : "r"(a[0]), "r"(a[1]), "r"(a[2]), "r"(a[3]), "r"(b0), "r"(b1));
}
__device__ __forceinline__ u32 f2h2(float lo, float hi) {
    __half2 h = __float22half2_rn(make_float2(lo, hi));
    return *(u32*)&h;
}
__device__ __forceinline__ float2 h22f(u32 v) {
    __half2 h = *(__half2*)&v;
    return __half22float2(h);
}
__device__ __forceinline__ void split2(float2 x, u32& hi, u32& lo) {
    hi = f2h2(x.x, x.y);
    float2 back = h22f(hi);
    lo = f2h2(x.x - back.x, x.y - back.y);
}
__device__ __forceinline__ u32 smem_u32(const void* p) {
    u32 a;
    asm("{ .reg .u64 t; cvta.to.shared.u64 t, %1; cvt.u32.u64 %0, t; }"
        : "=r"(a) : "l"(p));
    return a;
}
__device__ __forceinline__ void cpa16(u32 saddr, const void* gptr) {
    asm volatile("cp.async.cg.shared.global [%0], [%1], 16;"
                 :: "r"(saddr), "l"(gptr));
}
#define CP_COMMIT() asm volatile("cp.async.commit_group;" ::: "memory")
#define CP_WAIT(n)  asm volatile("cp.async.wait_group %0;" :: "n"(n) : "memory")

// ---------------------------------------------------------------------------
// Weight prep: W[512][512] -> B-fragment cells [ntg 64][ksg 32][ln 32] (hi+lo)
// ---------------------------------------------------------------------------
__global__ __launch_bounds__(256) void wprep_kernel(
    const float* __restrict__ W, uint4* __restrict__ out)
{
    __shared__ float sw[32][132];
    const int tid = threadIdx.x;
    const int n0 = blockIdx.x * 128;
    const int k0 = blockIdx.y * 32;

#pragma unroll
    for (int it = 0; it < 4; ++it) {
        int idx = tid + it * 256;
        int row = idx >> 5;
        int n4  = (idx & 31) * 4;
        *(float4*)&sw[row][n4] = *(const float4*)(W + (size_t)(k0 + row) * 512 + n0 + n4);
    }
    __syncthreads();

#pragma unroll
    for (int it = 0; it < 4; ++it) {
        int idx = tid + it * 256;
        int ln = idx & 31, ks = (idx >> 5) & 1, nt = idx >> 6;
        int gg = ln >> 2, tt = ln & 3;
        int nl = nt * 8 + gg;
        int kl = ks * 16 + 2 * tt;
        float2 x0 = make_float2(sw[kl][nl],     sw[kl + 1][nl]);
        float2 x1 = make_float2(sw[kl + 8][nl], sw[kl + 9][nl]);
        uint4 cv;
        split2(x0, cv.x, cv.z);
        split2(x1, cv.y, cv.w);
        out[((size_t)(blockIdx.x * 16 + nt) * 32 + blockIdx.y * 2 + ks) * 32 + ln] = cv;
    }
}

// ---------------------------------------------------------------------------
// K pack (hi only): [B,H,S,D] fp32 -> uint2 cells. grid(32 jt, 16 bh).
// ---------------------------------------------------------------------------
__global__ __launch_bounds__(256) void kpack_kernel(
    const float* __restrict__ Kh, uint2* __restrict__ out)
{
    const int tid = threadIdx.x;
    const int jt = blockIdx.x, bh = blockIdx.y, j0 = jt * 128;
    const float* Kb = Kh + (size_t)bh * SEQ * DEPTH;
    uint2* o = out + ((size_t)bh * 32 + jt) * 2048;
#pragma unroll
    for (int it = 0; it < 8; ++it) {
        int c = tid + it * 256;
        int ln = c & 31, ks = (c >> 5) & 3, nt = c >> 7;
        int gg = ln >> 2, tt = ln & 3;
        const float* src = Kb + (size_t)(j0 + nt * 8 + gg) * DEPTH + ks * 16 + 2 * tt;
        float2 x0 = *(const float2*)src;
        float2 x1 = *(const float2*)(src + 8);
        uint2 cv;
        cv.x = f2h2(x0.x, x0.y);
        cv.y = f2h2(x1.x, x1.y);
        o[c] = cv;
    }
}

// ---------------------------------------------------------------------------
// V pack (hi only): [B,H,D,S] fp32 -> uint2 cells.
// ---------------------------------------------------------------------------
__global__ __launch_bounds__(256) void vpack_kernel(
    const float* __restrict__ Vh, uint2* __restrict__ out)
{
    const int tid = threadIdx.x;
    const int jt = blockIdx.x, bh = blockIdx.y, j0 = jt * 128;
    const float* Vb = Vh + (size_t)bh * DEPTH * SEQ;
    uint2* o = out + ((size_t)bh * 32 + jt) * 2048;
#pragma unroll
    for (int it = 0; it < 8; ++it) {
        int c = tid + it * 256;
        int ln = c & 31, ks = (c >> 5) & 7, nt = c >> 8;
        int gg = ln >> 2, tt = ln & 3;
        const float* src = Vb + (size_t)(nt * 8 + gg) * SEQ + j0 + ks * 16 + 2 * tt;
        float2 x0 = *(const float2*)src;
        float2 x1 = *(const float2*)(src + 8);
        uint2 cv;
        cv.x = f2h2(x0.x, x0.y);
        cv.y = f2h2(x1.x, x1.y);
        o[c] = cv;
    }
}

// ---------------------------------------------------------------------------
// Tensor-core GEMM (hi/lo fp16 MMA, 3-term) -- unchanged.
// MODE 0: C row-major; MODE 1: C -> [B,H,S,D]; MODE 2: C^T -> [B,H,D,S]
// ---------------------------------------------------------------------------
#define ASTR 36

template <int MODE>
__global__ __launch_bounds__(256, 2) void gemm_mma(
    const float* __restrict__ A, const uint4* __restrict__ Wc,
    const float* __restrict__ bias, float* __restrict__ C)
{
    __shared__ float As[128 * ASTR];
    __shared__ uint4 BC[16 * 2 * 32];

    const int tid  = threadIdx.x;
    const int w    = tid >> 5;
    const int lane = tid & 31;
    const int g    = lane >> 2;
    const int t4   = lane & 3;
    const int n0   = blockIdx.x * 128;
    const int m0   = blockIdx.y * 128;

    float acc[16][4];
#pragma unroll
    for (int nt = 0; nt < 16; ++nt)
#pragma unroll
        for (int e = 0; e < 4; ++e) acc[nt][e] = 0.0f;

    const float* arow = As + (16 * w + g) * ASTR;

    for (int kc = 0; kc < 16; ++kc) {
        __syncthreads();
#pragma unroll
        for (int it = 0; it < 4; ++it) {
            int idx = tid + it * 256;
            int row = idx >> 3;
            int k4  = (idx & 7) * 4;
            *(float4*)&As[row * ASTR + k4] =
                *(const float4*)(A + (size_t)(m0 + row) * 512 + kc * 32 + k4);
        }
#pragma unroll
        for (int it = 0; it < 4; ++it) {
            int idx = tid + it * 256;
            int ln = idx & 31, ks = (idx >> 5) & 1, nt = idx >> 6;
            BC[idx] = Wc[((size_t)(blockIdx.x * 16 + nt) * 32 + kc * 2 + ks) * 32 + ln];
        }
        __syncthreads();

#pragma unroll
        for (int ks = 0; ks < 2; ++ks) {
            u32 ahi[4], alo[4];
            const float* base = arow + ks * 16 + 2 * t4;
            split2(*(const float2*)(base),                ahi[0], alo[0]);
            split2(*(const float2*)(base + 8 * ASTR),     ahi[1], alo[1]);
            split2(*(const float2*)(base + 8),            ahi[2], alo[2]);
            split2(*(const float2*)(base + 8 * ASTR + 8), ahi[3], alo[3]);
#pragma unroll
            for (int nt = 0; nt < 16; ++nt) {
                uint4 cv = BC[(nt * 2 + ks) * 32 + lane];
                mma16(acc[nt], ahi, cv.x, cv.y);
                mma16(acc[nt], alo, cv.x, cv.y);
                mma16(acc[nt], ahi, cv.z, cv.w);
            }
        }
    }

    const int m = m0 + 16 * w + g;
    if (MODE == 0) {
#pragma unroll
        for (int nt = 0; nt < 16; ++nt) {
            int n = n0 + nt * 8 + 2 * t4;
            float2 bi = *(const float2*)(bias + n);
            *(float2*)(C + (size_t)m * 512 + n) =
                make_float2(acc[nt][0] + bi.x, acc[nt][1] + bi.y);
            *(float2*)(C + (size_t)(m + 8) * 512 + n) =
                make_float2(acc[nt][2] + bi.x, acc[nt][3] + bi.y);
        }
    } else if (MODE == 1) {
        int b = m >> 12, s = m & 4095;
#pragma unroll
        for (int nt = 0; nt < 16; ++nt) {
            int n = n0 + nt * 8 + 2 * t4;
            int h = n >> 6, d = n & 63;
            float2 bi = *(const float2*)(bias + n);
            float* dst = C + ((size_t)(b * HEADS + h) * SEQ + s) * DEPTH + d;
            *(float2*)dst = make_float2(acc[nt][0] + bi.x, acc[nt][1] + bi.y);
            *(float2*)(dst + 8 * DEPTH) =
                make_float2(acc[nt][2] + bi.x, acc[nt][3] + bi.y);
        }
    } else {
        int b = m >> 12, s = m & 4095;
#pragma unroll
        for (int nt = 0; nt < 16; ++nt) {
            int n = n0 + nt * 8 + 2 * t4;
            int h = n >> 6, d = n & 63;
            float2 bi = *(const float2*)(bias + n);
            float* base = C + ((size_t)(b * HEADS + h) * DEPTH + d) * SEQ + s;
            base[0]       = acc[nt][0] + bi.x;
            base[SEQ]     = acc[nt][1] + bi.y;
            base[8]       = acc[nt][2] + bi.x;
            base[SEQ + 8] = acc[nt][3] + bi.y;
        }
    }
}

// ---------------------------------------------------------------------------
// Flash attention: hi-only K/V cells (uint2), K AND V double-buffered cp.async.
// QK^T: (Qhi+Qlo)*Khi (2 MMAs). PV: P*Vhi (1 MMA).
// ---------------------------------------------------------------------------
#define SM_MASK 0
#define SM_KC0  1024
#define SM_KC1  (SM_KC0 + 16384)
#define SM_VC0  (SM_KC1 + 16384)
#define SM_VC1  (SM_VC0 + 16384)
#define SM_TOT  (SM_VC1 + 16384)    // 66560 B

__global__ __launch_bounds__(256, 2) void attn_mma(
    const float* __restrict__ Qg, const uint2* __restrict__ Kc,
    const uint2* __restrict__ Vc, const float* __restrict__ mask,
    float* __restrict__ ctx)
{
    extern __shared__ char smem[];
    const u32 sb = smem_u32(smem);
    float* smask = (float*)(smem + SM_MASK);

    const int tid  = threadIdx.x;
    const int w    = tid >> 5;
    const int lane = tid & 31;
    const int g    = lane >> 2;
    const int t4   = lane & 3;
    const int bh   = blockIdx.y, b = bh >> 3, h = bh & 7;
    const int qi0  = blockIdx.x * 128;

    const float* Qb  = Qg + (size_t)bh * SEQ * DEPTH;
    const uint2* Kcb = Kc + (size_t)bh * 32 * 2048;
    const uint2* Vcb = Vc + (size_t)bh * 32 * 2048;
    const float* mb  = mask + (size_t)b * SEQ;

    // Q fragments in registers (hi/lo)
    u32 qhi[4][4], qlo[4][4];
    {
        const float* q0 = Qb + (size_t)(qi0 + 16 * w + g) * DEPTH;
#pragma unroll
        for (int ks = 0; ks < 4; ++ks) {
            int d0 = ks * 16 + 2 * t4;
            split2(*(const float2*)(q0 + d0),                 qhi[ks][0], qlo[ks][0]);
            split2(*(const float2*)(q0 + 8 * DEPTH + d0),     qhi[ks][1], qlo[ks][1]);
            split2(*(const float2*)(q0 + d0 + 8),             qhi[ks][2], qlo[ks][2]);
            split2(*(const float2*)(q0 + 8 * DEPTH + d0 + 8), qhi[ks][3], qlo[ks][3]);
        }
    }

    float oacc[8][4];
#pragma unroll
    for (int nt = 0; nt < 8; ++nt)
#pragma unroll
        for (int e = 0; e < 4; ++e) oacc[nt][e] = 0.0f;
    float lsum0 = 0.0f, lsum1 = 0.0f;

    // prologue: prefetch K0 + V0 (tiles are 1024 uint4 each)
#pragma unroll
    for (int it = 0; it < 4; ++it) {
        int c = tid + it * 256;
        cpa16(sb + SM_KC0 + c * 16, (const uint4*)Kcb + c);
        cpa16(sb + SM_VC0 + c * 16, (const uint4*)Vcb + c);
    }
    CP_COMMIT();

    for (int jt = 0; jt < 32; ++jt) {
        const int cur = jt & 1;
        const uint2* KCb = (const uint2*)(smem + (cur ? SM_KC1 : SM_KC0));
        const uint2* VCb = (const uint2*)(smem + (cur ? SM_VC1 : SM_VC0));
        const u32 kbufn  = sb + (cur ? SM_KC0 : SM_KC1);
        const u32 vbufn  = sb + (cur ? SM_VC0 : SM_VC1);

        __syncthreads();   // prior compute done before overwriting the other bufs

        // prefetch jt+1 (K and V) into the other buffers
        int jn = (jt + 1 < 32) ? jt + 1 : 31;
        const uint4* ksrc = (const uint4*)(Kcb + (size_t)jn * 2048);
        const uint4* vsrc = (const uint4*)(Vcb + (size_t)jn * 2048);
#pragma unroll
        for (int it = 0; it < 4; ++it) {
            int c = tid + it * 256;
            cpa16(kbufn + c * 16, ksrc + c);
            cpa16(vbufn + c * 16, vsrc + c);
        }
        CP_COMMIT();

        if (tid < 128) smask[tid] = mb[jt * 128 + tid] * (-1e9f);

        CP_WAIT(1);        // group(jt) complete; group(jt+1) in flight
        __syncthreads();

        // ---- QK^T + exp + pack ----
        u32 pa[8][4];
#pragma unroll
        for (int kp = 0; kp < 8; ++kp) {
            float sacc[2][4] = {{0.f,0.f,0.f,0.f},{0.f,0.f,0.f,0.f}};
#pragma unroll
            for (int i = 0; i < 2; ++i) {
                int nt = kp * 2 + i;
#pragma unroll
                for (int ks = 0; ks < 4; ++ks) {
                    uint2 cv = KCb[(nt * 4 + ks) * 32 + lane];
                    mma16(sacc[i], qhi[ks], cv.x, cv.y);
                    mma16(sacc[i], qlo[ks], cv.x, cv.y);
                }
            }
            float p[2][4];
#pragma unroll
            for (int i = 0; i < 2; ++i) {
                int c0 = (kp * 2 + i) * 8 + 2 * t4;
                float mk0 = smask[c0], mk1 = smask[c0 + 1];
                p[i][0] = __expf(fmaf(sacc[i][0], 0.125f, mk0));
                p[i][1] = __expf(fmaf(sacc[i][1], 0.125f, mk1));
                p[i][2] = __expf(fmaf(sacc[i][2], 0.125f, mk0));
                p[i][3] = __expf(fmaf(sacc[i][3], 0.125f, mk1));
                lsum0 += p[i][0] + p[i][1];
                lsum1 += p[i][2] + p[i][3];
            }
            pa[kp][0] = f2h2(p[0][0], p[0][1]);
            pa[kp][1] = f2h2(p[0][2], p[0][3]);
            pa[kp][2] = f2h2(p[1][0], p[1][1]);
            pa[kp][3] = f2h2(p[1][2], p[1][3]);
        }

        // ---- O += P V (hi only) ----
#pragma unroll
        for (int ks = 0; ks < 8; ++ks) {
#pragma unroll
            for (int nt = 0; nt < 8; ++nt) {
                uint2 cv = VCb[(nt * 8 + ks) * 32 + lane];
                mma16(oacc[nt], pa[ks], cv.x, cv.y);
            }
        }
    }

    lsum0 += __shfl_xor_sync(0xffffffffu, lsum0, 1);
    lsum0 += __shfl_xor_sync(0xffffffffu, lsum0, 2);
    lsum1 += __shfl_xor_sync(0xffffffffu, lsum1, 1);
    lsum1 += __shfl_xor_sync(0xffffffffu, lsum1, 2);
    float inv0 = 1.0f / lsum0, inv1 = 1.0f / lsum1;

    int row0 = qi0 + 16 * w + g;
    float* dst0 = ctx + ((size_t)(b * SEQ + row0)) * EMBED + h * DEPTH;
    float* dst1 = dst0 + (size_t)8 * EMBED;
#pragma unroll
    for (int nt = 0; nt < 8; ++nt) {
        int c = nt * 8 + 2 * t4;
        *(float2*)(dst0 + c) = make_float2(oacc[nt][0] * inv0, oacc[nt][1] * inv0);
        *(float2*)(dst1 + c) = make_float2(oacc[nt][2] * inv1, oacc[nt][3] * inv1);
    }
}

// ---------------------------------------------------------------------------
// Launcher
// ---------------------------------------------------------------------------
extern "C" void kernel_launch(void* const* d_in, const int* in_sizes, int n_in,
                              void* d_out, int out_size)
{
    const float* q    = (const float*)d_in[0];
    const float* k    = (const float*)d_in[1];
    const float* v    = (const float*)d_in[2];
    const float* mask = (const float*)d_in[3];
    const float* Wq   = (const float*)d_in[4];
    const float* bq   = (const float*)d_in[5];
    const float* Wk   = (const float*)d_in[6];
    const float* bk   = (const float*)d_in[7];
    const float* Wv   = (const float*)d_in[8];
    const float* bv   = (const float*)d_in[9];
    const float* Wo   = (const float*)d_in[10];
    const float* bo   = (const float*)d_in[11];
    float* out = (float*)d_out;

    float *Qh, *Kh, *Vh, *ctx;
    uint4* Wc;
    uint2 *Kc, *Vc;
    cudaGetSymbolAddress((void**)&Qh,  g_Qh);
    cudaGetSymbolAddress((void**)&Kh,  g_Kh);
    cudaGetSymbolAddress((void**)&Vh,  g_Vh);
    cudaGetSymbolAddress((void**)&ctx, g_ctx);
    cudaGetSymbolAddress((void**)&Wc,  g_Wc);
    cudaGetSymbolAddress((void**)&Kc,  g_Kc);
    cudaGetSymbolAddress((void**)&Vc,  g_Vc);

    const int WCN = 64 * 32 * 32;
    dim3 pgrid(4, 16);
    wprep_kernel<<<pgrid, 256>>>(Wq, Wc + 0 * WCN);
    wprep_kernel<<<pgrid, 256>>>(Wk, Wc + 1 * WCN);
    wprep_kernel<<<pgrid, 256>>>(Wv, Wc + 2 * WCN);
    wprep_kernel<<<pgrid, 256>>>(Wo, Wc + 3 * WCN);

    dim3 ggrid(4, 64);
    gemm_mma<1><<<ggrid, 256>>>(q, Wc + 0 * WCN, bq, Qh);   // [B,H,S,D]
    gemm_mma<1><<<ggrid, 256>>>(k, Wc + 1 * WCN, bk, Kh);   // [B,H,S,D]
    gemm_mma<2><<<ggrid, 256>>>(v, Wc + 2 * WCN, bv, Vh);   // [B,H,D,S]

    dim3 kgrid(32, BATCH * HEADS);
    kpack_kernel<<<kgrid, 256>>>(Kh, Kc);
    vpack_kernel<<<kgrid, 256>>>(Vh, Vc);

    cudaFuncSetAttribute(attn_mma, cudaFuncAttributeMaxDynamicSharedMemorySize, SM_TOT);
    attn_mma<<<dim3(SEQ / 128, BATCH * HEADS), 256, SM_TOT>>>(Qh, Kc, Vc, mask, ctx);

    gemm_mma<0><<<ggrid, 256>>>(ctx, Wc + 3 * WCN, bo, out);
}

// round 10
// speedup vs baseline: 5.5563x; 1.2176x over previous
#include <cuda_runtime.h>
#include <cuda.h>
#include <cuda_fp16.h>
#include <math.h>

#define EMBED 512
#define HEADS 8
#define DEPTH 64
#define BATCH 2
#define SEQ   4096
#define MROWS (BATCH * SEQ)          // 8192

typedef unsigned long long u64;
typedef unsigned int u32;

// ---------------------------------------------------------------------------
// Device scratch
// ---------------------------------------------------------------------------
__device__ float g_Qh[BATCH * HEADS * SEQ * DEPTH];   // [B,H,S,D]
__device__ float g_Vh[BATCH * HEADS * DEPTH * SEQ];   // [B,H,D,S] (d-major)
__device__ float g_ctx[BATCH * SEQ * EMBED];          // [B,S,E]
__device__ uint4 g_Wc[4 * 64 * 32 * 32];              // packed W B-cells (hi+lo)
__device__ uint2 g_Kc[BATCH * HEADS * 32 * 2048];     // packed K cells (hi only)
__device__ uint2 g_Vc[BATCH * HEADS * 32 * 2048];     // packed V cells (hi only)

// ---------------------------------------------------------------------------
// fp16 mma.sync + cp.async helpers (baseline PTX, compute_103-safe)
// ---------------------------------------------------------------------------
__device__ __forceinline__ void mma16(float c[4], const u32 a[4], u32 b0, u32 b1) {
    asm("mma.sync.aligned.m16n8k16.row.col.f32.f16.f16.f32 "
        "{%0,%1,%2,%3}, {%4,%5,%6,%7}, {%8,%9}, {%0,%1,%2,%3};"
        : "+f"(c[0]), "+f"(c[1]), "+f"(c[2]), "+f"(c[3])
        : "r"(a[0]), "r"(a[1]), "r"(a[2]), "r"(a[3]), "r"(b0), "r"(b1));
}
__device__ __forceinline__ u32 f2h2(float lo, float hi) {
    __half2 h = __float22half2_rn(make_float2(lo, hi));
    return *(u32*)&h;
}
__device__ __forceinline__ float2 h22f(u32 v) {
    __half2 h = *(__half2*)&v;
    return __half22float2(h);
}
__device__ __forceinline__ void split2(float2 x, u32& hi, u32& lo) {
    hi = f2h2(x.x, x.y);
    float2 back = h22f(hi);
    lo = f2h2(x.x - back.x, x.y - back.y);
}
__device__ __forceinline__ u32 smem_u32(const void* p) {
    u32 a;
    asm("{ .reg .u64 t; cvta.to.shared.u64 t, %1; cvt.u32.u64 %0, t; }"
        : "=r"(a) : "l"(p));
    return a;
}
__device__ __forceinline__ void cpa16(u32 saddr, const void* gptr) {
    asm volatile("cp.async.cg.shared.global [%0], [%1], 16;"
                 :: "r"(saddr), "l"(gptr));
}
#define CP_COMMIT() asm volatile("cp.async.commit_group;" ::: "memory")
#define CP_WAIT(n)  asm volatile("cp.async.wait_group %0;" :: "n"(n) : "memory")

// ---------------------------------------------------------------------------
// Weight prep x4 in one launch: W[512][512] -> cells [ntg 64][ksg 32][ln 32]
// grid (4 nblk, 16 kblk, 4 which)
// ---------------------------------------------------------------------------
__global__ __launch_bounds__(256) void wprep4_kernel(
    const float* __restrict__ W0, const float* __restrict__ W1,
    const float* __restrict__ W2, const float* __restrict__ W3,
    uint4* __restrict__ out)
{
    __shared__ float sw[32][132];
    const int tid = threadIdx.x;
    const int n0 = blockIdx.x * 128;
    const int k0 = blockIdx.y * 32;
    const int wz = blockIdx.z;
    const float* W = (wz == 0) ? W0 : (wz == 1) ? W1 : (wz == 2) ? W2 : W3;
    uint4* o = out + (size_t)wz * (64 * 32 * 32);

#pragma unroll
    for (int it = 0; it < 4; ++it) {
        int idx = tid + it * 256;
        int row = idx >> 5;
        int n4  = (idx & 31) * 4;
        *(float4*)&sw[row][n4] = *(const float4*)(W + (size_t)(k0 + row) * 512 + n0 + n4);
    }
    __syncthreads();

#pragma unroll
    for (int it = 0; it < 4; ++it) {
        int idx = tid + it * 256;
        int ln = idx & 31, ks = (idx >> 5) & 1, nt = idx >> 6;
        int gg = ln >> 2, tt = ln & 3;
        int nl = nt * 8 + gg;
        int kl = ks * 16 + 2 * tt;
        float2 x0 = make_float2(sw[kl][nl],     sw[kl + 1][nl]);
        float2 x1 = make_float2(sw[kl + 8][nl], sw[kl + 9][nl]);
        uint4 cv;
        split2(x0, cv.x, cv.z);
        split2(x1, cv.y, cv.w);
        o[((size_t)(blockIdx.x * 16 + nt) * 32 + blockIdx.y * 2 + ks) * 32 + ln] = cv;
    }
}

// ---------------------------------------------------------------------------
// V pack (hi only): [B,H,D,S] fp32 -> uint2 cells.
// ---------------------------------------------------------------------------
__global__ __launch_bounds__(256) void vpack_kernel(
    const float* __restrict__ Vh, uint2* __restrict__ out)
{
    const int tid = threadIdx.x;
    const int jt = blockIdx.x, bh = blockIdx.y, j0 = jt * 128;
    const float* Vb = Vh + (size_t)bh * DEPTH * SEQ;
    uint2* o = out + ((size_t)bh * 32 + jt) * 2048;
#pragma unroll
    for (int it = 0; it < 8; ++it) {
        int c = tid + it * 256;
        int ln = c & 31, ks = (c >> 5) & 7, nt = c >> 8;
        int gg = ln >> 2, tt = ln & 3;
        const float* src = Vb + (size_t)(nt * 8 + gg) * SEQ + j0 + ks * 16 + 2 * tt;
        float2 x0 = *(const float2*)src;
        float2 x1 = *(const float2*)(src + 8);
        uint2 cv;
        cv.x = f2h2(x0.x, x0.y);
        cv.y = f2h2(x1.x, x1.y);
        o[c] = cv;
    }
}

// ---------------------------------------------------------------------------
// Tensor-core GEMM, 2-term hi/lo: C = ahi*(bhi+blo) + bias.
// MODE 0: C row-major; MODE 1: C -> [B,H,S,D]; MODE 2: C^T -> [B,H,D,S];
// MODE 3: K-projection -> packed K cells (uint2, hi only) directly.
// ---------------------------------------------------------------------------
#define ASTR 36

template <int MODE>
__global__ __launch_bounds__(256, 2) void gemm_mma(
    const float* __restrict__ A, const uint4* __restrict__ Wc,
    const float* __restrict__ bias, float* __restrict__ C)
{
    __shared__ float As[128 * ASTR];
    __shared__ uint4 BC[16 * 2 * 32];

    const int tid  = threadIdx.x;
    const int w    = tid >> 5;
    const int lane = tid & 31;
    const int g    = lane >> 2;
    const int t4   = lane & 3;
    const int n0   = blockIdx.x * 128;
    const int m0   = blockIdx.y * 128;

    float acc[16][4];
#pragma unroll
    for (int nt = 0; nt < 16; ++nt)
#pragma unroll
        for (int e = 0; e < 4; ++e) acc[nt][e] = 0.0f;

    const float* arow = As + (16 * w + g) * ASTR;

    for (int kc = 0; kc < 16; ++kc) {
        __syncthreads();
#pragma unroll
        for (int it = 0; it < 4; ++it) {
            int idx = tid + it * 256;
            int row = idx >> 3;
            int k4  = (idx & 7) * 4;
            *(float4*)&As[row * ASTR + k4] =
                *(const float4*)(A + (size_t)(m0 + row) * 512 + kc * 32 + k4);
        }
#pragma unroll
        for (int it = 0; it < 4; ++it) {
            int idx = tid + it * 256;
            int ln = idx & 31, ks = (idx >> 5) & 1, nt = idx >> 6;
            BC[idx] = Wc[((size_t)(blockIdx.x * 16 + nt) * 32 + kc * 2 + ks) * 32 + ln];
        }
        __syncthreads();

#pragma unroll
        for (int ks = 0; ks < 2; ++ks) {
            u32 ahi[4];
            const float* base = arow + ks * 16 + 2 * t4;
            float2 a0 = *(const float2*)(base);
            float2 a1 = *(const float2*)(base + 8 * ASTR);
            float2 a2 = *(const float2*)(base + 8);
            float2 a3 = *(const float2*)(base + 8 * ASTR + 8);
            ahi[0] = f2h2(a0.x, a0.y);
            ahi[1] = f2h2(a1.x, a1.y);
            ahi[2] = f2h2(a2.x, a2.y);
            ahi[3] = f2h2(a3.x, a3.y);
#pragma unroll
            for (int nt = 0; nt < 16; ++nt) {
                uint4 cv = BC[(nt * 2 + ks) * 32 + lane];
                mma16(acc[nt], ahi, cv.x, cv.y);
                mma16(acc[nt], ahi, cv.z, cv.w);
            }
        }
    }

    const int m = m0 + 16 * w + g;
    if (MODE == 0) {
#pragma unroll
        for (int nt = 0; nt < 16; ++nt) {
            int n = n0 + nt * 8 + 2 * t4;
            float2 bi = *(const float2*)(bias + n);
            *(float2*)(C + (size_t)m * 512 + n) =
                make_float2(acc[nt][0] + bi.x, acc[nt][1] + bi.y);
            *(float2*)(C + (size_t)(m + 8) * 512 + n) =
                make_float2(acc[nt][2] + bi.x, acc[nt][3] + bi.y);
        }
    } else if (MODE == 1) {
        int b = m >> 12, s = m & 4095;
#pragma unroll
        for (int nt = 0; nt < 16; ++nt) {
            int n = n0 + nt * 8 + 2 * t4;
            int h = n >> 6, d = n & 63;
            float2 bi = *(const float2*)(bias + n);
            float* dst = C + ((size_t)(b * HEADS + h) * SEQ + s) * DEPTH + d;
            *(float2*)dst = make_float2(acc[nt][0] + bi.x, acc[nt][1] + bi.y);
            *(float2*)(dst + 8 * DEPTH) =
                make_float2(acc[nt][2] + bi.x, acc[nt][3] + bi.y);
        }
    } else if (MODE == 2) {
        int b = m >> 12, s = m & 4095;
#pragma unroll
        for (int nt = 0; nt < 16; ++nt) {
            int n = n0 + nt * 8 + 2 * t4;
            int h = n >> 6, d = n & 63;
            float2 bi = *(const float2*)(bias + n);
            float* base = C + ((size_t)(b * HEADS + h) * DEPTH + d) * SEQ + s;
            base[0]       = acc[nt][0] + bi.x;
            base[SEQ]     = acc[nt][1] + bi.y;
            base[8]       = acc[nt][2] + bi.x;
            base[SEQ + 8] = acc[nt][3] + bi.y;
        }
    } else {
        // MODE 3: write packed K cells directly (hi only).
        // cell c = ((s>>3)&15)*128 + (d>>4)*32 + (s&7)*4 + t4 ; word = nt&1
        int b = m >> 12, s = m & 4095;
        int jt = s >> 7;
        u32* o = (u32*)C;   // cell base array viewed as u32
#pragma unroll
        for (int nt = 0; nt < 16; ++nt) {
            int n = n0 + nt * 8 + 2 * t4;
            int h = n >> 6, d = n & 63;
            float2 bi = *(const float2*)(bias + n);
            size_t tilebase = ((size_t)(b * HEADS + h) * 32 + jt) * 4096;  // u32 units
            int c0 = ((s >> 3) & 15) * 128 + (d >> 4) * 32 + (s & 7) * 4 + t4;
            int c1 = (((s + 8) >> 3) & 15) * 128 + (d >> 4) * 32 + (s & 7) * 4 + t4;
            o[tilebase + (size_t)c0 * 2 + (nt & 1)] =
                f2h2(acc[nt][0] + bi.x, acc[nt][1] + bi.y);
            o[tilebase + (size_t)c1 * 2 + (nt & 1)] =
                f2h2(acc[nt][2] + bi.x, acc[nt][3] + bi.y);
        }
    }
}

// ---------------------------------------------------------------------------
// Flash attention: Q hi-only, K/V hi-only cells, K+V double-buffered cp.async.
// QK^T: Qhi*Khi (1 MMA). PV: P*Vhi (1 MMA).
// ---------------------------------------------------------------------------
#define SM_MASK 0
#define SM_KC0  1024
#define SM_KC1  (SM_KC0 + 16384)
#define SM_VC0  (SM_KC1 + 16384)
#define SM_VC1  (SM_VC0 + 16384)
#define SM_TOT  (SM_VC1 + 16384)    // 66560 B

__global__ __launch_bounds__(256, 2) void attn_mma(
    const float* __restrict__ Qg, const uint2* __restrict__ Kc,
    const uint2* __restrict__ Vc, const float* __restrict__ mask,
    float* __restrict__ ctx)
{
    extern __shared__ char smem[];
    const u32 sb = smem_u32(smem);
    float* smask = (float*)(smem + SM_MASK);

    const int tid  = threadIdx.x;
    const int w    = tid >> 5;
    const int lane = tid & 31;
    const int g    = lane >> 2;
    const int t4   = lane & 3;
    const int bh   = blockIdx.y, b = bh >> 3, h = bh & 7;
    const int qi0  = blockIdx.x * 128;

    const float* Qb  = Qg + (size_t)bh * SEQ * DEPTH;
    const uint2* Kcb = Kc + (size_t)bh * 32 * 2048;
    const uint2* Vcb = Vc + (size_t)bh * 32 * 2048;
    const float* mb  = mask + (size_t)b * SEQ;

    // Q fragments (hi only)
    u32 qhi[4][4];
    {
        const float* q0 = Qb + (size_t)(qi0 + 16 * w + g) * DEPTH;
#pragma unroll
        for (int ks = 0; ks < 4; ++ks) {
            int d0 = ks * 16 + 2 * t4;
            float2 a0 = *(const float2*)(q0 + d0);
            float2 a1 = *(const float2*)(q0 + 8 * DEPTH + d0);
            float2 a2 = *(const float2*)(q0 + d0 + 8);
            float2 a3 = *(const float2*)(q0 + 8 * DEPTH + d0 + 8);
            qhi[ks][0] = f2h2(a0.x, a0.y);
            qhi[ks][1] = f2h2(a1.x, a1.y);
            qhi[ks][2] = f2h2(a2.x, a2.y);
            qhi[ks][3] = f2h2(a3.x, a3.y);
        }
    }

    float oacc[8][4];
#pragma unroll
    for (int nt = 0; nt < 8; ++nt)
#pragma unroll
        for (int e = 0; e < 4; ++e) oacc[nt][e] = 0.0f;
    float lsum0 = 0.0f, lsum1 = 0.0f;

    // prologue: prefetch K0 + V0
#pragma unroll
    for (int it = 0; it < 4; ++it) {
        int c = tid + it * 256;
        cpa16(sb + SM_KC0 + c * 16, (const uint4*)Kcb + c);
        cpa16(sb + SM_VC0 + c * 16, (const uint4*)Vcb + c);
    }
    CP_COMMIT();

    for (int jt = 0; jt < 32; ++jt) {
        const int cur = jt & 1;
        const uint2* KCb = (const uint2*)(smem + (cur ? SM_KC1 : SM_KC0));
        const uint2* VCb = (const uint2*)(smem + (cur ? SM_VC1 : SM_VC0));
        const u32 kbufn  = sb + (cur ? SM_KC0 : SM_KC1);
        const u32 vbufn  = sb + (cur ? SM_VC0 : SM_VC1);

        __syncthreads();

        int jn = (jt + 1 < 32) ? jt + 1 : 31;
        const uint4* ksrc = (const uint4*)(Kcb + (size_t)jn * 2048);
        const uint4* vsrc = (const uint4*)(Vcb + (size_t)jn * 2048);
#pragma unroll
        for (int it = 0; it < 4; ++it) {
            int c = tid + it * 256;
            cpa16(kbufn + c * 16, ksrc + c);
            cpa16(vbufn + c * 16, vsrc + c);
        }
        CP_COMMIT();

        if (tid < 128) smask[tid] = mb[jt * 128 + tid] * (-1e9f);

        CP_WAIT(1);
        __syncthreads();

        // ---- QK^T + exp + pack ----
        u32 pa[8][4];
#pragma unroll
        for (int kp = 0; kp < 8; ++kp) {
            float sacc[2][4] = {{0.f,0.f,0.f,0.f},{0.f,0.f,0.f,0.f}};
#pragma unroll
            for (int i = 0; i < 2; ++i) {
                int nt = kp * 2 + i;
#pragma unroll
                for (int ks = 0; ks < 4; ++ks) {
                    uint2 cv = KCb[(nt * 4 + ks) * 32 + lane];
                    mma16(sacc[i], qhi[ks], cv.x, cv.y);
                }
            }
            float p[2][4];
#pragma unroll
            for (int i = 0; i < 2; ++i) {
                int c0 = (kp * 2 + i) * 8 + 2 * t4;
                float mk0 = smask[c0], mk1 = smask[c0 + 1];
                p[i][0] = __expf(fmaf(sacc[i][0], 0.125f, mk0));
                p[i][1] = __expf(fmaf(sacc[i][1], 0.125f, mk1));
                p[i][2] = __expf(fmaf(sacc[i][2], 0.125f, mk0));
                p[i][3] = __expf(fmaf(sacc[i][3], 0.125f, mk1));
                lsum0 += p[i][0] + p[i][1];
                lsum1 += p[i][2] + p[i][3];
            }
            pa[kp][0] = f2h2(p[0][0], p[0][1]);
            pa[kp][1] = f2h2(p[0][2], p[0][3]);
            pa[kp][2] = f2h2(p[1][0], p[1][1]);
            pa[kp][3] = f2h2(p[1][2], p[1][3]);
        }

        // ---- O += P V ----
#pragma unroll
        for (int ks = 0; ks < 8; ++ks) {
#pragma unroll
            for (int nt = 0; nt < 8; ++nt) {
                uint2 cv = VCb[(nt * 8 + ks) * 32 + lane];
                mma16(oacc[nt], pa[ks], cv.x, cv.y);
            }
        }
    }

    lsum0 += __shfl_xor_sync(0xffffffffu, lsum0, 1);
    lsum0 += __shfl_xor_sync(0xffffffffu, lsum0, 2);
    lsum1 += __shfl_xor_sync(0xffffffffu, lsum1, 1);
    lsum1 += __shfl_xor_sync(0xffffffffu, lsum1, 2);
    float inv0 = 1.0f / lsum0, inv1 = 1.0f / lsum1;

    int row0 = qi0 + 16 * w + g;
    float* dst0 = ctx + ((size_t)(b * SEQ + row0)) * EMBED + h * DEPTH;
    float* dst1 = dst0 + (size_t)8 * EMBED;
#pragma unroll
    for (int nt = 0; nt < 8; ++nt) {
        int c = nt * 8 + 2 * t4;
        *(float2*)(dst0 + c) = make_float2(oacc[nt][0] * inv0, oacc[nt][1] * inv0);
        *(float2*)(dst1 + c) = make_float2(oacc[nt][2] * inv1, oacc[nt][3] * inv1);
    }
}

// ---------------------------------------------------------------------------
// Launcher
// ---------------------------------------------------------------------------
extern "C" void kernel_launch(void* const* d_in, const int* in_sizes, int n_in,
                              void* d_out, int out_size)
{
    const float* q    = (const float*)d_in[0];
    const float* k    = (const float*)d_in[1];
    const float* v    = (const float*)d_in[2];
    const float* mask = (const float*)d_in[3];
    const float* Wq   = (const float*)d_in[4];
    const float* bq   = (const float*)d_in[5];
    const float* Wk   = (const float*)d_in[6];
    const float* bk   = (const float*)d_in[7];
    const float* Wv   = (const float*)d_in[8];
    const float* bv   = (const float*)d_in[9];
    const float* Wo   = (const float*)d_in[10];
    const float* bo   = (const float*)d_in[11];
    float* out = (float*)d_out;

    float *Qh, *Vh, *ctx;
    uint4* Wc;
    uint2 *Kc, *Vc;
    cudaGetSymbolAddress((void**)&Qh,  g_Qh);
    cudaGetSymbolAddress((void**)&Vh,  g_Vh);
    cudaGetSymbolAddress((void**)&ctx, g_ctx);
    cudaGetSymbolAddress((void**)&Wc,  g_Wc);
    cudaGetSymbolAddress((void**)&Kc,  g_Kc);
    cudaGetSymbolAddress((void**)&Vc,  g_Vc);

    const int WCN = 64 * 32 * 32;
    wprep4_kernel<<<dim3(4, 16, 4), 256>>>(Wq, Wk, Wv, Wo, Wc);

    dim3 ggrid(4, 64);
    gemm_mma<1><<<ggrid, 256>>>(q, Wc + 0 * WCN, bq, Qh);           // Q: [B,H,S,D]
    gemm_mma<3><<<ggrid, 256>>>(k, Wc + 1 * WCN, bk, (float*)Kc);   // K: packed cells
    gemm_mma<2><<<ggrid, 256>>>(v, Wc + 2 * WCN, bv, Vh);           // V: [B,H,D,S]

    vpack_kernel<<<dim3(32, BATCH * HEADS), 256>>>(Vh, Vc);

    cudaFuncSetAttribute(attn_mma, cudaFuncAttributeMaxDynamicSharedMemorySize, SM_TOT);
    attn_mma<<<dim3(SEQ / 128, BATCH * HEADS), 256, SM_TOT>>>(Qh, Kc, Vc, mask, ctx);

    gemm_mma<0><<<ggrid, 256>>>(ctx, Wc + 3 * WCN, bo, out);
}

// round 11
// speedup vs baseline: 5.9824x; 1.0767x over previous
#include <cuda_runtime.h>
#include <cuda.h>
#include <cuda_fp16.h>
#include <math.h>

#define EMBED 512
#define HEADS 8
#define DEPTH 64
#define BATCH 2
#define SEQ   4096
#define MROWS (BATCH * SEQ)          // 8192

typedef unsigned long long u64;
typedef unsigned int u32;

// ---------------------------------------------------------------------------
// Device scratch
// ---------------------------------------------------------------------------
__device__ float g_Qh[BATCH * HEADS * SEQ * DEPTH];   // [B,H,S,D]
__device__ float g_ctx[BATCH * SEQ * EMBED];          // [B,S,E]
__device__ uint4 g_Wc[4 * 64 * 32 * 32];              // packed W B-cells (hi+lo)
__device__ uint2 g_Kc[BATCH * HEADS * 32 * 2048];     // packed K cells (hi only)
__device__ uint2 g_Vc[BATCH * HEADS * 32 * 2048];     // packed V cells (hi only)

// ---------------------------------------------------------------------------
// fp16 mma.sync + cp.async helpers (baseline PTX, compute_103-safe)
// ---------------------------------------------------------------------------
__device__ __forceinline__ void mma16(float c[4], const u32 a[4], u32 b0, u32 b1) {
    asm("mma.sync.aligned.m16n8k16.row.col.f32.f16.f16.f32 "
        "{%0,%1,%2,%3}, {%4,%5,%6,%7}, {%8,%9}, {%0,%1,%2,%3};"
        : "+f"(c[0]), "+f"(c[1]), "+f"(c[2]), "+f"(c[3])
        : "r"(a[0]), "r"(a[1]), "r"(a[2]), "r"(a[3]), "r"(b0), "r"(b1));
}
__device__ __forceinline__ u32 f2h2(float lo, float hi) {
    __half2 h = __float22half2_rn(make_float2(lo, hi));
    return *(u32*)&h;
}
__device__ __forceinline__ float2 h22f(u32 v) {
    __half2 h = *(__half2*)&v;
    return __half22float2(h);
}
__device__ __forceinline__ void split2(float2 x, u32& hi, u32& lo) {
    hi = f2h2(x.x, x.y);
    float2 back = h22f(hi);
    lo = f2h2(x.x - back.x, x.y - back.y);
}
__device__ __forceinline__ u32 packhh(__half a, __half b) {
    return (u32)__half_as_ushort(a) | ((u32)__half_as_ushort(b) << 16);
}
__device__ __forceinline__ u32 smem_u32(const void* p) {
    u32 a;
    asm("{ .reg .u64 t; cvta.to.shared.u64 t, %1; cvt.u32.u64 %0, t; }"
        : "=r"(a) : "l"(p));
    return a;
}
__device__ __forceinline__ void cpa16(u32 saddr, const void* gptr) {
    asm volatile("cp.async.cg.shared.global [%0], [%1], 16;"
                 :: "r"(saddr), "l"(gptr));
}
#define CP_COMMIT() asm volatile("cp.async.commit_group;" ::: "memory")
#define CP_WAIT(n)  asm volatile("cp.async.wait_group %0;" :: "n"(n) : "memory")

// ---------------------------------------------------------------------------
// Weight prep x4: W[512][512] -> cells [ntg 64][ksg 32][ln 32] (hi+lo)
// ---------------------------------------------------------------------------
__global__ __launch_bounds__(256) void wprep4_kernel(
    const float* __restrict__ W0, const float* __restrict__ W1,
    const float* __restrict__ W2, const float* __restrict__ W3,
    uint4* __restrict__ out)
{
    __shared__ float sw[32][132];
    const int tid = threadIdx.x;
    const int n0 = blockIdx.x * 128;
    const int k0 = blockIdx.y * 32;
    const int wz = blockIdx.z;
    const float* W = (wz == 0) ? W0 : (wz == 1) ? W1 : (wz == 2) ? W2 : W3;
    uint4* o = out + (size_t)wz * (64 * 32 * 32);

#pragma unroll
    for (int it = 0; it < 4; ++it) {
        int idx = tid + it * 256;
        int row = idx >> 5;
        int n4  = (idx & 31) * 4;
        *(float4*)&sw[row][n4] = *(const float4*)(W + (size_t)(k0 + row) * 512 + n0 + n4);
    }
    __syncthreads();

#pragma unroll
    for (int it = 0; it < 4; ++it) {
        int idx = tid + it * 256;
        int ln = idx & 31, ks = (idx >> 5) & 1, nt = idx >> 6;
        int gg = ln >> 2, tt = ln & 3;
        int nl = nt * 8 + gg;
        int kl = ks * 16 + 2 * tt;
        float2 x0 = make_float2(sw[kl][nl],     sw[kl + 1][nl]);
        float2 x1 = make_float2(sw[kl + 8][nl], sw[kl + 9][nl]);
        uint4 cv;
        split2(x0, cv.x, cv.z);
        split2(x1, cv.y, cv.w);
        o[((size_t)(blockIdx.x * 16 + nt) * 32 + blockIdx.y * 2 + ks) * 32 + ln] = cv;
    }
}

// ---------------------------------------------------------------------------
// Tensor-core GEMM, 2-term hi/lo, cp.async double-buffered.
// MODE 0: C row-major; MODE 1: C -> [B,H,S,D];
// MODE 3: K-projection -> packed K cells (uint2, hi only);
// MODE 4: V-projection -> packed V cells via smem fp16 transpose.
// Dynamic smem: A0 | A1 | B0 | B1 (69632 B); MODE 4 reuses it for staging.
// ---------------------------------------------------------------------------
#define ASTR 36
#define SG_A0 0
#define SG_A1 18432
#define SG_B0 36864
#define SG_B1 53248
#define SG_TOT 69632
#define HST 132

template <int MODE>
__global__ __launch_bounds__(256, 2) void gemm_mma(
    const float* __restrict__ A, const uint4* __restrict__ Wc,
    const float* __restrict__ bias, float* __restrict__ C)
{
    extern __shared__ char smem[];
    const u32 sb = smem_u32(smem);

    const int tid  = threadIdx.x;
    const int w    = tid >> 5;
    const int lane = tid & 31;
    const int g    = lane >> 2;
    const int t4   = lane & 3;
    const int n0   = blockIdx.x * 128;
    const int m0   = blockIdx.y * 128;

    float acc[16][4];
#pragma unroll
    for (int nt = 0; nt < 16; ++nt)
#pragma unroll
        for (int e = 0; e < 4; ++e) acc[nt][e] = 0.0f;

    // prologue: prefetch chunk 0
#pragma unroll
    for (int it = 0; it < 4; ++it) {
        int idx = tid + it * 256;
        int row = idx >> 3, k4 = (idx & 7) * 4;
        cpa16(sb + SG_A0 + (row * ASTR + k4) * 4,
              A + (size_t)(m0 + row) * 512 + k4);
        int ln = idx & 31, ks = (idx >> 5) & 1, nt = idx >> 6;
        cpa16(sb + SG_B0 + idx * 16,
              Wc + ((size_t)(blockIdx.x * 16 + nt) * 32 + ks) * 32 + ln);
    }
    CP_COMMIT();

    for (int kc = 0; kc < 16; ++kc) {
        const int cur = kc & 1;
        const u32 abufn = sb + (cur ? SG_A0 : SG_A1);
        const u32 bbufn = sb + (cur ? SG_B0 : SG_B1);

        __syncthreads();   // prior compute done before overwriting next bufs

        int kn = (kc + 1 < 16) ? kc + 1 : 15;
#pragma unroll
        for (int it = 0; it < 4; ++it) {
            int idx = tid + it * 256;
            int row = idx >> 3, k4 = (idx & 7) * 4;
            cpa16(abufn + (row * ASTR + k4) * 4,
                  A + (size_t)(m0 + row) * 512 + kn * 32 + k4);
            int ln = idx & 31, ks = (idx >> 5) & 1, nt = idx >> 6;
            cpa16(bbufn + idx * 16,
                  Wc + ((size_t)(blockIdx.x * 16 + nt) * 32 + kn * 2 + ks) * 32 + ln);
        }
        CP_COMMIT();

        CP_WAIT(1);
        __syncthreads();

        const float* arow = (const float*)(smem + (cur ? SG_A1 : SG_A0)) + (16 * w + g) * ASTR;
        const uint4* BCc  = (const uint4*)(smem + (cur ? SG_B1 : SG_B0));

#pragma unroll
        for (int ks = 0; ks < 2; ++ks) {
            u32 ahi[4];
            const float* base = arow + ks * 16 + 2 * t4;
            float2 a0 = *(const float2*)(base);
            float2 a1 = *(const float2*)(base + 8 * ASTR);
            float2 a2 = *(const float2*)(base + 8);
            float2 a3 = *(const float2*)(base + 8 * ASTR + 8);
            ahi[0] = f2h2(a0.x, a0.y);
            ahi[1] = f2h2(a1.x, a1.y);
            ahi[2] = f2h2(a2.x, a2.y);
            ahi[3] = f2h2(a3.x, a3.y);
#pragma unroll
            for (int nt = 0; nt < 16; ++nt) {
                uint4 cv = BCc[(nt * 2 + ks) * 32 + lane];
                mma16(acc[nt], ahi, cv.x, cv.y);
                mma16(acc[nt], ahi, cv.z, cv.w);
            }
        }
    }

    const int m = m0 + 16 * w + g;
    if (MODE == 0) {
#pragma unroll
        for (int nt = 0; nt < 16; ++nt) {
            int n = n0 + nt * 8 + 2 * t4;
            float2 bi = *(const float2*)(bias + n);
            *(float2*)(C + (size_t)m * 512 + n) =
                make_float2(acc[nt][0] + bi.x, acc[nt][1] + bi.y);
            *(float2*)(C + (size_t)(m + 8) * 512 + n) =
                make_float2(acc[nt][2] + bi.x, acc[nt][3] + bi.y);
        }
    } else if (MODE == 1) {
        int b = m >> 12, s = m & 4095;
#pragma unroll
        for (int nt = 0; nt < 16; ++nt) {
            int n = n0 + nt * 8 + 2 * t4;
            int h = n >> 6, d = n & 63;
            float2 bi = *(const float2*)(bias + n);
            float* dst = C + ((size_t)(b * HEADS + h) * SEQ + s) * DEPTH + d;
            *(float2*)dst = make_float2(acc[nt][0] + bi.x, acc[nt][1] + bi.y);
            *(float2*)(dst + 8 * DEPTH) =
                make_float2(acc[nt][2] + bi.x, acc[nt][3] + bi.y);
        }
    } else if (MODE == 3) {
        // K cells directly (hi only): pairs along d match C-frag pairs.
        int b = m >> 12, s = m & 4095;
        int jt = s >> 7;
        u32* o = (u32*)C;
#pragma unroll
        for (int nt = 0; nt < 16; ++nt) {
            int n = n0 + nt * 8 + 2 * t4;
            int h = n >> 6, d = n & 63;
            float2 bi = *(const float2*)(bias + n);
            size_t tilebase = ((size_t)(b * HEADS + h) * 32 + jt) * 4096;  // u32 units
            int c0 = ((s >> 3) & 15) * 128 + (d >> 4) * 32 + (s & 7) * 4 + t4;
            int c1 = (((s + 8) >> 3) & 15) * 128 + (d >> 4) * 32 + (s & 7) * 4 + t4;
            o[tilebase + (size_t)c0 * 2 + (nt & 1)] =
                f2h2(acc[nt][0] + bi.x, acc[nt][1] + bi.y);
            o[tilebase + (size_t)c1 * 2 + (nt & 1)] =
                f2h2(acc[nt][2] + bi.x, acc[nt][3] + bi.y);
        }
    } else {
        // MODE 4: V cells via fp16 smem transpose (pairs along s).
        __syncthreads();                    // k-loop buffers dead; reuse smem
        __half* Hs = (__half*)smem;         // [128 s][HST]
        const int r0 = 16 * w + g;
#pragma unroll
        for (int nt = 0; nt < 16; ++nt) {
            int n = nt * 8 + 2 * t4;        // local n (d within 2 heads)
            float2 bi = *(const float2*)(bias + n0 + n);
            *(u32*)&Hs[r0 * HST + n]       = f2h2(acc[nt][0] + bi.x, acc[nt][1] + bi.y);
            *(u32*)&Hs[(r0 + 8) * HST + n] = f2h2(acc[nt][2] + bi.x, acc[nt][3] + bi.y);
        }
        __syncthreads();

        int b = m0 >> 12, jt = (m0 & 4095) >> 7;
        uint2* o = (uint2*)C;
#pragma unroll
        for (int it = 0; it < 16; ++it) {
            int c  = tid + it * 256;        // 4096 cells (2 head-tiles)
            int hh = c >> 11;
            int cl = c & 2047;
            int ln = cl & 31, ks = (cl >> 5) & 7, ntv = cl >> 8;
            int gg = ln >> 2, tt = ln & 3;
            int nl = hh * 64 + ntv * 8 + gg;    // local col (d)
            int j  = ks * 16 + 2 * tt;          // local row (s)
            uint2 cv;
            cv.x = packhh(Hs[j * HST + nl],       Hs[(j + 1) * HST + nl]);
            cv.y = packhh(Hs[(j + 8) * HST + nl], Hs[(j + 9) * HST + nl]);
            int hgl = (n0 >> 6) + hh;
            o[((size_t)(b * HEADS + hgl) * 32 + jt) * 2048 + cl] = cv;
        }
    }
}

// ---------------------------------------------------------------------------
// Flash attention: Q hi-only, K/V hi-only cells, K+V double-buffered cp.async.
// ---------------------------------------------------------------------------
#define SM_MASK 0
#define SM_KC0  1024
#define SM_KC1  (SM_KC0 + 16384)
#define SM_VC0  (SM_KC1 + 16384)
#define SM_VC1  (SM_VC0 + 16384)
#define SM_TOT  (SM_VC1 + 16384)    // 66560 B

__global__ __launch_bounds__(256, 2) void attn_mma(
    const float* __restrict__ Qg, const uint2* __restrict__ Kc,
    const uint2* __restrict__ Vc, const float* __restrict__ mask,
    float* __restrict__ ctx)
{
    extern __shared__ char smem[];
    const u32 sb = smem_u32(smem);
    float* smask = (float*)(smem + SM_MASK);

    const int tid  = threadIdx.x;
    const int w    = tid >> 5;
    const int lane = tid & 31;
    const int g    = lane >> 2;
    const int t4   = lane & 3;
    const int bh   = blockIdx.y, b = bh >> 3, h = bh & 7;
    const int qi0  = blockIdx.x * 128;

    const float* Qb  = Qg + (size_t)bh * SEQ * DEPTH;
    const uint2* Kcb = Kc + (size_t)bh * 32 * 2048;
    const uint2* Vcb = Vc + (size_t)bh * 32 * 2048;
    const float* mb  = mask + (size_t)b * SEQ;

    u32 qhi[4][4];
    {
        const float* q0 = Qb + (size_t)(qi0 + 16 * w + g) * DEPTH;
#pragma unroll
        for (int ks = 0; ks < 4; ++ks) {
            int d0 = ks * 16 + 2 * t4;
            float2 a0 = *(const float2*)(q0 + d0);
            float2 a1 = *(const float2*)(q0 + 8 * DEPTH + d0);
            float2 a2 = *(const float2*)(q0 + d0 + 8);
            float2 a3 = *(const float2*)(q0 + 8 * DEPTH + d0 + 8);
            qhi[ks][0] = f2h2(a0.x, a0.y);
            qhi[ks][1] = f2h2(a1.x, a1.y);
            qhi[ks][2] = f2h2(a2.x, a2.y);
            qhi[ks][3] = f2h2(a3.x, a3.y);
        }
    }

    float oacc[8][4];
#pragma unroll
    for (int nt = 0; nt < 8; ++nt)
#pragma unroll
        for (int e = 0; e < 4; ++e) oacc[nt][e] = 0.0f;
    float lsum0 = 0.0f, lsum1 = 0.0f;

#pragma unroll
    for (int it = 0; it < 4; ++it) {
        int c = tid + it * 256;
        cpa16(sb + SM_KC0 + c * 16, (const uint4*)Kcb + c);
        cpa16(sb + SM_VC0 + c * 16, (const uint4*)Vcb + c);
    }
    CP_COMMIT();

    for (int jt = 0; jt < 32; ++jt) {
        const int cur = jt & 1;
        const uint2* KCb = (const uint2*)(smem + (cur ? SM_KC1 : SM_KC0));
        const uint2* VCb = (const uint2*)(smem + (cur ? SM_VC1 : SM_VC0));
        const u32 kbufn  = sb + (cur ? SM_KC0 : SM_KC1);
        const u32 vbufn  = sb + (cur ? SM_VC0 : SM_VC1);

        __syncthreads();

        int jn = (jt + 1 < 32) ? jt + 1 : 31;
        const uint4* ksrc = (const uint4*)(Kcb + (size_t)jn * 2048);
        const uint4* vsrc = (const uint4*)(Vcb + (size_t)jn * 2048);
#pragma unroll
        for (int it = 0; it < 4; ++it) {
            int c = tid + it * 256;
            cpa16(kbufn + c * 16, ksrc + c);
            cpa16(vbufn + c * 16, vsrc + c);
        }
        CP_COMMIT();

        if (tid < 128) smask[tid] = mb[jt * 128 + tid] * (-1e9f);

        CP_WAIT(1);
        __syncthreads();

        u32 pa[8][4];
#pragma unroll
        for (int kp = 0; kp < 8; ++kp) {
            float sacc[2][4] = {{0.f,0.f,0.f,0.f},{0.f,0.f,0.f,0.f}};
#pragma unroll
            for (int i = 0; i < 2; ++i) {
                int nt = kp * 2 + i;
#pragma unroll
                for (int ks = 0; ks < 4; ++ks) {
                    uint2 cv = KCb[(nt * 4 + ks) * 32 + lane];
                    mma16(sacc[i], qhi[ks], cv.x, cv.y);
                }
            }
            float p[2][4];
#pragma unroll
            for (int i = 0; i < 2; ++i) {
                int c0 = (kp * 2 + i) * 8 + 2 * t4;
                float mk0 = smask[c0], mk1 = smask[c0 + 1];
                p[i][0] = __expf(fmaf(sacc[i][0], 0.125f, mk0));
                p[i][1] = __expf(fmaf(sacc[i][1], 0.125f, mk1));
                p[i][2] = __expf(fmaf(sacc[i][2], 0.125f, mk0));
                p[i][3] = __expf(fmaf(sacc[i][3], 0.125f, mk1));
                lsum0 += p[i][0] + p[i][1];
                lsum1 += p[i][2] + p[i][3];
            }
            pa[kp][0] = f2h2(p[0][0], p[0][1]);
            pa[kp][1] = f2h2(p[0][2], p[0][3]);
            pa[kp][2] = f2h2(p[1][0], p[1][1]);
            pa[kp][3] = f2h2(p[1][2], p[1][3]);
        }

#pragma unroll
        for (int ks = 0; ks < 8; ++ks) {
#pragma unroll
            for (int nt = 0; nt < 8; ++nt) {
                uint2 cv = VCb[(nt * 8 + ks) * 32 + lane];
                mma16(oacc[nt], pa[ks], cv.x, cv.y);
            }
        }
    }

    lsum0 += __shfl_xor_sync(0xffffffffu, lsum0, 1);
    lsum0 += __shfl_xor_sync(0xffffffffu, lsum0, 2);
    lsum1 += __shfl_xor_sync(0xffffffffu, lsum1, 1);
    lsum1 += __shfl_xor_sync(0xffffffffu, lsum1, 2);
    float inv0 = 1.0f / lsum0, inv1 = 1.0f / lsum1;

    int row0 = qi0 + 16 * w + g;
    float* dst0 = ctx + ((size_t)(b * SEQ + row0)) * EMBED + h * DEPTH;
    float* dst1 = dst0 + (size_t)8 * EMBED;
#pragma unroll
    for (int nt = 0; nt < 8; ++nt) {
        int c = nt * 8 + 2 * t4;
        *(float2*)(dst0 + c) = make_float2(oacc[nt][0] * inv0, oacc[nt][1] * inv0);
        *(float2*)(dst1 + c) = make_float2(oacc[nt][2] * inv1, oacc[nt][3] * inv1);
    }
}

// ---------------------------------------------------------------------------
// Launcher
// ---------------------------------------------------------------------------
extern "C" void kernel_launch(void* const* d_in, const int* in_sizes, int n_in,
                              void* d_out, int out_size)
{
    const float* q    = (const float*)d_in[0];
    const float* k    = (const float*)d_in[1];
    const float* v    = (const float*)d_in[2];
    const float* mask = (const float*)d_in[3];
    const float* Wq   = (const float*)d_in[4];
    const float* bq   = (const float*)d_in[5];
    const float* Wk   = (const float*)d_in[6];
    const float* bk   = (const float*)d_in[7];
    const float* Wv   = (const float*)d_in[8];
    const float* bv   = (const float*)d_in[9];
    const float* Wo   = (const float*)d_in[10];
    const float* bo   = (const float*)d_in[11];
    float* out = (float*)d_out;

    float *Qh, *ctx;
    uint4* Wc;
    uint2 *Kc, *Vc;
    cudaGetSymbolAddress((void**)&Qh,  g_Qh);
    cudaGetSymbolAddress((void**)&ctx, g_ctx);
    cudaGetSymbolAddress((void**)&Wc,  g_Wc);
    cudaGetSymbolAddress((void**)&Kc,  g_Kc);
    cudaGetSymbolAddress((void**)&Vc,  g_Vc);

    const int WCN = 64 * 32 * 32;
    wprep4_kernel<<<dim3(4, 16, 4), 256>>>(Wq, Wk, Wv, Wo, Wc);

    cudaFuncSetAttribute(gemm_mma<0>, cudaFuncAttributeMaxDynamicSharedMemorySize, SG_TOT);
    cudaFuncSetAttribute(gemm_mma<1>, cudaFuncAttributeMaxDynamicSharedMemorySize, SG_TOT);
    cudaFuncSetAttribute(gemm_mma<3>, cudaFuncAttributeMaxDynamicSharedMemorySize, SG_TOT);
    cudaFuncSetAttribute(gemm_mma<4>, cudaFuncAttributeMaxDynamicSharedMemorySize, SG_TOT);

    dim3 ggrid(4, 64);
    gemm_mma<1><<<ggrid, 256, SG_TOT>>>(q, Wc + 0 * WCN, bq, Qh);           // Q
    gemm_mma<3><<<ggrid, 256, SG_TOT>>>(k, Wc + 1 * WCN, bk, (float*)Kc);   // K cells
    gemm_mma<4><<<ggrid, 256, SG_TOT>>>(v, Wc + 2 * WCN, bv, (float*)Vc);   // V cells

    cudaFuncSetAttribute(attn_mma, cudaFuncAttributeMaxDynamicSharedMemorySize, SM_TOT);
    attn_mma<<<dim3(SEQ / 128, BATCH * HEADS), 256, SM_TOT>>>(Qh, Kc, Vc, mask, ctx);

    gemm_mma<0><<<ggrid, 256, SG_TOT>>>(ctx, Wc + 3 * WCN, bo, out);
}

// round 12
// speedup vs baseline: 6.2271x; 1.0409x over previous
#include <cuda_runtime.h>
#include <cuda.h>
#include <cuda_fp16.h>
#include <math.h>

#define EMBED 512
#define HEADS 8
#define DEPTH 64
#define BATCH 2
#define SEQ   4096
#define MROWS (BATCH * SEQ)          // 8192

typedef unsigned long long u64;
typedef unsigned int u32;

// ---------------------------------------------------------------------------
// Device scratch
// ---------------------------------------------------------------------------
__device__ float g_Qh[BATCH * HEADS * SEQ * DEPTH];   // [B,H,S,D]
__device__ float g_ctx[BATCH * SEQ * EMBED];          // [B,S,E]
__device__ uint4 g_Wc[4 * 64 * 32 * 32];              // packed W B-cells (hi+lo)
__device__ uint4 g_Kc[BATCH * HEADS * 32 * 1024];     // packed K cells (uint4, 2 ks/word)
__device__ uint4 g_Vc[BATCH * HEADS * 32 * 1024];     // packed V cells (uint4, 2 ks/word)

// ---------------------------------------------------------------------------
// fp16 mma.sync + cp.async helpers (baseline PTX, compute_103-safe)
// ---------------------------------------------------------------------------
__device__ __forceinline__ void mma16(float c[4], const u32 a[4], u32 b0, u32 b1) {
    asm("mma.sync.aligned.m16n8k16.row.col.f32.f16.f16.f32 "
        "{%0,%1,%2,%3}, {%4,%5,%6,%7}, {%8,%9}, {%0,%1,%2,%3};"
        : "+f"(c[0]), "+f"(c[1]), "+f"(c[2]), "+f"(c[3])
        : "r"(a[0]), "r"(a[1]), "r"(a[2]), "r"(a[3]), "r"(b0), "r"(b1));
}
__device__ __forceinline__ u32 f2h2(float lo, float hi) {
    __half2 h = __float22half2_rn(make_float2(lo, hi));
    return *(u32*)&h;
}
__device__ __forceinline__ float2 h22f(u32 v) {
    __half2 h = *(__half2*)&v;
    return __half22float2(h);
}
__device__ __forceinline__ void split2(float2 x, u32& hi, u32& lo) {
    hi = f2h2(x.x, x.y);
    float2 back = h22f(hi);
    lo = f2h2(x.x - back.x, x.y - back.y);
}
__device__ __forceinline__ u32 packhh(__half a, __half b) {
    return (u32)__half_as_ushort(a) | ((u32)__half_as_ushort(b) << 16);
}
__device__ __forceinline__ u32 smem_u32(const void* p) {
    u32 a;
    asm("{ .reg .u64 t; cvta.to.shared.u64 t, %1; cvt.u32.u64 %0, t; }"
        : "=r"(a) : "l"(p));
    return a;
}
__device__ __forceinline__ void cpa16(u32 saddr, const void* gptr) {
    asm volatile("cp.async.cg.shared.global [%0], [%1], 16;"
                 :: "r"(saddr), "l"(gptr));
}
#define CP_COMMIT() asm volatile("cp.async.commit_group;" ::: "memory")
#define CP_WAIT(n)  asm volatile("cp.async.wait_group %0;" :: "n"(n) : "memory")

// ---------------------------------------------------------------------------
// Weight prep x4: W[512][512] -> cells [ntg 64][ksg 32][ln 32] (hi+lo)
// ---------------------------------------------------------------------------
__global__ __launch_bounds__(256) void wprep4_kernel(
    const float* __restrict__ W0, const float* __restrict__ W1,
    const float* __restrict__ W2, const float* __restrict__ W3,
    uint4* __restrict__ out)
{
    __shared__ float sw[32][132];
    const int tid = threadIdx.x;
    const int n0 = blockIdx.x * 128;
    const int k0 = blockIdx.y * 32;
    const int wz = blockIdx.z;
    const float* W = (wz == 0) ? W0 : (wz == 1) ? W1 : (wz == 2) ? W2 : W3;
    uint4* o = out + (size_t)wz * (64 * 32 * 32);

#pragma unroll
    for (int it = 0; it < 4; ++it) {
        int idx = tid + it * 256;
        int row = idx >> 5;
        int n4  = (idx & 31) * 4;
        *(float4*)&sw[row][n4] = *(const float4*)(W + (size_t)(k0 + row) * 512 + n0 + n4);
    }
    __syncthreads();

#pragma unroll
    for (int it = 0; it < 4; ++it) {
        int idx = tid + it * 256;
        int ln = idx & 31, ks = (idx >> 5) & 1, nt = idx >> 6;
        int gg = ln >> 2, tt = ln & 3;
        int nl = nt * 8 + gg;
        int kl = ks * 16 + 2 * tt;
        float2 x0 = make_float2(sw[kl][nl],     sw[kl + 1][nl]);
        float2 x1 = make_float2(sw[kl + 8][nl], sw[kl + 9][nl]);
        uint4 cv;
        split2(x0, cv.x, cv.z);
        split2(x1, cv.y, cv.w);
        o[((size_t)(blockIdx.x * 16 + nt) * 32 + blockIdx.y * 2 + ks) * 32 + ln] = cv;
    }
}

// ---------------------------------------------------------------------------
// Shared GEMM mainloop pieces (2-term hi/lo, cp.async double-buffered)
// ---------------------------------------------------------------------------
#define ASTR 36
#define SG_A0 0
#define SG_A1 18432
#define SG_B0 36864
#define SG_B1 53248
#define SG_TOT 69632
#define HST 132

__device__ __forceinline__ void gemm_mainloop(
    const float* __restrict__ A, const uint4* __restrict__ Wc,
    const char* smem, u32 sb, int m0, int nblk,
    int tid, int w, int g, int t4, int lane, float acc[16][4])
{
#pragma unroll
    for (int nt = 0; nt < 16; ++nt)
#pragma unroll
        for (int e = 0; e < 4; ++e) acc[nt][e] = 0.0f;

#pragma unroll
    for (int it = 0; it < 4; ++it) {
        int idx = tid + it * 256;
        int row = idx >> 3, k4 = (idx & 7) * 4;
        cpa16(sb + SG_A0 + (row * ASTR + k4) * 4,
              A + (size_t)(m0 + row) * 512 + k4);
        int ln = idx & 31, ks = (idx >> 5) & 1, nt = idx >> 6;
        cpa16(sb + SG_B0 + idx * 16,
              Wc + ((size_t)(nblk * 16 + nt) * 32 + ks) * 32 + ln);
    }
    CP_COMMIT();

    for (int kc = 0; kc < 16; ++kc) {
        const int cur = kc & 1;
        const u32 abufn = sb + (cur ? SG_A0 : SG_A1);
        const u32 bbufn = sb + (cur ? SG_B0 : SG_B1);

        __syncthreads();

        int kn = (kc + 1 < 16) ? kc + 1 : 15;
#pragma unroll
        for (int it = 0; it < 4; ++it) {
            int idx = tid + it * 256;
            int row = idx >> 3, k4 = (idx & 7) * 4;
            cpa16(abufn + (row * ASTR + k4) * 4,
                  A + (size_t)(m0 + row) * 512 + kn * 32 + k4);
            int ln = idx & 31, ks = (idx >> 5) & 1, nt = idx >> 6;
            cpa16(bbufn + idx * 16,
                  Wc + ((size_t)(nblk * 16 + nt) * 32 + kn * 2 + ks) * 32 + ln);
        }
        CP_COMMIT();

        CP_WAIT(1);
        __syncthreads();

        const float* arow = (const float*)(smem + (cur ? SG_A1 : SG_A0)) + (16 * w + g) * ASTR;
        const uint4* BCc  = (const uint4*)(smem + (cur ? SG_B1 : SG_B0));

#pragma unroll
        for (int ks = 0; ks < 2; ++ks) {
            u32 ahi[4];
            const float* base = arow + ks * 16 + 2 * t4;
            float2 a0 = *(const float2*)(base);
            float2 a1 = *(const float2*)(base + 8 * ASTR);
            float2 a2 = *(const float2*)(base + 8);
            float2 a3 = *(const float2*)(base + 8 * ASTR + 8);
            ahi[0] = f2h2(a0.x, a0.y);
            ahi[1] = f2h2(a1.x, a1.y);
            ahi[2] = f2h2(a2.x, a2.y);
            ahi[3] = f2h2(a3.x, a3.y);
#pragma unroll
            for (int nt = 0; nt < 16; ++nt) {
                uint4 cv = BCc[(nt * 2 + ks) * 32 + lane];
                mma16(acc[nt], ahi, cv.x, cv.y);
                mma16(acc[nt], ahi, cv.z, cv.w);
            }
        }
    }
}

// ---------------------------------------------------------------------------
// Fused Q/K/V projection GEMM. grid (4 n, 64 m, 3 which).
// z=0: Q -> [B,H,S,D] fp32; z=1: K -> packed uint4 cells; z=2: V -> cells.
// ---------------------------------------------------------------------------
__global__ __launch_bounds__(256, 2) void gemm_qkv(
    const float* __restrict__ q, const float* __restrict__ k,
    const float* __restrict__ v, const uint4* __restrict__ Wc,
    const float* __restrict__ bq, const float* __restrict__ bk,
    const float* __restrict__ bv, float* __restrict__ Qh,
    u32* __restrict__ Kc, u32* __restrict__ Vc)
{
    extern __shared__ char smem[];
    const u32 sb = smem_u32(smem);

    const int tid  = threadIdx.x;
    const int w    = tid >> 5;
    const int lane = tid & 31;
    const int g    = lane >> 2;
    const int t4   = lane & 3;
    const int n0   = blockIdx.x * 128;
    const int m0   = blockIdx.y * 128;
    const int z    = blockIdx.z;

    const float* A    = (z == 0) ? q : (z == 1) ? k : v;
    const float* bias = (z == 0) ? bq : (z == 1) ? bk : bv;
    const uint4* Wcz  = Wc + (size_t)z * (64 * 32 * 32);

    float acc[16][4];
    gemm_mainloop(A, Wcz, smem, sb, m0, blockIdx.x, tid, w, g, t4, lane, acc);

    const int m = m0 + 16 * w + g;
    if (z == 0) {
        int b = m >> 12, s = m & 4095;
#pragma unroll
        for (int nt = 0; nt < 16; ++nt) {
            int n = n0 + nt * 8 + 2 * t4;
            int h = n >> 6, d = n & 63;
            float2 bi = *(const float2*)(bias + n);
            float* dst = Qh + ((size_t)(b * HEADS + h) * SEQ + s) * DEPTH + d;
            *(float2*)dst = make_float2(acc[nt][0] + bi.x, acc[nt][1] + bi.y);
            *(float2*)(dst + 8 * DEPTH) =
                make_float2(acc[nt][2] + bi.x, acc[nt][3] + bi.y);
        }
    } else if (z == 1) {
        // K cells: u32 idx = ntA*256 + (ksA>>1)*128 + ln*4 + (ksA&1)*2 + wbit
        int b = m >> 12, s = m & 4095;
        int jt = s >> 7;
#pragma unroll
        for (int nt = 0; nt < 16; ++nt) {
            int n = n0 + nt * 8 + 2 * t4;
            int h = n >> 6, d = n & 63;
            float2 bi = *(const float2*)(bias + n);
            size_t tilebase = ((size_t)(b * HEADS + h) * 32 + jt) * 4096;  // u32
            int ksA = d >> 4, wbit = (d >> 3) & 1;
            int sub = (ksA >> 1) * 128 + (ksA & 1) * 2 + wbit;
            int ln0 = (s & 7) * 4 + t4;
            int i0 = ((s >> 3) & 15) * 256 + sub + ln0 * 4;
            int i1 = (((s + 8) >> 3) & 15) * 256 + sub + ln0 * 4;
            Kc[tilebase + i0] = f2h2(acc[nt][0] + bi.x, acc[nt][1] + bi.y);
            Kc[tilebase + i1] = f2h2(acc[nt][2] + bi.x, acc[nt][3] + bi.y);
        }
    } else {
        // V cells via fp16 smem transpose (pairs along s).
        __syncthreads();
        __half* Hs = (__half*)smem;         // [128 s][HST]
        const int r0 = 16 * w + g;
#pragma unroll
        for (int nt = 0; nt < 16; ++nt) {
            int n = nt * 8 + 2 * t4;
            float2 bi = *(const float2*)(bias + n0 + n);
            *(u32*)&Hs[r0 * HST + n]       = f2h2(acc[nt][0] + bi.x, acc[nt][1] + bi.y);
            *(u32*)&Hs[(r0 + 8) * HST + n] = f2h2(acc[nt][2] + bi.x, acc[nt][3] + bi.y);
        }
        __syncthreads();

        int b = m0 >> 12, jt = (m0 & 4095) >> 7;
#pragma unroll
        for (int it = 0; it < 16; ++it) {
            int c  = tid + it * 256;        // 4096 old-style cells (2 head-tiles)
            int hh = c >> 11;
            int cl = c & 2047;
            int ln = cl & 31, ks = (cl >> 5) & 7, ntv = cl >> 8;
            int gg = ln >> 2, tt = ln & 3;
            int nl = hh * 64 + ntv * 8 + gg;    // local col (d)
            int j  = ks * 16 + 2 * tt;          // local row (s)
            u32 w0 = packhh(Hs[j * HST + nl],       Hs[(j + 1) * HST + nl]);
            u32 w1 = packhh(Hs[(j + 8) * HST + nl], Hs[(j + 9) * HST + nl]);
            int hgl = (n0 >> 6) + hh;
            size_t tilebase = ((size_t)(b * HEADS + hgl) * 32 + jt) * 4096;  // u32
            // uint4 cell (ntv*4 + ks>>1)*32 + ln, words (ks&1)*2 + {0,1}
            int base4 = (ntv * 4 + (ks >> 1)) * 128 + ln * 4 + (ks & 1) * 2;
            Vc[tilebase + base4]     = w0;
            Vc[tilebase + base4 + 1] = w1;
        }
    }
}

// ---------------------------------------------------------------------------
// Output GEMM: ctx @ Wo + bo -> row-major out.
// ---------------------------------------------------------------------------
__global__ __launch_bounds__(256, 2) void gemm_out(
    const float* __restrict__ A, const uint4* __restrict__ Wc,
    const float* __restrict__ bias, float* __restrict__ C)
{
    extern __shared__ char smem[];
    const u32 sb = smem_u32(smem);

    const int tid  = threadIdx.x;
    const int w    = tid >> 5;
    const int lane = tid & 31;
    const int g    = lane >> 2;
    const int t4   = lane & 3;
    const int n0   = blockIdx.x * 128;
    const int m0   = blockIdx.y * 128;

    float acc[16][4];
    gemm_mainloop(A, Wc, smem, sb, m0, blockIdx.x, tid, w, g, t4, lane, acc);

    const int m = m0 + 16 * w + g;
#pragma unroll
    for (int nt = 0; nt < 16; ++nt) {
        int n = n0 + nt * 8 + 2 * t4;
        float2 bi = *(const float2*)(bias + n);
        *(float2*)(C + (size_t)m * 512 + n) =
            make_float2(acc[nt][0] + bi.x, acc[nt][1] + bi.y);
        *(float2*)(C + (size_t)(m + 8) * 512 + n) =
            make_float2(acc[nt][2] + bi.x, acc[nt][3] + bi.y);
    }
}

// ---------------------------------------------------------------------------
// Flash attention: Q hi-only regs, K/V uint4 cells (2 ks per LDS.128),
// K+V double-buffered cp.async.
// ---------------------------------------------------------------------------
#define SM_MASK 0
#define SM_KC0  1024
#define SM_KC1  (SM_KC0 + 16384)
#define SM_VC0  (SM_KC1 + 16384)
#define SM_VC1  (SM_VC0 + 16384)
#define SM_TOT  (SM_VC1 + 16384)    // 66560 B

__global__ __launch_bounds__(256, 2) void attn_mma(
    const float* __restrict__ Qg, const uint4* __restrict__ Kc,
    const uint4* __restrict__ Vc, const float* __restrict__ mask,
    float* __restrict__ ctx)
{
    extern __shared__ char smem[];
    const u32 sb = smem_u32(smem);
    float* smask = (float*)(smem + SM_MASK);

    const int tid  = threadIdx.x;
    const int w    = tid >> 5;
    const int lane = tid & 31;
    const int g    = lane >> 2;
    const int t4   = lane & 3;
    const int bh   = blockIdx.y, b = bh >> 3, h = bh & 7;
    const int qi0  = blockIdx.x * 128;

    const float* Qb  = Qg + (size_t)bh * SEQ * DEPTH;
    const uint4* Kcb = Kc + (size_t)bh * 32 * 1024;
    const uint4* Vcb = Vc + (size_t)bh * 32 * 1024;
    const float* mb  = mask + (size_t)b * SEQ;

    u32 qhi[4][4];
    {
        const float* q0 = Qb + (size_t)(qi0 + 16 * w + g) * DEPTH;
#pragma unroll
        for (int ks = 0; ks < 4; ++ks) {
            int d0 = ks * 16 + 2 * t4;
            float2 a0 = *(const float2*)(q0 + d0);
            float2 a1 = *(const float2*)(q0 + 8 * DEPTH + d0);
            float2 a2 = *(const float2*)(q0 + d0 + 8);
            float2 a3 = *(const float2*)(q0 + 8 * DEPTH + d0 + 8);
            qhi[ks][0] = f2h2(a0.x, a0.y);
            qhi[ks][1] = f2h2(a1.x, a1.y);
            qhi[ks][2] = f2h2(a2.x, a2.y);
            qhi[ks][3] = f2h2(a3.x, a3.y);
        }
    }

    float oacc[8][4];
#pragma unroll
    for (int nt = 0; nt < 8; ++nt)
#pragma unroll
        for (int e = 0; e < 4; ++e) oacc[nt][e] = 0.0f;
    float lsum0 = 0.0f, lsum1 = 0.0f;

#pragma unroll
    for (int it = 0; it < 4; ++it) {
        int c = tid + it * 256;
        cpa16(sb + SM_KC0 + c * 16, Kcb + c);
        cpa16(sb + SM_VC0 + c * 16, Vcb + c);
    }
    CP_COMMIT();

    for (int jt = 0; jt < 32; ++jt) {
        const int cur = jt & 1;
        const uint4* KCb = (const uint4*)(smem + (cur ? SM_KC1 : SM_KC0));
        const uint4* VCb = (const uint4*)(smem + (cur ? SM_VC1 : SM_VC0));
        const u32 kbufn  = sb + (cur ? SM_KC0 : SM_KC1);
        const u32 vbufn  = sb + (cur ? SM_VC0 : SM_VC1);

        __syncthreads();

        int jn = (jt + 1 < 32) ? jt + 1 : 31;
        const uint4* ksrc = Kcb + (size_t)jn * 1024;
        const uint4* vsrc = Vcb + (size_t)jn * 1024;
#pragma unroll
        for (int it = 0; it < 4; ++it) {
            int c = tid + it * 256;
            cpa16(kbufn + c * 16, ksrc + c);
            cpa16(vbufn + c * 16, vsrc + c);
        }
        CP_COMMIT();

        if (tid < 128) smask[tid] = mb[jt * 128 + tid] * (-1e9f);

        CP_WAIT(1);
        __syncthreads();

        // ---- QK^T + exp + pack ----
        u32 pa[8][4];
#pragma unroll
        for (int kp = 0; kp < 8; ++kp) {
            float sacc[2][4] = {{0.f,0.f,0.f,0.f},{0.f,0.f,0.f,0.f}};
#pragma unroll
            for (int i = 0; i < 2; ++i) {
                int nt = kp * 2 + i;
#pragma unroll
                for (int ksp = 0; ksp < 2; ++ksp) {
                    uint4 cv = KCb[(nt * 2 + ksp) * 32 + lane];
                    mma16(sacc[i], qhi[2 * ksp],     cv.x, cv.y);
                    mma16(sacc[i], qhi[2 * ksp + 1], cv.z, cv.w);
                }
            }
            float p[2][4];
#pragma unroll
            for (int i = 0; i < 2; ++i) {
                int c0 = (kp * 2 + i) * 8 + 2 * t4;
                float mk0 = smask[c0], mk1 = smask[c0 + 1];
                p[i][0] = __expf(fmaf(sacc[i][0], 0.125f, mk0));
                p[i][1] = __expf(fmaf(sacc[i][1], 0.125f, mk1));
                p[i][2] = __expf(fmaf(sacc[i][2], 0.125f, mk0));
                p[i][3] = __expf(fmaf(sacc[i][3], 0.125f, mk1));
                lsum0 += p[i][0] + p[i][1];
                lsum1 += p[i][2] + p[i][3];
            }
            pa[kp][0] = f2h2(p[0][0], p[0][1]);
            pa[kp][1] = f2h2(p[0][2], p[0][3]);
            pa[kp][2] = f2h2(p[1][0], p[1][1]);
            pa[kp][3] = f2h2(p[1][2], p[1][3]);
        }

        // ---- O += P V ----
#pragma unroll
        for (int ksp = 0; ksp < 4; ++ksp) {
#pragma unroll
            for (int nt = 0; nt < 8; ++nt) {
                uint4 cv = VCb[(nt * 4 + ksp) * 32 + lane];
                mma16(oacc[nt], pa[2 * ksp],     cv.x, cv.y);
                mma16(oacc[nt], pa[2 * ksp + 1], cv.z, cv.w);
            }
        }
    }

    lsum0 += __shfl_xor_sync(0xffffffffu, lsum0, 1);
    lsum0 += __shfl_xor_sync(0xffffffffu, lsum0, 2);
    lsum1 += __shfl_xor_sync(0xffffffffu, lsum1, 1);
    lsum1 += __shfl_xor_sync(0xffffffffu, lsum1, 2);
    float inv0 = 1.0f / lsum0, inv1 = 1.0f / lsum1;

    int row0 = qi0 + 16 * w + g;
    float* dst0 = ctx + ((size_t)(b * SEQ + row0)) * EMBED + h * DEPTH;
    float* dst1 = dst0 + (size_t)8 * EMBED;
#pragma unroll
    for (int nt = 0; nt < 8; ++nt) {
        int c = nt * 8 + 2 * t4;
        *(float2*)(dst0 + c) = make_float2(oacc[nt][0] * inv0, oacc[nt][1] * inv0);
        *(float2*)(dst1 + c) = make_float2(oacc[nt][2] * inv1, oacc[nt][3] * inv1);
    }
}

// ---------------------------------------------------------------------------
// Launcher
// ---------------------------------------------------------------------------
extern "C" void kernel_launch(void* const* d_in, const int* in_sizes, int n_in,
                              void* d_out, int out_size)
{
    const float* q    = (const float*)d_in[0];
    const float* k    = (const float*)d_in[1];
    const float* v    = (const float*)d_in[2];
    const float* mask = (const float*)d_in[3];
    const float* Wq   = (const float*)d_in[4];
    const float* bq   = (const float*)d_in[5];
    const float* Wk   = (const float*)d_in[6];
    const float* bk   = (const float*)d_in[7];
    const float* Wv   = (const float*)d_in[8];
    const float* bv   = (const float*)d_in[9];
    const float* Wo   = (const float*)d_in[10];
    const float* bo   = (const float*)d_in[11];
    float* out = (float*)d_out;

    float *Qh, *ctx;
    uint4 *Wc, *Kc, *Vc;
    cudaGetSymbolAddress((void**)&Qh,  g_Qh);
    cudaGetSymbolAddress((void**)&ctx, g_ctx);
    cudaGetSymbolAddress((void**)&Wc,  g_Wc);
    cudaGetSymbolAddress((void**)&Kc,  g_Kc);
    cudaGetSymbolAddress((void**)&Vc,  g_Vc);

    const int WCN = 64 * 32 * 32;
    wprep4_kernel<<<dim3(4, 16, 4), 256>>>(Wq, Wk, Wv, Wo, Wc);

    cudaFuncSetAttribute(gemm_qkv, cudaFuncAttributeMaxDynamicSharedMemorySize, SG_TOT);
    cudaFuncSetAttribute(gemm_out, cudaFuncAttributeMaxDynamicSharedMemorySize, SG_TOT);

    gemm_qkv<<<dim3(4, 64, 3), 256, SG_TOT>>>(
        q, k, v, Wc, bq, bk, bv, Qh, (u32*)Kc, (u32*)Vc);

    cudaFuncSetAttribute(attn_mma, cudaFuncAttributeMaxDynamicSharedMemorySize, SM_TOT);
    attn_mma<<<dim3(SEQ / 128, BATCH * HEADS), 256, SM_TOT>>>(Qh, Kc, Vc, mask, ctx);

    gemm_out<<<dim3(4, 64), 256, SG_TOT>>>(ctx, Wc + 3 * WCN, bo, out);
}

// round 13
// speedup vs baseline: 6.5914x; 1.0585x over previous
#include <cuda_runtime.h>
#include <cuda.h>
#include <cuda_fp16.h>
#include <math.h>

#define EMBED 512
#define HEADS 8
#define DEPTH 64
#define BATCH 2
#define SEQ   4096
#define MROWS (BATCH * SEQ)          // 8192

typedef unsigned long long u64;
typedef unsigned int u32;

// ---------------------------------------------------------------------------
// Device scratch
// ---------------------------------------------------------------------------
__device__ float g_Qh[BATCH * HEADS * SEQ * DEPTH];   // [B,H,S,D]
__device__ float g_ctx[BATCH * SEQ * EMBED];          // [B,S,E]
__device__ uint4 g_Wc[4 * 64 * 32 * 32];              // packed W B-cells (hi+lo)
__device__ uint4 g_Kc[BATCH * HEADS * 32 * 1024];     // packed K cells (uint4)
__device__ uint4 g_Vc[BATCH * HEADS * 32 * 1024];     // packed V cells (uint4)

// ---------------------------------------------------------------------------
// fp16 mma.sync + cp.async helpers (baseline PTX, compute_103-safe)
// ---------------------------------------------------------------------------
__device__ __forceinline__ void mma16(float c[4], const u32 a[4], u32 b0, u32 b1) {
    asm("mma.sync.aligned.m16n8k16.row.col.f32.f16.f16.f32 "
        "{%0,%1,%2,%3}, {%4,%5,%6,%7}, {%8,%9}, {%0,%1,%2,%3};"
        : "+f"(c[0]), "+f"(c[1]), "+f"(c[2]), "+f"(c[3])
        : "r"(a[0]), "r"(a[1]), "r"(a[2]), "r"(a[3]), "r"(b0), "r"(b1));
}
__device__ __forceinline__ u32 f2h2(float lo, float hi) {
    __half2 h = __float22half2_rn(make_float2(lo, hi));
    return *(u32*)&h;
}
__device__ __forceinline__ float2 h22f(u32 v) {
    __half2 h = *(__half2*)&v;
    return __half22float2(h);
}
__device__ __forceinline__ void split2(float2 x, u32& hi, u32& lo) {
    hi = f2h2(x.x, x.y);
    float2 back = h22f(hi);
    lo = f2h2(x.x - back.x, x.y - back.y);
}
__device__ __forceinline__ u32 packhh(__half a, __half b) {
    return (u32)__half_as_ushort(a) | ((u32)__half_as_ushort(b) << 16);
}
__device__ __forceinline__ u32 smem_u32(const void* p) {
    u32 a;
    asm("{ .reg .u64 t; cvta.to.shared.u64 t, %1; cvt.u32.u64 %0, t; }"
        : "=r"(a) : "l"(p));
    return a;
}
__device__ __forceinline__ void cpa16(u32 saddr, const void* gptr) {
    asm volatile("cp.async.cg.shared.global [%0], [%1], 16;"
                 :: "r"(saddr), "l"(gptr));
}
__device__ __forceinline__ float ex2f(float x) {
    float r; asm("ex2.approx.f32 %0, %1;" : "=f"(r) : "f"(x)); return r;
}
#define CP_COMMIT() asm volatile("cp.async.commit_group;" ::: "memory")
#define CP_WAIT(n)  asm volatile("cp.async.wait_group %0;" :: "n"(n) : "memory")

#define SCL_L2E  0.180336890f        // 0.125 * log2(e)
#define MSK_L2E  (-1.442695041e9f)   // -1e9 * log2(e)

// ---------------------------------------------------------------------------
// Weight prep x4: W[512][512] -> cells [ntg 64][ksg 32][ln 32] (hi+lo)
// ---------------------------------------------------------------------------
__global__ __launch_bounds__(256) void wprep4_kernel(
    const float* __restrict__ W0, const float* __restrict__ W1,
    const float* __restrict__ W2, const float* __restrict__ W3,
    uint4* __restrict__ out)
{
    __shared__ float sw[32][132];
    const int tid = threadIdx.x;
    const int n0 = blockIdx.x * 128;
    const int k0 = blockIdx.y * 32;
    const int wz = blockIdx.z;
    const float* W = (wz == 0) ? W0 : (wz == 1) ? W1 : (wz == 2) ? W2 : W3;
    uint4* o = out + (size_t)wz * (64 * 32 * 32);

#pragma unroll
    for (int it = 0; it < 4; ++it) {
        int idx = tid + it * 256;
        int row = idx >> 5;
        int n4  = (idx & 31) * 4;
        *(float4*)&sw[row][n4] = *(const float4*)(W + (size_t)(k0 + row) * 512 + n0 + n4);
    }
    __syncthreads();

#pragma unroll
    for (int it = 0; it < 4; ++it) {
        int idx = tid + it * 256;
        int ln = idx & 31, ks = (idx >> 5) & 1, nt = idx >> 6;
        int gg = ln >> 2, tt = ln & 3;
        int nl = nt * 8 + gg;
        int kl = ks * 16 + 2 * tt;
        float2 x0 = make_float2(sw[kl][nl],     sw[kl + 1][nl]);
        float2 x1 = make_float2(sw[kl + 8][nl], sw[kl + 9][nl]);
        uint4 cv;
        split2(x0, cv.x, cv.z);
        split2(x1, cv.y, cv.w);
        o[((size_t)(blockIdx.x * 16 + nt) * 32 + blockIdx.y * 2 + ks) * 32 + ln] = cv;
    }
}

// ---------------------------------------------------------------------------
// GEMM mainloop: 2-term hi/lo, 3-stage cp.async ring, ONE sync per chunk.
// smem: A stages at i*18432 (i=0..2), B stages at 55296 + i*16384.
// ---------------------------------------------------------------------------
#define ASTR 36
#define SG_BOFF 55296
#define SG_TOT  104448
#define HST 132

__device__ __forceinline__ void gemm_issue_chunk(
    const float* __restrict__ A, const uint4* __restrict__ Wc,
    u32 sb, int m0, int nblk, int tid, int st, int kn)
{
#pragma unroll
    for (int it = 0; it < 4; ++it) {
        int idx = tid + it * 256;
        int row = idx >> 3, k4 = (idx & 7) * 4;
        cpa16(sb + st * 18432 + (row * ASTR + k4) * 4,
              A + (size_t)(m0 + row) * 512 + kn * 32 + k4);
        int ln = idx & 31, ks = (idx >> 5) & 1, nt = idx >> 6;
        cpa16(sb + SG_BOFF + st * 16384 + idx * 16,
              Wc + ((size_t)(nblk * 16 + nt) * 32 + kn * 2 + ks) * 32 + ln);
    }
    CP_COMMIT();
}

__device__ __forceinline__ void gemm_mainloop(
    const float* __restrict__ A, const uint4* __restrict__ Wc,
    const char* smem, u32 sb, int m0, int nblk,
    int tid, int w, int g, int t4, int lane, float acc[16][4])
{
#pragma unroll
    for (int nt = 0; nt < 16; ++nt)
#pragma unroll
        for (int e = 0; e < 4; ++e) acc[nt][e] = 0.0f;

    gemm_issue_chunk(A, Wc, sb, m0, nblk, tid, 0, 0);
    gemm_issue_chunk(A, Wc, sb, m0, nblk, tid, 1, 1);

    int cb = 0;
    for (int kc = 0; kc < 16; ++kc) {
        CP_WAIT(1);          // chunk kc resident
        __syncthreads();     // compute(kc-1) done -> safe to overwrite stage (cb+2)%3

        int kn = (kc + 2 <= 15) ? kc + 2 : 15;
        int nb = (cb == 0) ? 2 : cb - 1;     // (cb+2)%3
        gemm_issue_chunk(A, Wc, sb, m0, nblk, tid, nb, kn);

        const float* arow = (const float*)(smem + cb * 18432) + (16 * w + g) * ASTR;
        const uint4* BCc  = (const uint4*)(smem + SG_BOFF + cb * 16384);

#pragma unroll
        for (int ks = 0; ks < 2; ++ks) {
            u32 ahi[4];
            const float* base = arow + ks * 16 + 2 * t4;
            float2 a0 = *(const float2*)(base);
            float2 a1 = *(const float2*)(base + 8 * ASTR);
            float2 a2 = *(const float2*)(base + 8);
            float2 a3 = *(const float2*)(base + 8 * ASTR + 8);
            ahi[0] = f2h2(a0.x, a0.y);
            ahi[1] = f2h2(a1.x, a1.y);
            ahi[2] = f2h2(a2.x, a2.y);
            ahi[3] = f2h2(a3.x, a3.y);
#pragma unroll
            for (int nt = 0; nt < 16; ++nt) {
                uint4 cv = BCc[(nt * 2 + ks) * 32 + lane];
                mma16(acc[nt], ahi, cv.x, cv.y);
                mma16(acc[nt], ahi, cv.z, cv.w);
            }
        }
        cb = (cb == 2) ? 0 : cb + 1;
    }
}

// ---------------------------------------------------------------------------
// Fused Q/K/V projection GEMM. grid (4 n, 64 m, 3 which).
// ---------------------------------------------------------------------------
__global__ __launch_bounds__(256, 2) void gemm_qkv(
    const float* __restrict__ q, const float* __restrict__ k,
    const float* __restrict__ v, const uint4* __restrict__ Wc,
    const float* __restrict__ bq, const float* __restrict__ bk,
    const float* __restrict__ bv, float* __restrict__ Qh,
    u32* __restrict__ Kc, u32* __restrict__ Vc)
{
    extern __shared__ char smem[];
    const u32 sb = smem_u32(smem);

    const int tid  = threadIdx.x;
    const int w    = tid >> 5;
    const int lane = tid & 31;
    const int g    = lane >> 2;
    const int t4   = lane & 3;
    const int n0   = blockIdx.x * 128;
    const int m0   = blockIdx.y * 128;
    const int z    = blockIdx.z;

    const float* A    = (z == 0) ? q : (z == 1) ? k : v;
    const float* bias = (z == 0) ? bq : (z == 1) ? bk : bv;
    const uint4* Wcz  = Wc + (size_t)z * (64 * 32 * 32);

    float acc[16][4];
    gemm_mainloop(A, Wcz, smem, sb, m0, blockIdx.x, tid, w, g, t4, lane, acc);

    const int m = m0 + 16 * w + g;
    if (z == 0) {
        int b = m >> 12, s = m & 4095;
#pragma unroll
        for (int nt = 0; nt < 16; ++nt) {
            int n = n0 + nt * 8 + 2 * t4;
            int h = n >> 6, d = n & 63;
            float2 bi = *(const float2*)(bias + n);
            float* dst = Qh + ((size_t)(b * HEADS + h) * SEQ + s) * DEPTH + d;
            *(float2*)dst = make_float2(acc[nt][0] + bi.x, acc[nt][1] + bi.y);
            *(float2*)(dst + 8 * DEPTH) =
                make_float2(acc[nt][2] + bi.x, acc[nt][3] + bi.y);
        }
    } else if (z == 1) {
        int b = m >> 12, s = m & 4095;
        int jt = s >> 7;
#pragma unroll
        for (int nt = 0; nt < 16; ++nt) {
            int n = n0 + nt * 8 + 2 * t4;
            int h = n >> 6, d = n & 63;
            float2 bi = *(const float2*)(bias + n);
            size_t tilebase = ((size_t)(b * HEADS + h) * 32 + jt) * 4096;  // u32
            int ksA = d >> 4, wbit = (d >> 3) & 1;
            int sub = (ksA >> 1) * 128 + (ksA & 1) * 2 + wbit;
            int ln0 = (s & 7) * 4 + t4;
            int i0 = ((s >> 3) & 15) * 256 + sub + ln0 * 4;
            int i1 = (((s + 8) >> 3) & 15) * 256 + sub + ln0 * 4;
            Kc[tilebase + i0] = f2h2(acc[nt][0] + bi.x, acc[nt][1] + bi.y);
            Kc[tilebase + i1] = f2h2(acc[nt][2] + bi.x, acc[nt][3] + bi.y);
        }
    } else {
        // V cells via fp16 smem transpose (pairs along s).
        __syncthreads();
        __half* Hs = (__half*)smem;         // [128 s][HST]
        const int r0 = 16 * w + g;
#pragma unroll
        for (int nt = 0; nt < 16; ++nt) {
            int n = nt * 8 + 2 * t4;
            float2 bi = *(const float2*)(bias + n0 + n);
            *(u32*)&Hs[r0 * HST + n]       = f2h2(acc[nt][0] + bi.x, acc[nt][1] + bi.y);
            *(u32*)&Hs[(r0 + 8) * HST + n] = f2h2(acc[nt][2] + bi.x, acc[nt][3] + bi.y);
        }
        __syncthreads();

        int b = m0 >> 12, jt = (m0 & 4095) >> 7;
#pragma unroll
        for (int it = 0; it < 16; ++it) {
            int c  = tid + it * 256;
            int hh = c >> 11;
            int cl = c & 2047;
            int ln = cl & 31, ks = (cl >> 5) & 7, ntv = cl >> 8;
            int gg = ln >> 2, tt = ln & 3;
            int nl = hh * 64 + ntv * 8 + gg;
            int j  = ks * 16 + 2 * tt;
            u32 w0 = packhh(Hs[j * HST + nl],       Hs[(j + 1) * HST + nl]);
            u32 w1 = packhh(Hs[(j + 8) * HST + nl], Hs[(j + 9) * HST + nl]);
            int hgl = (n0 >> 6) + hh;
            size_t tilebase = ((size_t)(b * HEADS + hgl) * 32 + jt) * 4096;  // u32
            int base4 = (ntv * 4 + (ks >> 1)) * 128 + ln * 4 + (ks & 1) * 2;
            Vc[tilebase + base4]     = w0;
            Vc[tilebase + base4 + 1] = w1;
        }
    }
}

// ---------------------------------------------------------------------------
// Output GEMM: ctx @ Wo + bo -> row-major out.
// ---------------------------------------------------------------------------
__global__ __launch_bounds__(256, 2) void gemm_out(
    const float* __restrict__ A, const uint4* __restrict__ Wc,
    const float* __restrict__ bias, float* __restrict__ C)
{
    extern __shared__ char smem[];
    const u32 sb = smem_u32(smem);

    const int tid  = threadIdx.x;
    const int w    = tid >> 5;
    const int lane = tid & 31;
    const int g    = lane >> 2;
    const int t4   = lane & 3;
    const int n0   = blockIdx.x * 128;
    const int m0   = blockIdx.y * 128;

    float acc[16][4];
    gemm_mainloop(A, Wc, smem, sb, m0, blockIdx.x, tid, w, g, t4, lane, acc);

    const int m = m0 + 16 * w + g;
#pragma unroll
    for (int nt = 0; nt < 16; ++nt) {
        int n = n0 + nt * 8 + 2 * t4;
        float2 bi = *(const float2*)(bias + n);
        *(float2*)(C + (size_t)m * 512 + n) =
            make_float2(acc[nt][0] + bi.x, acc[nt][1] + bi.y);
        *(float2*)(C + (size_t)(m + 8) * 512 + n) =
            make_float2(acc[nt][2] + bi.x, acc[nt][3] + bi.y);
    }
}

// ---------------------------------------------------------------------------
// Flash attention: 3-stage K/V ring, ONE sync per jtile, double-buffered mask.
// Q hi-only regs, K/V uint4 cells, exp via ex2 with folded log2(e).
// smem: mask 2x512 @0; K stages @1024 + i*16384; V stages @50176 + i*16384.
// ---------------------------------------------------------------------------
#define SM_MASK 0
#define SM_KS   1024
#define SM_VS   (SM_KS + 3 * 16384)
#define SM_TOT  (SM_VS + 3 * 16384)   // 99328

__global__ __launch_bounds__(256, 2) void attn_mma(
    const float* __restrict__ Qg, const uint4* __restrict__ Kc,
    const uint4* __restrict__ Vc, const float* __restrict__ mask,
    float* __restrict__ ctx)
{
    extern __shared__ char smem[];
    const u32 sb = smem_u32(smem);
    float* smask = (float*)(smem + SM_MASK);   // [2][128]

    const int tid  = threadIdx.x;
    const int w    = tid >> 5;
    const int lane = tid & 31;
    const int g    = lane >> 2;
    const int t4   = lane & 3;
    const int bh   = blockIdx.y, b = bh >> 3, h = bh & 7;
    const int qi0  = blockIdx.x * 128;

    const float* Qb  = Qg + (size_t)bh * SEQ * DEPTH;
    const uint4* Kcb = Kc + (size_t)bh * 32 * 1024;
    const uint4* Vcb = Vc + (size_t)bh * 32 * 1024;
    const float* mb  = mask + (size_t)b * SEQ;

    u32 qhi[4][4];
    {
        const float* q0 = Qb + (size_t)(qi0 + 16 * w + g) * DEPTH;
#pragma unroll
        for (int ks = 0; ks < 4; ++ks) {
            int d0 = ks * 16 + 2 * t4;
            float2 a0 = *(const float2*)(q0 + d0);
            float2 a1 = *(const float2*)(q0 + 8 * DEPTH + d0);
            float2 a2 = *(const float2*)(q0 + d0 + 8);
            float2 a3 = *(const float2*)(q0 + 8 * DEPTH + d0 + 8);
            qhi[ks][0] = f2h2(a0.x, a0.y);
            qhi[ks][1] = f2h2(a1.x, a1.y);
            qhi[ks][2] = f2h2(a2.x, a2.y);
            qhi[ks][3] = f2h2(a3.x, a3.y);
        }
    }

    float oacc[8][4];
#pragma unroll
    for (int nt = 0; nt < 8; ++nt)
#pragma unroll
        for (int e = 0; e < 4; ++e) oacc[nt][e] = 0.0f;
    float ls0a = 0.0f, ls0b = 0.0f, ls1a = 0.0f, ls1b = 0.0f;

    // prologue: stages 0 and 1, mask(0)
#pragma unroll
    for (int it = 0; it < 4; ++it) {
        int c = tid + it * 256;
        cpa16(sb + SM_KS + c * 16, Kcb + c);
        cpa16(sb + SM_VS + c * 16, Vcb + c);
    }
    CP_COMMIT();
#pragma unroll
    for (int it = 0; it < 4; ++it) {
        int c = tid + it * 256;
        cpa16(sb + SM_KS + 16384 + c * 16, Kcb + 1024 + c);
        cpa16(sb + SM_VS + 16384 + c * 16, Vcb + 1024 + c);
    }
    CP_COMMIT();
    if (tid < 128) smask[tid] = mb[tid] * MSK_L2E;

    int cb = 0;
    for (int jt = 0; jt < 32; ++jt) {
        CP_WAIT(1);          // tile jt resident
        __syncthreads();     // compute(jt-1) done; mask(jt) visible

        // prefetch tile jt+2 into stage (cb+2)%3
        int jn = (jt + 2 <= 31) ? jt + 2 : 31;
        int nb = (cb == 0) ? 2 : cb - 1;
        const uint4* ksrc = Kcb + (size_t)jn * 1024;
        const uint4* vsrc = Vcb + (size_t)jn * 1024;
#pragma unroll
        for (int it = 0; it < 4; ++it) {
            int c = tid + it * 256;
            cpa16(sb + SM_KS + nb * 16384 + c * 16, ksrc + c);
            cpa16(sb + SM_VS + nb * 16384 + c * 16, vsrc + c);
        }
        CP_COMMIT();

        // stage mask for jt+1 (read next iteration, after its top sync)
        if (tid < 128 && jt + 1 < 32)
            smask[((jt + 1) & 1) * 128 + tid] = mb[(jt + 1) * 128 + tid] * MSK_L2E;

        const uint4* KCb = (const uint4*)(smem + SM_KS + cb * 16384);
        const uint4* VCb = (const uint4*)(smem + SM_VS + cb * 16384);
        const float* mrow = smask + (jt & 1) * 128;

        // ---- QK^T + exp + pack ----
        u32 pa[8][4];
#pragma unroll
        for (int kp = 0; kp < 8; ++kp) {
            float sacc[2][4] = {{0.f,0.f,0.f,0.f},{0.f,0.f,0.f,0.f}};
#pragma unroll
            for (int i = 0; i < 2; ++i) {
                int nt = kp * 2 + i;
#pragma unroll
                for (int ksp = 0; ksp < 2; ++ksp) {
                    uint4 cv = KCb[(nt * 2 + ksp) * 32 + lane];
                    mma16(sacc[i], qhi[2 * ksp],     cv.x, cv.y);
                    mma16(sacc[i], qhi[2 * ksp + 1], cv.z, cv.w);
                }
            }
            float p[2][4];
#pragma unroll
            for (int i = 0; i < 2; ++i) {
                int c0 = (kp * 2 + i) * 8 + 2 * t4;
                float mk0 = mrow[c0], mk1 = mrow[c0 + 1];
                p[i][0] = ex2f(fmaf(sacc[i][0], SCL_L2E, mk0));
                p[i][1] = ex2f(fmaf(sacc[i][1], SCL_L2E, mk1));
                p[i][2] = ex2f(fmaf(sacc[i][2], SCL_L2E, mk0));
                p[i][3] = ex2f(fmaf(sacc[i][3], SCL_L2E, mk1));
            }
            if (kp & 1) {
                ls0b += (p[0][0] + p[0][1]) + (p[1][0] + p[1][1]);
                ls1b += (p[0][2] + p[0][3]) + (p[1][2] + p[1][3]);
            } else {
                ls0a += (p[0][0] + p[0][1]) + (p[1][0] + p[1][1]);
                ls1a += (p[0][2] + p[0][3]) + (p[1][2] + p[1][3]);
            }
            pa[kp][0] = f2h2(p[0][0], p[0][1]);
            pa[kp][1] = f2h2(p[0][2], p[0][3]);
            pa[kp][2] = f2h2(p[1][0], p[1][1]);
            pa[kp][3] = f2h2(p[1][2], p[1][3]);
        }

        // ---- O += P V ----
#pragma unroll
        for (int ksp = 0; ksp < 4; ++ksp) {
#pragma unroll
            for (int nt = 0; nt < 8; ++nt) {
                uint4 cv = VCb[(nt * 4 + ksp) * 32 + lane];
                mma16(oacc[nt], pa[2 * ksp],     cv.x, cv.y);
                mma16(oacc[nt], pa[2 * ksp + 1], cv.z, cv.w);
            }
        }
        cb = (cb == 2) ? 0 : cb + 1;
    }

    float lsum0 = ls0a + ls0b, lsum1 = ls1a + ls1b;
    lsum0 += __shfl_xor_sync(0xffffffffu, lsum0, 1);
    lsum0 += __shfl_xor_sync(0xffffffffu, lsum0, 2);
    lsum1 += __shfl_xor_sync(0xffffffffu, lsum1, 1);
    lsum1 += __shfl_xor_sync(0xffffffffu, lsum1, 2);
    float inv0 = 1.0f / lsum0, inv1 = 1.0f / lsum1;

    int row0 = qi0 + 16 * w + g;
    float* dst0 = ctx + ((size_t)(b * SEQ + row0)) * EMBED + h * DEPTH;
    float* dst1 = dst0 + (size_t)8 * EMBED;
#pragma unroll
    for (int nt = 0; nt < 8; ++nt) {
        int c = nt * 8 + 2 * t4;
        *(float2*)(dst0 + c) = make_float2(oacc[nt][0] * inv0, oacc[nt][1] * inv0);
        *(float2*)(dst1 + c) = make_float2(oacc[nt][2] * inv1, oacc[nt][3] * inv1);
    }
}

// ---------------------------------------------------------------------------
// Launcher
// ---------------------------------------------------------------------------
extern "C" void kernel_launch(void* const* d_in, const int* in_sizes, int n_in,
                              void* d_out, int out_size)
{
    const float* q    = (const float*)d_in[0];
    const float* k    = (const float*)d_in[1];
    const float* v    = (const float*)d_in[2];
    const float* mask = (const float*)d_in[3];
    const float* Wq   = (const float*)d_in[4];
    const float* bq   = (const float*)d_in[5];
    const float* Wk   = (const float*)d_in[6];
    const float* bk   = (const float*)d_in[7];
    const float* Wv   = (const float*)d_in[8];
    const float* bv   = (const float*)d_in[9];
    const float* Wo   = (const float*)d_in[10];
    const float* bo   = (const float*)d_in[11];
    float* out = (float*)d_out;

    float *Qh, *ctx;
    uint4 *Wc, *Kc, *Vc;
    cudaGetSymbolAddress((void**)&Qh,  g_Qh);
    cudaGetSymbolAddress((void**)&ctx, g_ctx);
    cudaGetSymbolAddress((void**)&Wc,  g_Wc);
    cudaGetSymbolAddress((void**)&Kc,  g_Kc);
    cudaGetSymbolAddress((void**)&Vc,  g_Vc);

    const int WCN = 64 * 32 * 32;
    wprep4_kernel<<<dim3(4, 16, 4), 256>>>(Wq, Wk, Wv, Wo, Wc);

    cudaFuncSetAttribute(gemm_qkv, cudaFuncAttributeMaxDynamicSharedMemorySize, SG_TOT);
    cudaFuncSetAttribute(gemm_out, cudaFuncAttributeMaxDynamicSharedMemorySize, SG_TOT);

    gemm_qkv<<<dim3(4, 64, 3), 256, SG_TOT>>>(
        q, k, v, Wc, bq, bk, bv, Qh, (u32*)Kc, (u32*)Vc);

    cudaFuncSetAttribute(attn_mma, cudaFuncAttributeMaxDynamicSharedMemorySize, SM_TOT);
    attn_mma<<<dim3(SEQ / 128, BATCH * HEADS), 256, SM_TOT>>>(Qh, Kc, Vc, mask, ctx);

    gemm_out<<<dim3(4, 64), 256, SG_TOT>>>(ctx, Wc + 3 * WCN, bo, out);
}